// round 11
// baseline (speedup 1.0000x reference)
#include <cuda_runtime.h>
#include <cuda_fp16.h>
#include <cstdint>
#include <math.h>

#define T_ 512
#define B_ 64
#define N_ 1024
#define G_ 4096   // 4*N
#define SPF 516   // smem pitch (u32) for a FULL fp16 h row (512 u32 + 4 pad)
#define GP 132    // gates pitch (floats) for 128 cols

// ---------------- static device scratch ----------------
__device__ float g_Pf[(size_t)T_ * B_ * G_];
__device__ float g_Pb[(size_t)T_ * B_ * G_];
__device__ float g_Pc[(size_t)T_ * B_ * G_];
__device__ __half g_bi16[(size_t)T_ * B_ * 2 * N_];   // bilstm output, fp16
__device__ __half g_x16[(size_t)B_ * T_ * N_];        // inputs converted to fp16
__device__ __half g_Wih16[16 * 1024 * 1024];          // fp16 W_ih: f(4M) b(4M) c(8M)
__device__ __half g_h16[6][B_ * N_];                  // fp16 recurrent h
__device__ uint32_t g_Wsw_bi[64 * 65536];             // fp16 frag-swizzled W_hh fwd/bwd
__device__ uint32_t g_Wsw_c[32 * 65536];              // fp16 frag-swizzled W_hh cell

__device__ unsigned g_barc[2] = {0, 0};
__device__ unsigned g_barg[2] = {0, 0};

__device__ __forceinline__ void grid_barrier(int which, unsigned nb) {
    __syncthreads();
    if (threadIdx.x == 0) {
        __threadfence();
        volatile unsigned* gen = &g_barg[which];
        unsigned g = *gen;
        if (atomicAdd(&g_barc[which], 1) == nb - 1) {
            g_barc[which] = 0;
            __threadfence();
            atomicExch((unsigned*)gen, g + 1);
        } else {
            while (*gen == g) { }
            __threadfence();
        }
    }
    __syncthreads();
}

__global__ void zero_state_kernel() {
    int i = blockIdx.x * blockDim.x + threadIdx.x;
    ((uint32_t*)g_h16)[i] = 0;   // 196608 u32 = all 6 h buffers
}

// ---------------- helpers ----------------
__device__ __forceinline__ void mma_f16(float* c, const uint32_t* a, const uint32_t* b) {
    asm volatile(
        "mma.sync.aligned.m16n8k16.row.col.f32.f16.f16.f32 "
        "{%0,%1,%2,%3}, {%4,%5,%6,%7}, {%8,%9}, {%0,%1,%2,%3};"
        : "+f"(c[0]), "+f"(c[1]), "+f"(c[2]), "+f"(c[3])
        : "r"(a[0]), "r"(a[1]), "r"(a[2]), "r"(a[3]), "r"(b[0]), "r"(b[1]));
}
__device__ __forceinline__ void ldsm_x4(uint32_t& r0, uint32_t& r1, uint32_t& r2, uint32_t& r3,
                                        uint32_t addr) {
    asm volatile("ldmatrix.sync.aligned.m8n8.x4.shared.b16 {%0,%1,%2,%3}, [%4];"
                 : "=r"(r0), "=r"(r1), "=r"(r2), "=r"(r3) : "r"(addr));
}
__device__ __forceinline__ void cp16(uint32_t dst, const void* src) {
    asm volatile("cp.async.cg.shared.global [%0], [%1], 16;" :: "r"(dst), "l"(src));
}
__device__ __forceinline__ void cp_commit() { asm volatile("cp.async.commit_group;"); }
template <int NN> __device__ __forceinline__ void cp_wait() {
    asm volatile("cp.async.wait_group %0;" :: "n"(NN));
}
__device__ __forceinline__ uint32_t pack2h(float a, float b) {
    __half2 h = __floats2half2_rn(a, b);
    return *(uint32_t*)&h;
}
__device__ __forceinline__ uint32_t s2u(const void* p) {
    return (uint32_t)__cvta_generic_to_shared(p);
}
// fast activations (rel error ~1e-6, far below fp16 noise at 3.9e-4)
__device__ __forceinline__ float sig_f(float x) {
    return __fdividef(1.0f, 1.0f + __expf(-x));
}
__device__ __forceinline__ float tanh_f(float x) {
    return 1.0f - 2.0f * __fdividef(1.0f, __expf(2.0f * x) + 1.0f);
}

// ---------------- one-time conversions ----------------
__global__ void xconv_kernel(const float* __restrict__ x) {
    size_t i = (size_t)blockIdx.x * blockDim.x + threadIdx.x;
    float4 v = ((const float4*)x)[i];
    uint2 o;
    o.x = pack2h(v.x, v.y);
    o.y = pack2h(v.z, v.w);
    ((uint2*)g_x16)[i] = o;
}
__global__ void wconv_ih_kernel(const float* __restrict__ Wf,
                                const float* __restrict__ Wb,
                                const float* __restrict__ Wc) {
    size_t i = (size_t)blockIdx.x * blockDim.x + threadIdx.x;
    const float* src;
    size_t off;
    if (i < (1u << 20))      { src = Wf; off = i; }
    else if (i < (2u << 20)) { src = Wb; off = i - (1u << 20); }
    else                     { src = Wc; off = i - (2u << 20); }
    float4 v = ((const float4*)src)[off];
    uint2 o;
    o.x = pack2h(v.x, v.y);
    o.y = pack2h(v.z, v.w);
    ((uint2*)g_Wih16)[i] = o;
}

// ---------------- one-time W_hh fragment swizzles (fp16, 128-col regions) ----------------
// Region = 128 gate-cols x 1024 k. u32 layout within region:
// idx = k16*1024 + jn*128 + lane*4 + nf*2 + r
// element: col = jn*16 + nf*8 + (lane>>2); gate = col>>5; u = col&31;
//          k = k16*16 + r*8 + (lane&3)*2  (pack2h of k, k+1)
__global__ void wswz_bi_kernel(const float* __restrict__ Wf,
                               const float* __restrict__ Wb) {
    size_t idx = (size_t)blockIdx.x * blockDim.x + threadIdx.x;   // 64*65536
    unsigned region = idx >> 16;
    unsigned w = idx & 65535;
    int dir = region >> 5, ublk = region & 31;
    int k16 = w >> 10;
    int jn = (w >> 7) & 7;
    int lane = (w >> 2) & 31;
    int nf = (w >> 1) & 1;
    int r = w & 1;
    int col = jn * 16 + nf * 8 + (lane >> 2);
    int gate = col >> 5, u = col & 31;
    int row = gate * N_ + ublk * 32 + u;
    int k = k16 * 16 + r * 8 + (lane & 3) * 2;
    const float* W = dir ? Wb : Wf;
    g_Wsw_bi[idx] = pack2h(W[(size_t)row * N_ + k], W[(size_t)row * N_ + k + 1]);
}
__global__ void wswz_cell_kernel(const float* __restrict__ Wc) {
    size_t idx = (size_t)blockIdx.x * blockDim.x + threadIdx.x;   // 32*65536
    unsigned region = idx >> 16;
    unsigned w = idx & 65535;
    int k16 = w >> 10;
    int jn = (w >> 7) & 7;
    int lane = (w >> 2) & 31;
    int nf = (w >> 1) & 1;
    int r = w & 1;
    int col = jn * 16 + nf * 8 + (lane >> 2);
    int gate = col >> 5, u = col & 31;
    int row = gate * N_ + region * 32 + u;
    int k = k16 * 16 + r * 8 + (lane & 3) * 2;
    g_Wsw_c[idx] = pack2h(Wc[(size_t)row * N_ + k], Wc[(size_t)row * N_ + k + 1]);
}

// ---------------- fp16 GEMM: 128x128x32, cp.async double buffered, ldmatrix ----------------
__global__ __launch_bounds__(256, 2) void gemm_f16_kernel(
    const __half* __restrict__ A,
    const __half* __restrict__ Wt,
    const float* __restrict__ bias,
    int K, int a_mode, int dst_sel)
{
    float* C = (dst_sel == 0) ? g_Pf : (dst_sel == 1) ? g_Pb : g_Pc;

    __shared__ __align__(16) uint32_t As[2][128 * 20];
    __shared__ __align__(16) uint32_t Ws[2][128 * 20];

    const int tid = threadIdx.x;
    const int m0 = blockIdx.y * 128;
    const int g0 = blockIdx.x * 128;

    const __half* asrc[2];
    const __half* wsrc[2];
    int lrow[2], lseg[2];
#pragma unroll
    for (int i = 0; i < 2; i++) {
        int idx = tid + 256 * i;
        int row = idx >> 2;
        int seg = idx & 3;
        int m = m0 + row;
        int prow = (a_mode == 1) ? ((m & 63) * T_ + (m >> 6)) : m;
        asrc[i] = A + (size_t)prow * K + seg * 8;
        wsrc[i] = Wt + (size_t)(g0 + row) * K + seg * 8;
        lrow[i] = row; lseg[i] = seg;
    }
    uint32_t asm_a[2][2], wsm_a[2][2];
#pragma unroll
    for (int b = 0; b < 2; b++)
#pragma unroll
        for (int i = 0; i < 2; i++) {
            asm_a[b][i] = s2u(&As[b][lrow[i] * 20 + lseg[i] * 4]);
            wsm_a[b][i] = s2u(&Ws[b][lrow[i] * 20 + lseg[i] * 4]);
        }

    const int lane = tid & 31;
    const int wid = tid >> 5;
    const int gid = lane >> 2;
    const int tig = lane & 3;
    const int wm = (wid & 3) * 32;
    const int wn = (wid >> 2) * 64;

    const int rowA = lane & 15;
    const int koffA = (lane >> 4) * 4;
    const int cB = (lane & 7) + ((lane >> 4) << 3);
    const int kB = ((lane >> 3) & 1) * 4;

    uint32_t aaddr[2][2], baddr[2][4];
#pragma unroll
    for (int b = 0; b < 2; b++) {
#pragma unroll
        for (int mf = 0; mf < 2; mf++)
            aaddr[b][mf] = s2u(&As[b][(wm + mf * 16 + rowA) * 20 + koffA]);
#pragma unroll
        for (int np = 0; np < 4; np++)
            baddr[b][np] = s2u(&Ws[b][(wn + np * 16 + cB) * 20 + kB]);
    }

    float acc[2][8][4];
#pragma unroll
    for (int mf = 0; mf < 2; mf++)
#pragma unroll
        for (int nf = 0; nf < 8; nf++)
#pragma unroll
            for (int j = 0; j < 4; j++) acc[mf][nf][j] = 0.0f;

    const int NC = K / 32;
#pragma unroll
    for (int i = 0; i < 2; i++) {
        cp16(asm_a[0][i], asrc[i]);
        cp16(wsm_a[0][i], wsrc[i]);
    }
    cp_commit();

    for (int ch = 0; ch < NC; ch++) {
        const int buf = ch & 1;
        if (ch + 1 < NC) {
            const int nb = (ch + 1) & 1;
            const int k0 = (ch + 1) * 32;
#pragma unroll
            for (int i = 0; i < 2; i++) {
                cp16(asm_a[nb][i], asrc[i] + k0);
                cp16(wsm_a[nb][i], wsrc[i] + k0);
            }
            cp_commit();
            cp_wait<1>();
        } else {
            cp_wait<0>();
        }
        __syncthreads();

#pragma unroll
        for (int ks = 0; ks < 2; ks++) {
            const int kbb = ks * 32;
            uint32_t af[2][4];
#pragma unroll
            for (int mf = 0; mf < 2; mf++)
                ldsm_x4(af[mf][0], af[mf][1], af[mf][2], af[mf][3], aaddr[buf][mf] + kbb);
            uint32_t bf[8][2];
#pragma unroll
            for (int np = 0; np < 4; np++)
                ldsm_x4(bf[2 * np][0], bf[2 * np][1], bf[2 * np + 1][0], bf[2 * np + 1][1],
                        baddr[buf][np] + kbb);
#pragma unroll
            for (int mf = 0; mf < 2; mf++)
#pragma unroll
                for (int nf = 0; nf < 8; nf++)
                    mma_f16(acc[mf][nf], af[mf], bf[nf]);
        }
        __syncthreads();
    }

#pragma unroll
    for (int mf = 0; mf < 2; mf++) {
#pragma unroll
        for (int nf = 0; nf < 8; nf++) {
            int row = m0 + wm + mf * 16 + gid;
            int col = g0 + wn + nf * 8 + 2 * tig;
            float b0 = bias[col], b1 = bias[col + 1];
            float2 v0 = make_float2(acc[mf][nf][0] + b0, acc[mf][nf][1] + b1);
            float2 v1 = make_float2(acc[mf][nf][2] + b0, acc[mf][nf][3] + b1);
            *(float2*)&C[(size_t)row * G_ + col] = v0;
            *(float2*)&C[(size_t)(row + 8) * G_ + col] = v1;
        }
    }
}

// ---------------- persistent bilstm recurrence (wide blocks, c in regs) ----------------
// 64 blocks x 512 threads. dir = bid>>5, 32 units (128 gate cols) per block.
// Warp: wm=(wid&1)*32 (batch), jn=wid>>1 (16 cols). mma m64 n128 k1024 per block/step.
__global__ __launch_bounds__(512, 1) void bilstm_mma_kernel()
{
    extern __shared__ uint32_t smem_u[];
    uint32_t* hs = smem_u;                         // [64][SPF]
    float* gates = (float*)(smem_u + 64 * SPF);    // [64][GP]

    const int bid = blockIdx.x;
    const int dir = bid >> 5;
    const int u0 = (bid & 31) * 32;
    const float* Pbase = dir ? g_Pb : g_Pf;

    const int tid = threadIdx.x;
    const int lane = tid & 31;
    const int wid = tid >> 5;
    const int gid = lane >> 2;
    const int tig = lane & 3;
    const int wm = (wid & 1) * 32;
    const int jn = wid >> 1;

    const uint32_t* wp = g_Wsw_bi + ((size_t)(dir * 32 + (bid & 31)) << 16)
                       + jn * 128 + lane * 4;      // + k16*1024

    // staging: 16 cp16/thread; row tid>>3, seg (tid&7)+8j
    const int srow = tid >> 3;
    const int sseg = tid & 7;
    const uint32_t hs_row = s2u(hs) + (uint32_t)srow * SPF * 4;

    const int rowA = lane & 15;
    const int koffA = (lane >> 4) * 4;
    uint32_t haddr[2];
#pragma unroll
    for (int mf = 0; mf < 2; mf++)
        haddr[mf] = s2u(&hs[(wm + mf * 16 + rowA) * SPF + koffA]);

    // activation mapping: 4 pairs/thread
    int abl[4], au[4];
#pragma unroll
    for (int i = 0; i < 4; i++) {
        int p = tid + 512 * i;
        abl[i] = p >> 5;
        au[i] = p & 31;
    }
    float c_reg[4] = {0.0f, 0.0f, 0.0f, 0.0f};

    // prefetch P for step 0
    float pre[4][4];
    {
        const float* P = Pbase + (size_t)(dir ? (T_ - 1) : 0) * B_ * G_;
#pragma unroll
        for (int i = 0; i < 4; i++) {
            const float* Pb = P + (size_t)abl[i] * G_ + u0 + au[i];
            pre[i][0] = Pb[0];
            pre[i][1] = Pb[N_];
            pre[i][2] = Pb[2 * N_];
            pre[i][3] = Pb[3 * N_];
        }
    }

    for (int s = 0; s < T_; s++) {
        const int t = dir ? (T_ - 1 - s) : s;
        const __half* h_prev = g_h16[2 * dir + (s & 1)];
        __half* h_next = g_h16[2 * dir + ((s + 1) & 1)];
        __half* hist = g_bi16 + (size_t)t * B_ * 2 * N_ + dir * N_;

        // stage full h in two committed halves
        const __half* hp = h_prev + (size_t)srow * N_;
#pragma unroll
        for (int j = 0; j < 8; j++) {
            int seg = sseg + 8 * j;
            cp16(hs_row + seg * 16, hp + seg * 8);
        }
        cp_commit();
#pragma unroll
        for (int j = 8; j < 16; j++) {
            int seg = sseg + 8 * j;
            cp16(hs_row + seg * 16, hp + seg * 8);
        }
        cp_commit();

        uint4 wcur[4], wnext[4];
#pragma unroll
        for (int l = 0; l < 4; l++)
            wcur[l] = *(const uint4*)(wp + (size_t)l * 1024);

        float acc[2][2][4];   // [mf][nf][4] — 4 independent chains
#pragma unroll
        for (int mf = 0; mf < 2; mf++)
#pragma unroll
            for (int nf = 0; nf < 2; nf++)
#pragma unroll
                for (int j = 0; j < 4; j++) acc[mf][nf][j] = 0.0f;

        cp_wait<1>();
        __syncthreads();

#pragma unroll
        for (int grp = 0; grp < 16; grp++) {
            if (grp == 8) {
                cp_wait<0>();
                __syncthreads();
            }
            if (grp < 15) {
#pragma unroll
                for (int l = 0; l < 4; l++)
                    wnext[l] = *(const uint4*)(wp + (size_t)((grp + 1) * 4 + l) * 1024);
            }
#pragma unroll
            for (int l = 0; l < 4; l++) {
                const int k16 = grp * 4 + l;
                uint32_t af[2][4];
#pragma unroll
                for (int mf = 0; mf < 2; mf++)
                    ldsm_x4(af[mf][0], af[mf][1], af[mf][2], af[mf][3],
                            haddr[mf] + k16 * 32);
                uint32_t bf0[2] = { wcur[l].x, wcur[l].y };
                uint32_t bf1[2] = { wcur[l].z, wcur[l].w };
#pragma unroll
                for (int mf = 0; mf < 2; mf++) {
                    mma_f16(acc[mf][0], af[mf], bf0);
                    mma_f16(acc[mf][1], af[mf], bf1);
                }
            }
            if (grp < 15) {
#pragma unroll
                for (int l = 0; l < 4; l++) wcur[l] = wnext[l];
            }
        }

        // write gates
#pragma unroll
        for (int mf = 0; mf < 2; mf++)
#pragma unroll
            for (int nf = 0; nf < 2; nf++) {
                int row = wm + mf * 16 + gid;
                int col = jn * 16 + nf * 8 + 2 * tig;
                gates[row * GP + col]           = acc[mf][nf][0];
                gates[row * GP + col + 1]       = acc[mf][nf][1];
                gates[(row + 8) * GP + col]     = acc[mf][nf][2];
                gates[(row + 8) * GP + col + 1] = acc[mf][nf][3];
            }
        __syncthreads();

        // activation + state update (4 pairs/thread, c in regs)
#pragma unroll
        for (int i = 0; i < 4; i++) {
            int bl = abl[i];
            int u = au[i];
            int ug = u0 + u;
            float ig = gates[bl * GP + u]      + pre[i][0];
            float fg = gates[bl * GP + 32 + u] + pre[i][1];
            float gg = gates[bl * GP + 64 + u] + pre[i][2];
            float og = gates[bl * GP + 96 + u] + pre[i][3];
            ig = sig_f(ig);
            fg = sig_f(fg);
            gg = tanh_f(gg);
            og = sig_f(og);
            float cn = fg * c_reg[i] + ig * gg;
            c_reg[i] = cn;
            __half hn = __float2half_rn(og * tanh_f(cn));
            h_next[(size_t)bl * N_ + ug] = hn;
            hist[(size_t)bl * 2 * N_ + ug] = hn;
        }

        // prefetch next step's P before the barrier
        if (s + 1 < T_) {
            const int tn = dir ? (T_ - 2 - s) : (s + 1);
            const float* P = Pbase + (size_t)tn * B_ * G_;
#pragma unroll
            for (int i = 0; i < 4; i++) {
                const float* Pb = P + (size_t)abl[i] * G_ + u0 + au[i];
                pre[i][0] = Pb[0];
                pre[i][1] = Pb[N_];
                pre[i][2] = Pb[2 * N_];
                pre[i][3] = Pb[3 * N_];
            }
        }
        grid_barrier(dir, 32);
    }
}

// ---------------- persistent cell recurrence (wide blocks, c in regs) ----------------
// 32 blocks x 512 threads. 32 units (128 gate cols) per block.
__global__ __launch_bounds__(512, 1) void cell_mma_kernel(float* __restrict__ out)
{
    extern __shared__ uint32_t smem_u[];
    uint32_t* hs = smem_u;
    float* gates = (float*)(smem_u + 64 * SPF);

    const int bid = blockIdx.x;
    const int u0 = bid * 32;

    const int tid = threadIdx.x;
    const int lane = tid & 31;
    const int wid = tid >> 5;
    const int gid = lane >> 2;
    const int tig = lane & 3;
    const int wm = (wid & 1) * 32;
    const int jn = wid >> 1;

    const uint32_t* wp = g_Wsw_c + ((size_t)bid << 16) + jn * 128 + lane * 4;

    const int srow = tid >> 3;
    const int sseg = tid & 7;
    const uint32_t hs_row = s2u(hs) + (uint32_t)srow * SPF * 4;

    const int rowA = lane & 15;
    const int koffA = (lane >> 4) * 4;
    uint32_t haddr[2];
#pragma unroll
    for (int mf = 0; mf < 2; mf++)
        haddr[mf] = s2u(&hs[(wm + mf * 16 + rowA) * SPF + koffA]);

    int abl[4], au[4];
#pragma unroll
    for (int i = 0; i < 4; i++) {
        int p = tid + 512 * i;
        abl[i] = p >> 5;
        au[i] = p & 31;
    }
    float c_reg[4] = {0.0f, 0.0f, 0.0f, 0.0f};

    float pre[4][4];
    {
        const float* P = g_Pc;
#pragma unroll
        for (int i = 0; i < 4; i++) {
            const float* Pb = P + (size_t)abl[i] * G_ + u0 + au[i];
            pre[i][0] = Pb[0];
            pre[i][1] = Pb[N_];
            pre[i][2] = Pb[2 * N_];
            pre[i][3] = Pb[3 * N_];
        }
    }

    for (int s = 0; s < T_; s++) {
        const __half* h_prev = g_h16[4 + (s & 1)];
        __half* h_next = g_h16[4 + ((s + 1) & 1)];

        const __half* hp = h_prev + (size_t)srow * N_;
#pragma unroll
        for (int j = 0; j < 8; j++) {
            int seg = sseg + 8 * j;
            cp16(hs_row + seg * 16, hp + seg * 8);
        }
        cp_commit();
#pragma unroll
        for (int j = 8; j < 16; j++) {
            int seg = sseg + 8 * j;
            cp16(hs_row + seg * 16, hp + seg * 8);
        }
        cp_commit();

        uint4 wcur[4], wnext[4];
#pragma unroll
        for (int l = 0; l < 4; l++)
            wcur[l] = *(const uint4*)(wp + (size_t)l * 1024);

        float acc[2][2][4];
#pragma unroll
        for (int mf = 0; mf < 2; mf++)
#pragma unroll
            for (int nf = 0; nf < 2; nf++)
#pragma unroll
                for (int j = 0; j < 4; j++) acc[mf][nf][j] = 0.0f;

        cp_wait<1>();
        __syncthreads();

#pragma unroll
        for (int grp = 0; grp < 16; grp++) {
            if (grp == 8) {
                cp_wait<0>();
                __syncthreads();
            }
            if (grp < 15) {
#pragma unroll
                for (int l = 0; l < 4; l++)
                    wnext[l] = *(const uint4*)(wp + (size_t)((grp + 1) * 4 + l) * 1024);
            }
#pragma unroll
            for (int l = 0; l < 4; l++) {
                const int k16 = grp * 4 + l;
                uint32_t af[2][4];
#pragma unroll
                for (int mf = 0; mf < 2; mf++)
                    ldsm_x4(af[mf][0], af[mf][1], af[mf][2], af[mf][3],
                            haddr[mf] + k16 * 32);
                uint32_t bf0[2] = { wcur[l].x, wcur[l].y };
                uint32_t bf1[2] = { wcur[l].z, wcur[l].w };
#pragma unroll
                for (int mf = 0; mf < 2; mf++) {
                    mma_f16(acc[mf][0], af[mf], bf0);
                    mma_f16(acc[mf][1], af[mf], bf1);
                }
            }
            if (grp < 15) {
#pragma unroll
                for (int l = 0; l < 4; l++) wcur[l] = wnext[l];
            }
        }

#pragma unroll
        for (int mf = 0; mf < 2; mf++)
#pragma unroll
            for (int nf = 0; nf < 2; nf++) {
                int row = wm + mf * 16 + gid;
                int col = jn * 16 + nf * 8 + 2 * tig;
                gates[row * GP + col]           = acc[mf][nf][0];
                gates[row * GP + col + 1]       = acc[mf][nf][1];
                gates[(row + 8) * GP + col]     = acc[mf][nf][2];
                gates[(row + 8) * GP + col + 1] = acc[mf][nf][3];
            }
        __syncthreads();

#pragma unroll
        for (int i = 0; i < 4; i++) {
            int bl = abl[i];
            int u = au[i];
            int ug = u0 + u;
            float ig = gates[bl * GP + u]      + pre[i][0];
            float fg = gates[bl * GP + 32 + u] + pre[i][1];
            float gg = gates[bl * GP + 64 + u] + pre[i][2];
            float og = gates[bl * GP + 96 + u] + pre[i][3];
            ig = sig_f(ig);
            fg = sig_f(fg);
            gg = tanh_f(gg);
            og = sig_f(og);
            float cn = fg * c_reg[i] + ig * gg;
            c_reg[i] = cn;
            float hn = og * tanh_f(cn);
            out[((size_t)bl * T_ + s) * N_ + ug] = hn;
            h_next[(size_t)bl * N_ + ug] = __float2half_rn(hn);
            if (s == T_ - 1) {
                const size_t tail = (size_t)B_ * T_ * N_;
                size_t gi = (size_t)bl * N_ + ug;
                out[tail + gi] = hn;
                out[tail + (size_t)B_ * N_ + gi] = cn;
            }
        }

        if (s + 1 < T_) {
            const float* P = g_Pc + (size_t)(s + 1) * B_ * G_;
#pragma unroll
            for (int i = 0; i < 4; i++) {
                const float* Pb = P + (size_t)abl[i] * G_ + u0 + au[i];
                pre[i][0] = Pb[0];
                pre[i][1] = Pb[N_];
                pre[i][2] = Pb[2 * N_];
                pre[i][3] = Pb[3 * N_];
            }
        }
        grid_barrier(0, 32);
    }
}

// ---------------- host launcher ----------------
extern "C" void kernel_launch(void* const* d_in, const int* in_sizes, int n_in,
                              void* d_out, int out_size) {
    (void)in_sizes; (void)n_in; (void)out_size;
    const float* x     = (const float*)d_in[0];
    const float* Wf_ih = (const float*)d_in[1];
    const float* Wf_hh = (const float*)d_in[2];
    const float* bf    = (const float*)d_in[3];
    const float* Wb_ih = (const float*)d_in[4];
    const float* Wb_hh = (const float*)d_in[5];
    const float* bb    = (const float*)d_in[6];
    const float* Wc_ih = (const float*)d_in[7];
    const float* Wc_hh = (const float*)d_in[8];
    const float* bc    = (const float*)d_in[9];
    float* out = (float*)d_out;

    __half *wih, *x16, *bi16;
    cudaGetSymbolAddress((void**)&wih, g_Wih16);
    cudaGetSymbolAddress((void**)&x16, g_x16);
    cudaGetSymbolAddress((void**)&bi16, g_bi16);
    const __half* wih_f = wih;
    const __half* wih_b = wih + (4u << 20);
    const __half* wih_c = wih + (8u << 20);

    const int rec_smem = (64 * SPF + 64 * GP) * 4;   // 165888
    cudaFuncSetAttribute(bilstm_mma_kernel, cudaFuncAttributeMaxDynamicSharedMemorySize, rec_smem);
    cudaFuncSetAttribute(cell_mma_kernel, cudaFuncAttributeMaxDynamicSharedMemorySize, rec_smem);

    // 1) init + one-time conversions/swizzles
    zero_state_kernel<<<384, 512>>>();
    xconv_kernel<<<(8 << 20) / 256, 256>>>(x);
    wconv_ih_kernel<<<(4 << 20) / 256, 256>>>(Wf_ih, Wb_ih, Wc_ih);
    wswz_bi_kernel<<<16384, 256>>>(Wf_hh, Wb_hh);
    wswz_cell_kernel<<<8192, 256>>>(Wc_hh);

    // 2) input projections (fp16 mma)
    dim3 ggrid(G_ / 128, (T_ * B_) / 128);
    gemm_f16_kernel<<<ggrid, 256>>>(x16, wih_f, bf, N_, 1, 0);
    gemm_f16_kernel<<<ggrid, 256>>>(x16, wih_b, bb, N_, 1, 1);

    // 3) bilstm recurrence (wide persistent blocks)
    bilstm_mma_kernel<<<64, 512, rec_smem>>>();

    // 4) cell input projection (K = 2N, A = g_bi16)
    gemm_f16_kernel<<<ggrid, 256>>>(bi16, wih_c, bc, 2 * N_, 0, 2);

    // 5) cell recurrence + output (+ hT/cT tail at final step)
    cell_mma_kernel<<<32, 512, rec_smem>>>(out);
}

// round 12
// speedup vs baseline: 1.1495x; 1.1495x over previous
#include <cuda_runtime.h>
#include <cuda_fp16.h>
#include <cstdint>
#include <math.h>

#define T_ 512
#define B_ 64
#define N_ 1024
#define G_ 4096   // 4*N
#define SPF 516   // smem pitch (u32) for a FULL fp16 h row (512 u32 + 4 pad)

// ---------------- static device scratch ----------------
__device__ float g_Pf[(size_t)T_ * B_ * G_];
__device__ float g_Pb[(size_t)T_ * B_ * G_];
__device__ float g_Pc[(size_t)T_ * B_ * G_];
__device__ __half g_bi16[(size_t)T_ * B_ * 2 * N_];   // bilstm output, fp16
__device__ __half g_x16[(size_t)B_ * T_ * N_];        // inputs converted to fp16
__device__ __half g_Wih16[16 * 1024 * 1024];          // fp16 W_ih: f(4M) b(4M) c(8M)
__device__ __half g_h16[6][B_ * N_];                  // fp16 recurrent h
__device__ uint32_t g_Wsw_bi[2 * 64 * 32768];         // fp16 frag-swizzled W_hh fwd/bwd
__device__ uint32_t g_Wsw_c[128 * 16384];             // fp16 frag-swizzled W_hh cell

__device__ unsigned g_barc[2] = {0, 0};
__device__ unsigned g_barg[2] = {0, 0};

__device__ __forceinline__ void grid_barrier(int which, unsigned nb) {
    __syncthreads();
    if (threadIdx.x == 0) {
        __threadfence();
        volatile unsigned* gen = &g_barg[which];
        unsigned g = *gen;
        if (atomicAdd(&g_barc[which], 1) == nb - 1) {
            g_barc[which] = 0;
            __threadfence();
            atomicExch((unsigned*)gen, g + 1);
        } else {
            while (*gen == g) { }
            __threadfence();
        }
    }
    __syncthreads();
}

__global__ void zero_state_kernel() {
    int i = blockIdx.x * blockDim.x + threadIdx.x;
    ((uint32_t*)g_h16)[i] = 0;   // 196608 u32 = all 6 h buffers
}

// ---------------- helpers ----------------
__device__ __forceinline__ void mma_f16(float* c, const uint32_t* a, const uint32_t* b) {
    asm volatile(
        "mma.sync.aligned.m16n8k16.row.col.f32.f16.f16.f32 "
        "{%0,%1,%2,%3}, {%4,%5,%6,%7}, {%8,%9}, {%0,%1,%2,%3};"
        : "+f"(c[0]), "+f"(c[1]), "+f"(c[2]), "+f"(c[3])
        : "r"(a[0]), "r"(a[1]), "r"(a[2]), "r"(a[3]), "r"(b[0]), "r"(b[1]));
}
__device__ __forceinline__ void ldsm_x4(uint32_t& r0, uint32_t& r1, uint32_t& r2, uint32_t& r3,
                                        uint32_t addr) {
    asm volatile("ldmatrix.sync.aligned.m8n8.x4.shared.b16 {%0,%1,%2,%3}, [%4];"
                 : "=r"(r0), "=r"(r1), "=r"(r2), "=r"(r3) : "r"(addr));
}
__device__ __forceinline__ void cp16(uint32_t dst, const void* src) {
    asm volatile("cp.async.cg.shared.global [%0], [%1], 16;" :: "r"(dst), "l"(src));
}
__device__ __forceinline__ void cp_commit() { asm volatile("cp.async.commit_group;"); }
template <int NN> __device__ __forceinline__ void cp_wait() {
    asm volatile("cp.async.wait_group %0;" :: "n"(NN));
}
__device__ __forceinline__ uint32_t pack2h(float a, float b) {
    __half2 h = __floats2half2_rn(a, b);
    return *(uint32_t*)&h;
}
__device__ __forceinline__ uint32_t s2u(const void* p) {
    return (uint32_t)__cvta_generic_to_shared(p);
}
// fast activations (rel error ~1e-6, far below fp16 noise at 3.9e-4)
__device__ __forceinline__ float sig_f(float x) {
    return __fdividef(1.0f, 1.0f + __expf(-x));
}
__device__ __forceinline__ float tanh_f(float x) {
    return 1.0f - 2.0f * __fdividef(1.0f, __expf(2.0f * x) + 1.0f);
}

// ---------------- one-time conversions ----------------
__global__ void xconv_kernel(const float* __restrict__ x) {
    size_t i = (size_t)blockIdx.x * blockDim.x + threadIdx.x;
    float4 v = ((const float4*)x)[i];
    uint2 o;
    o.x = pack2h(v.x, v.y);
    o.y = pack2h(v.z, v.w);
    ((uint2*)g_x16)[i] = o;
}
__global__ void wconv_ih_kernel(const float* __restrict__ Wf,
                                const float* __restrict__ Wb,
                                const float* __restrict__ Wc) {
    size_t i = (size_t)blockIdx.x * blockDim.x + threadIdx.x;
    const float* src;
    size_t off;
    if (i < (1u << 20))      { src = Wf; off = i; }
    else if (i < (2u << 20)) { src = Wb; off = i - (1u << 20); }
    else                     { src = Wc; off = i - (2u << 20); }
    float4 v = ((const float4*)src)[off];
    uint2 o;
    o.x = pack2h(v.x, v.y);
    o.y = pack2h(v.z, v.w);
    ((uint2*)g_Wih16)[i] = o;
}

// ---------------- one-time W_hh fragment swizzles (fp16) ----------------
// bilstm: idx(u32) = region*32768 + k16*512 + jn*64 + lane*2 + r
__global__ void wswz_bi_kernel(const float* __restrict__ Wf,
                               const float* __restrict__ Wb) {
    size_t idx = (size_t)blockIdx.x * blockDim.x + threadIdx.x;
    unsigned region = idx >> 15;
    unsigned w = idx & 32767;
    int dir = region >> 6, ublk = region & 63;
    int k16 = w >> 9;
    int jn = (w >> 6) & 7;
    int lane = (w >> 1) & 31;
    int r = w & 1;
    int gid = lane >> 2, tig = lane & 3;
    int col = jn * 8 + gid;
    int gate = col >> 4, u = col & 15;
    int row = gate * N_ + ublk * 16 + u;
    int k = k16 * 16 + r * 8 + tig * 2;
    const float* W = dir ? Wb : Wf;
    g_Wsw_bi[idx] = pack2h(W[(size_t)row * N_ + k], W[(size_t)row * N_ + k + 1]);
}
__global__ void wswz_cell_kernel(const float* __restrict__ Wc) {
    size_t idx = (size_t)blockIdx.x * blockDim.x + threadIdx.x;
    unsigned blk = idx >> 14;
    unsigned w = idx & 16383;
    int k16 = w >> 8;
    int nwq = (w >> 6) & 3;
    int lane = (w >> 1) & 31;
    int r = w & 1;
    int gid = lane >> 2, tig = lane & 3;
    int col = nwq * 8 + gid;
    int gate = col >> 3, u = col & 7;
    int row = gate * N_ + blk * 8 + u;
    int k = k16 * 16 + r * 8 + tig * 2;
    g_Wsw_c[idx] = pack2h(Wc[(size_t)row * N_ + k], Wc[(size_t)row * N_ + k + 1]);
}

// ---------------- fp16 GEMM: 128x128x32, cp.async double buffered, ldmatrix ----------------
__global__ __launch_bounds__(256, 2) void gemm_f16_kernel(
    const __half* __restrict__ A,
    const __half* __restrict__ Wt,
    const float* __restrict__ bias,
    int K, int a_mode, int dst_sel)
{
    float* C = (dst_sel == 0) ? g_Pf : (dst_sel == 1) ? g_Pb : g_Pc;

    __shared__ __align__(16) uint32_t As[2][128 * 20];
    __shared__ __align__(16) uint32_t Ws[2][128 * 20];

    const int tid = threadIdx.x;
    const int m0 = blockIdx.y * 128;
    const int g0 = blockIdx.x * 128;

    const __half* asrc[2];
    const __half* wsrc[2];
    int lrow[2], lseg[2];
#pragma unroll
    for (int i = 0; i < 2; i++) {
        int idx = tid + 256 * i;
        int row = idx >> 2;
        int seg = idx & 3;
        int m = m0 + row;
        int prow = (a_mode == 1) ? ((m & 63) * T_ + (m >> 6)) : m;
        asrc[i] = A + (size_t)prow * K + seg * 8;
        wsrc[i] = Wt + (size_t)(g0 + row) * K + seg * 8;
        lrow[i] = row; lseg[i] = seg;
    }
    uint32_t asm_a[2][2], wsm_a[2][2];
#pragma unroll
    for (int b = 0; b < 2; b++)
#pragma unroll
        for (int i = 0; i < 2; i++) {
            asm_a[b][i] = s2u(&As[b][lrow[i] * 20 + lseg[i] * 4]);
            wsm_a[b][i] = s2u(&Ws[b][lrow[i] * 20 + lseg[i] * 4]);
        }

    const int lane = tid & 31;
    const int wid = tid >> 5;
    const int gid = lane >> 2;
    const int tig = lane & 3;
    const int wm = (wid & 3) * 32;
    const int wn = (wid >> 2) * 64;

    const int rowA = lane & 15;
    const int koffA = (lane >> 4) * 4;
    const int cB = (lane & 7) + ((lane >> 4) << 3);
    const int kB = ((lane >> 3) & 1) * 4;

    uint32_t aaddr[2][2], baddr[2][4];
#pragma unroll
    for (int b = 0; b < 2; b++) {
#pragma unroll
        for (int mf = 0; mf < 2; mf++)
            aaddr[b][mf] = s2u(&As[b][(wm + mf * 16 + rowA) * 20 + koffA]);
#pragma unroll
        for (int np = 0; np < 4; np++)
            baddr[b][np] = s2u(&Ws[b][(wn + np * 16 + cB) * 20 + kB]);
    }

    float acc[2][8][4];
#pragma unroll
    for (int mf = 0; mf < 2; mf++)
#pragma unroll
        for (int nf = 0; nf < 8; nf++)
#pragma unroll
            for (int j = 0; j < 4; j++) acc[mf][nf][j] = 0.0f;

    const int NC = K / 32;
#pragma unroll
    for (int i = 0; i < 2; i++) {
        cp16(asm_a[0][i], asrc[i]);
        cp16(wsm_a[0][i], wsrc[i]);
    }
    cp_commit();

    for (int ch = 0; ch < NC; ch++) {
        const int buf = ch & 1;
        if (ch + 1 < NC) {
            const int nb = (ch + 1) & 1;
            const int k0 = (ch + 1) * 32;
#pragma unroll
            for (int i = 0; i < 2; i++) {
                cp16(asm_a[nb][i], asrc[i] + k0);
                cp16(wsm_a[nb][i], wsrc[i] + k0);
            }
            cp_commit();
            cp_wait<1>();
        } else {
            cp_wait<0>();
        }
        __syncthreads();

#pragma unroll
        for (int ks = 0; ks < 2; ks++) {
            const int kbb = ks * 32;
            uint32_t af[2][4];
#pragma unroll
            for (int mf = 0; mf < 2; mf++)
                ldsm_x4(af[mf][0], af[mf][1], af[mf][2], af[mf][3], aaddr[buf][mf] + kbb);
            uint32_t bf[8][2];
#pragma unroll
            for (int np = 0; np < 4; np++)
                ldsm_x4(bf[2 * np][0], bf[2 * np][1], bf[2 * np + 1][0], bf[2 * np + 1][1],
                        baddr[buf][np] + kbb);
#pragma unroll
            for (int mf = 0; mf < 2; mf++)
#pragma unroll
                for (int nf = 0; nf < 8; nf++)
                    mma_f16(acc[mf][nf], af[mf], bf[nf]);
        }
        __syncthreads();
    }

#pragma unroll
    for (int mf = 0; mf < 2; mf++) {
#pragma unroll
        for (int nf = 0; nf < 8; nf++) {
            int row = m0 + wm + mf * 16 + gid;
            int col = g0 + wn + nf * 8 + 2 * tig;
            float b0 = bias[col], b1 = bias[col + 1];
            float2 v0 = make_float2(acc[mf][nf][0] + b0, acc[mf][nf][1] + b1);
            float2 v1 = make_float2(acc[mf][nf][2] + b0, acc[mf][nf][3] + b1);
            *(float2*)&C[(size_t)row * G_ + col] = v0;
            *(float2*)&C[(size_t)(row + 8) * G_ + col] = v1;
        }
    }
}

// ---------------- persistent bilstm recurrence (R9 shape + c-in-regs + fast act + P prefetch) ----------------
// 128 blocks x 512 threads. dir = bid>>6, 16 units (64 gate cols) per block.
__global__ __launch_bounds__(512, 1) void bilstm_mma_kernel()
{
    extern __shared__ uint32_t smem_u[];
    uint32_t* hs = smem_u;                         // [64][SPF]
    float* gates = (float*)(smem_u + 64 * SPF);    // [64][68]

    const int bid = blockIdx.x;
    const int dir = bid >> 6;
    const int u0 = (bid & 63) * 16;
    const float* Pbase = dir ? g_Pb : g_Pf;

    const int tid = threadIdx.x;
    const int lane = tid & 31;
    const int wid = tid >> 5;
    const int gid = lane >> 2;
    const int tig = lane & 3;
    const int wm = (wid & 1) * 32;
    const int jn = wid >> 1;
    const int wn = jn * 8;

    const uint32_t* wp = g_Wsw_bi + ((size_t)(dir * 64 + (bid & 63)) << 15)
                       + jn * 64 + lane * 2;       // + k16*512

    // staging: 16 cp16/thread; row tid>>3, segs (tid&7)+8j
    const int srow = tid >> 3;
    const int sseg = tid & 7;
    const uint32_t hs_row = s2u(hs) + (uint32_t)srow * SPF * 4;

    const int rowA = lane & 15;
    const int koffA = (lane >> 4) * 4;
    uint32_t haddr[2];
#pragma unroll
    for (int mf = 0; mf < 2; mf++)
        haddr[mf] = s2u(&hs[(wm + mf * 16 + rowA) * SPF + koffA]);

    // activation indices (2 pairs per thread, static across steps)
    int abl[2], au[2];
#pragma unroll
    for (int i = 0; i < 2; i++) {
        int p = tid + 512 * i;
        abl[i] = p >> 4;
        au[i] = p & 15;
    }
    float c_reg[2] = {0.0f, 0.0f};

    // prefetch P for step 0
    float pre[2][4];
    {
        const float* P = Pbase + (size_t)(dir ? (T_ - 1) : 0) * B_ * G_;
#pragma unroll
        for (int i = 0; i < 2; i++) {
            const float* Pb = P + (size_t)abl[i] * G_ + u0 + au[i];
            pre[i][0] = Pb[0];
            pre[i][1] = Pb[N_];
            pre[i][2] = Pb[2 * N_];
            pre[i][3] = Pb[3 * N_];
        }
    }

    for (int s = 0; s < T_; s++) {
        const int t = dir ? (T_ - 1 - s) : s;
        const __half* h_prev = g_h16[2 * dir + (s & 1)];
        __half* h_next = g_h16[2 * dir + ((s + 1) & 1)];
        __half* hist = g_bi16 + (size_t)t * B_ * 2 * N_ + dir * N_;

        // stage full h in two committed halves
        const __half* hp = h_prev + (size_t)srow * N_;
#pragma unroll
        for (int j = 0; j < 8; j++) {
            int seg = sseg + 8 * j;
            cp16(hs_row + seg * 16, hp + seg * 8);
        }
        cp_commit();
#pragma unroll
        for (int j = 8; j < 16; j++) {
            int seg = sseg + 8 * j;
            cp16(hs_row + seg * 16, hp + seg * 8);
        }
        cp_commit();

        // W queue group 0
        uint2 wcur[8], wnext[8];
#pragma unroll
        for (int l = 0; l < 8; l++)
            wcur[l] = *(const uint2*)(wp + (size_t)l * 512);

        float acc[2][4];
#pragma unroll
        for (int mf = 0; mf < 2; mf++)
#pragma unroll
            for (int j = 0; j < 4; j++) acc[mf][j] = 0.0f;

        cp_wait<1>();
        __syncthreads();

#pragma unroll
        for (int gi = 0; gi < 8; gi++) {
            if (gi == 4) {
                cp_wait<0>();
                __syncthreads();
            }
            if (gi < 7) {
#pragma unroll
                for (int l = 0; l < 8; l++)
                    wnext[l] = *(const uint2*)(wp + (size_t)((gi + 1) * 8 + l) * 512);
            }
#pragma unroll
            for (int l = 0; l < 8; l++) {
                const int g16 = gi * 8 + l;
                uint32_t af[2][4];
#pragma unroll
                for (int mf = 0; mf < 2; mf++)
                    ldsm_x4(af[mf][0], af[mf][1], af[mf][2], af[mf][3],
                            haddr[mf] + g16 * 32);
                uint32_t bf[2] = { wcur[l].x, wcur[l].y };
#pragma unroll
                for (int mf = 0; mf < 2; mf++)
                    mma_f16(acc[mf], af[mf], bf);
            }
            if (gi < 7) {
#pragma unroll
                for (int l = 0; l < 8; l++) wcur[l] = wnext[l];
            }
        }
        __syncthreads();

#pragma unroll
        for (int mf = 0; mf < 2; mf++) {
            int row = wm + mf * 16 + gid;
            int col = wn + 2 * tig;
            gates[row * 68 + col]           = acc[mf][0];
            gates[row * 68 + col + 1]       = acc[mf][1];
            gates[(row + 8) * 68 + col]     = acc[mf][2];
            gates[(row + 8) * 68 + col + 1] = acc[mf][3];
        }
        __syncthreads();

        // activation + state update (c in regs, fast activations)
#pragma unroll
        for (int i = 0; i < 2; i++) {
            int bl = abl[i];
            int u = au[i];
            int ug = u0 + u;
            float ig = gates[bl * 68 + u]      + pre[i][0];
            float fg = gates[bl * 68 + 16 + u] + pre[i][1];
            float gg = gates[bl * 68 + 32 + u] + pre[i][2];
            float og = gates[bl * 68 + 48 + u] + pre[i][3];
            ig = sig_f(ig);
            fg = sig_f(fg);
            gg = tanh_f(gg);
            og = sig_f(og);
            float cn = fg * c_reg[i] + ig * gg;
            c_reg[i] = cn;
            __half hn = __float2half_rn(og * tanh_f(cn));
            h_next[(size_t)bl * N_ + ug] = hn;
            hist[(size_t)bl * 2 * N_ + ug] = hn;
        }

        // prefetch next step's P before the barrier (static data, fully hides latency)
        if (s + 1 < T_) {
            const int tn = dir ? (T_ - 2 - s) : (s + 1);
            const float* P = Pbase + (size_t)tn * B_ * G_;
#pragma unroll
            for (int i = 0; i < 2; i++) {
                const float* Pb = P + (size_t)abl[i] * G_ + u0 + au[i];
                pre[i][0] = Pb[0];
                pre[i][1] = Pb[N_];
                pre[i][2] = Pb[2 * N_];
                pre[i][3] = Pb[3 * N_];
            }
        }
        grid_barrier(dir, 64);
    }
}

// ---------------- persistent cell recurrence (R9 shape + c-in-regs + fast act + P prefetch) ----------------
// 128 blocks x 512 threads. u0 = bid*8, kh split over k halves, W in smem.
__global__ __launch_bounds__(512, 1) void cell_mma_kernel(float* __restrict__ out)
{
    extern __shared__ uint32_t smem_u[];
    uint32_t* wsm = smem_u;
    uint32_t* hs = smem_u + 16384;
    float* gates0 = (float*)(hs + 64 * SPF);
    float* gates1 = gates0 + 64 * 36;

    const int bid = blockIdx.x;
    const int u0 = bid * 8;

    const int tid = threadIdx.x;
    const int lane = tid & 31;
    const int wid = tid >> 5;
    const int gid = lane >> 2;
    const int tig = lane & 3;
    const int kh = wid >> 3;
    const int w8 = wid & 7;
    const int wm = (w8 & 1) * 32;
    const int nwq = w8 >> 1;
    const int wn = nwq * 8;

    // one-time: W region to smem (64 KB)
    {
        const uint4* wr = (const uint4*)(g_Wsw_c + ((size_t)bid << 14));
#pragma unroll
        for (int i = 0; i < 8; i++)
            ((uint4*)wsm)[tid + 512 * i] = wr[tid + 512 * i];
    }
    __syncthreads();
    const uint32_t* wq = wsm + nwq * 64 + lane * 2;   // + k16*256
    const int k16base = kh * 32;

    const int srow = tid >> 3;
    const int sseg = tid & 7;
    const uint32_t hs_row = s2u(hs) + (uint32_t)srow * SPF * 4;

    const int rowA = lane & 15;
    const int koffA = (lane >> 4) * 4;
    uint32_t haddr[2];
#pragma unroll
    for (int mf = 0; mf < 2; mf++)
        haddr[mf] = s2u(&hs[(wm + mf * 16 + rowA) * SPF + kh * 256 + koffA]);

    const int abl = tid >> 3;
    const int au = tid & 7;
    float c_reg = 0.0f;

    // prefetch P for step 0
    float pre[4];
    {
        const float* Pb = g_Pc + (size_t)abl * G_ + u0 + au;
        pre[0] = Pb[0];
        pre[1] = Pb[N_];
        pre[2] = Pb[2 * N_];
        pre[3] = Pb[3 * N_];
    }

    for (int s = 0; s < T_; s++) {
        const __half* h_prev = g_h16[4 + (s & 1)];
        __half* h_next = g_h16[4 + ((s + 1) & 1)];

        // stage full h (single phase)
        const __half* hp = h_prev + (size_t)srow * N_;
#pragma unroll
        for (int j = 0; j < 16; j++) {
            int seg = sseg + 8 * j;
            cp16(hs_row + seg * 16, hp + seg * 8);
        }
        cp_commit();

        float acc[2][4];
#pragma unroll
        for (int mf = 0; mf < 2; mf++)
#pragma unroll
            for (int j = 0; j < 4; j++) acc[mf][j] = 0.0f;

        cp_wait<0>();
        __syncthreads();

#pragma unroll
        for (int l = 0; l < 32; l++) {
            uint32_t af[2][4];
#pragma unroll
            for (int mf = 0; mf < 2; mf++)
                ldsm_x4(af[mf][0], af[mf][1], af[mf][2], af[mf][3],
                        haddr[mf] + l * 32);
            uint2 wv = *(const uint2*)(wq + (size_t)(k16base + l) * 256);
            uint32_t bf[2] = { wv.x, wv.y };
#pragma unroll
            for (int mf = 0; mf < 2; mf++)
                mma_f16(acc[mf], af[mf], bf);
        }
        __syncthreads();

        float* G = kh ? gates1 : gates0;
#pragma unroll
        for (int mf = 0; mf < 2; mf++) {
            int row = wm + mf * 16 + gid;
            int col = wn + 2 * tig;
            G[row * 36 + col]           = acc[mf][0];
            G[row * 36 + col + 1]       = acc[mf][1];
            G[(row + 8) * 36 + col]     = acc[mf][2];
            G[(row + 8) * 36 + col + 1] = acc[mf][3];
        }
        __syncthreads();

        {
            int ug = u0 + au;
            float ig = gates0[abl * 36 + au]      + gates1[abl * 36 + au]      + pre[0];
            float fg = gates0[abl * 36 + 8 + au]  + gates1[abl * 36 + 8 + au]  + pre[1];
            float gg = gates0[abl * 36 + 16 + au] + gates1[abl * 36 + 16 + au] + pre[2];
            float og = gates0[abl * 36 + 24 + au] + gates1[abl * 36 + 24 + au] + pre[3];
            ig = sig_f(ig);
            fg = sig_f(fg);
            gg = tanh_f(gg);
            og = sig_f(og);
            float cn = fg * c_reg + ig * gg;
            c_reg = cn;
            float hn = og * tanh_f(cn);
            out[((size_t)abl * T_ + s) * N_ + ug] = hn;
            h_next[(size_t)abl * N_ + ug] = __float2half_rn(hn);
            if (s == T_ - 1) {
                const size_t tail = (size_t)B_ * T_ * N_;
                size_t gi = (size_t)abl * N_ + ug;
                out[tail + gi] = hn;
                out[tail + (size_t)B_ * N_ + gi] = cn;
            }
        }

        // prefetch next step's P before the barrier
        if (s + 1 < T_) {
            const float* Pb = g_Pc + (size_t)(s + 1) * B_ * G_ + (size_t)abl * G_ + u0 + au;
            pre[0] = Pb[0];
            pre[1] = Pb[N_];
            pre[2] = Pb[2 * N_];
            pre[3] = Pb[3 * N_];
        }
        grid_barrier(0, 128);
    }
}

// ---------------- host launcher ----------------
extern "C" void kernel_launch(void* const* d_in, const int* in_sizes, int n_in,
                              void* d_out, int out_size) {
    (void)in_sizes; (void)n_in; (void)out_size;
    const float* x     = (const float*)d_in[0];
    const float* Wf_ih = (const float*)d_in[1];
    const float* Wf_hh = (const float*)d_in[2];
    const float* bf    = (const float*)d_in[3];
    const float* Wb_ih = (const float*)d_in[4];
    const float* Wb_hh = (const float*)d_in[5];
    const float* bb    = (const float*)d_in[6];
    const float* Wc_ih = (const float*)d_in[7];
    const float* Wc_hh = (const float*)d_in[8];
    const float* bc    = (const float*)d_in[9];
    float* out = (float*)d_out;

    __half *wih, *x16, *bi16;
    cudaGetSymbolAddress((void**)&wih, g_Wih16);
    cudaGetSymbolAddress((void**)&x16, g_x16);
    cudaGetSymbolAddress((void**)&bi16, g_bi16);
    const __half* wih_f = wih;
    const __half* wih_b = wih + (4u << 20);
    const __half* wih_c = wih + (8u << 20);

    const int bilstm_smem = (64 * SPF + 64 * 68) * 4;                 // 149504
    const int cell_smem   = (16384 + 64 * SPF + 2 * 64 * 36) * 4;     // 216064
    cudaFuncSetAttribute(bilstm_mma_kernel, cudaFuncAttributeMaxDynamicSharedMemorySize, bilstm_smem);
    cudaFuncSetAttribute(cell_mma_kernel, cudaFuncAttributeMaxDynamicSharedMemorySize, cell_smem);

    // 1) init + one-time conversions/swizzles
    zero_state_kernel<<<384, 512>>>();
    xconv_kernel<<<(8 << 20) / 256, 256>>>(x);
    wconv_ih_kernel<<<(4 << 20) / 256, 256>>>(Wf_ih, Wb_ih, Wc_ih);
    wswz_bi_kernel<<<(4 << 20) / 256, 256>>>(Wf_hh, Wb_hh);
    wswz_cell_kernel<<<(2 << 20) / 256, 256>>>(Wc_hh);

    // 2) input projections (fp16 mma)
    dim3 ggrid(G_ / 128, (T_ * B_) / 128);
    gemm_f16_kernel<<<ggrid, 256>>>(x16, wih_f, bf, N_, 1, 0);
    gemm_f16_kernel<<<ggrid, 256>>>(x16, wih_b, bb, N_, 1, 1);

    // 3) bilstm recurrence
    bilstm_mma_kernel<<<128, 512, bilstm_smem>>>();

    // 4) cell input projection (K = 2N, A = g_bi16)
    gemm_f16_kernel<<<ggrid, 256>>>(bi16, wih_c, bc, 2 * N_, 0, 2);

    // 5) cell recurrence + output (+ hT/cT tail at final step)
    cell_mma_kernel<<<128, 512, cell_smem>>>(out);
}

// round 13
// speedup vs baseline: 1.2105x; 1.0531x over previous
#include <cuda_runtime.h>
#include <cuda_fp16.h>
#include <cstdint>
#include <math.h>

#define T_ 512
#define B_ 64
#define N_ 1024
#define G_ 4096   // 4*N
#define SPH 68    // smem pitch (u32) for a 128-fp16 h chunk row (64 u32 + 4 pad)

// ---------------- static device scratch ----------------
__device__ float g_Pf[(size_t)T_ * B_ * G_];
__device__ float g_Pb[(size_t)T_ * B_ * G_];
__device__ float g_Pc[(size_t)T_ * B_ * G_];
__device__ __half g_bi16[(size_t)T_ * B_ * 2 * N_];   // bilstm output, fp16
__device__ __half g_x16[(size_t)B_ * T_ * N_];        // inputs converted to fp16
__device__ __half g_Wih16[16 * 1024 * 1024];          // fp16 W_ih: f(4M) b(4M) c(8M)
__device__ __half g_h16[6][B_ * N_];                  // fp16 recurrent h
__device__ uint32_t g_Wsw_bi[2 * 64 * 32768];         // fp16 frag-swizzled W_hh fwd/bwd
__device__ uint32_t g_Wsw_c[128 * 16384];             // fp16 frag-swizzled W_hh cell

__device__ unsigned g_barc[2] = {0, 0};
__device__ unsigned g_barg[2] = {0, 0};

__device__ __forceinline__ void grid_barrier(int which, unsigned nb) {
    __syncthreads();
    if (threadIdx.x == 0) {
        __threadfence();
        volatile unsigned* gen = &g_barg[which];
        unsigned g = *gen;
        if (atomicAdd(&g_barc[which], 1) == nb - 1) {
            g_barc[which] = 0;
            __threadfence();
            atomicExch((unsigned*)gen, g + 1);
        } else {
            while (*gen == g) { }
            __threadfence();
        }
    }
    __syncthreads();
}

// ---------------- helpers ----------------
__device__ __forceinline__ void mma_f16(float* c, const uint32_t* a, const uint32_t* b) {
    asm volatile(
        "mma.sync.aligned.m16n8k16.row.col.f32.f16.f16.f32 "
        "{%0,%1,%2,%3}, {%4,%5,%6,%7}, {%8,%9}, {%0,%1,%2,%3};"
        : "+f"(c[0]), "+f"(c[1]), "+f"(c[2]), "+f"(c[3])
        : "r"(a[0]), "r"(a[1]), "r"(a[2]), "r"(a[3]), "r"(b[0]), "r"(b[1]));
}
__device__ __forceinline__ void ldsm_x4(uint32_t& r0, uint32_t& r1, uint32_t& r2, uint32_t& r3,
                                        uint32_t addr) {
    asm volatile("ldmatrix.sync.aligned.m8n8.x4.shared.b16 {%0,%1,%2,%3}, [%4];"
                 : "=r"(r0), "=r"(r1), "=r"(r2), "=r"(r3) : "r"(addr));
}
__device__ __forceinline__ void cp16(uint32_t dst, const void* src) {
    asm volatile("cp.async.cg.shared.global [%0], [%1], 16;" :: "r"(dst), "l"(src));
}
__device__ __forceinline__ void cp_commit() { asm volatile("cp.async.commit_group;"); }
template <int NN> __device__ __forceinline__ void cp_wait() {
    asm volatile("cp.async.wait_group %0;" :: "n"(NN));
}
__device__ __forceinline__ uint32_t pack2h(float a, float b) {
    __half2 h = __floats2half2_rn(a, b);
    return *(uint32_t*)&h;
}
__device__ __forceinline__ uint32_t s2u(const void* p) {
    return (uint32_t)__cvta_generic_to_shared(p);
}
__device__ __forceinline__ float sig_f(float x) {
    return __fdividef(1.0f, 1.0f + __expf(-x));
}
__device__ __forceinline__ float tanh_f(float x) {
    return 1.0f - 2.0f * __fdividef(1.0f, __expf(2.0f * x) + 1.0f);
}

// ---------------- merged one-time prep: xconv + wconv + zero ----------------
__global__ void prep_all_kernel(const float* __restrict__ x,
                                const float* __restrict__ Wf,
                                const float* __restrict__ Wb,
                                const float* __restrict__ Wc) {
    const int bid = blockIdx.x;
    const int tid = threadIdx.x;
    if (bid < 32768) {                     // xconv: 8M float4
        size_t i = (size_t)bid * 256 + tid;
        float4 v = ((const float4*)x)[i];
        uint2 o;
        o.x = pack2h(v.x, v.y);
        o.y = pack2h(v.z, v.w);
        ((uint2*)g_x16)[i] = o;
    } else if (bid < 49152) {              // wconv: 4M float4
        size_t i = (size_t)(bid - 32768) * 256 + tid;
        const float* src;
        size_t off;
        if (i < (1u << 20))      { src = Wf; off = i; }
        else if (i < (2u << 20)) { src = Wb; off = i - (1u << 20); }
        else                     { src = Wc; off = i - (2u << 20); }
        float4 v = ((const float4*)src)[off];
        uint2 o;
        o.x = pack2h(v.x, v.y);
        o.y = pack2h(v.z, v.w);
        ((uint2*)g_Wih16)[i] = o;
    } else {                               // zero h: 196608 u32
        size_t i = (size_t)(bid - 49152) * 256 + tid;
        ((uint32_t*)g_h16)[i] = 0;
    }
}

// ---------------- merged W_hh fragment swizzles (layouts identical to R12) ----------------
__global__ void wswz_all_kernel(const float* __restrict__ Wf,
                                const float* __restrict__ Wb,
                                const float* __restrict__ Wc) {
    const int bid = blockIdx.x;
    const int tid = threadIdx.x;
    if (bid < 16384) {
        // bilstm: idx(u32) = region*32768 + k16*512 + jn*64 + lane*2 + r
        size_t idx = (size_t)bid * 256 + tid;
        unsigned region = idx >> 15;
        unsigned w = idx & 32767;
        int dir = region >> 6, ublk = region & 63;
        int k16 = w >> 9;
        int jn = (w >> 6) & 7;
        int lane = (w >> 1) & 31;
        int r = w & 1;
        int col = jn * 8 + (lane >> 2);
        int gate = col >> 4, u = col & 15;
        int row = gate * N_ + ublk * 16 + u;
        int k = k16 * 16 + r * 8 + (lane & 3) * 2;
        const float* W = dir ? Wb : Wf;
        g_Wsw_bi[idx] = pack2h(W[(size_t)row * N_ + k], W[(size_t)row * N_ + k + 1]);
    } else {
        // cell: idx(u32) = blk*16384 + k16*256 + nwq*64 + lane*2 + r
        size_t idx = (size_t)(bid - 16384) * 256 + tid;
        unsigned blk = idx >> 14;
        unsigned w = idx & 16383;
        int k16 = w >> 8;
        int nwq = (w >> 6) & 3;
        int lane = (w >> 1) & 31;
        int r = w & 1;
        int col = nwq * 8 + (lane >> 2);
        int gate = col >> 3, u = col & 7;
        int row = gate * N_ + blk * 8 + u;
        int k = k16 * 16 + r * 8 + (lane & 3) * 2;
        g_Wsw_c[idx] = pack2h(Wc[(size_t)row * N_ + k], Wc[(size_t)row * N_ + k + 1]);
    }
}

// ---------------- fp16 GEMM: 128x128x32, cp.async double buffered, ldmatrix ----------------
// gridDim.z selects (W, bias, dst): z=0 -> W0/bias0/dst0, z=1 -> W1/bias1/dst0+1.
__global__ __launch_bounds__(256, 2) void gemm_f16_kernel(
    const __half* __restrict__ A,
    const __half* __restrict__ W0, const __half* __restrict__ W1,
    const float* __restrict__ bias0, const float* __restrict__ bias1,
    int K, int a_mode, int dst0)
{
    const int z = blockIdx.z;
    const __half* Wt = z ? W1 : W0;
    const float* bias = z ? bias1 : bias0;
    const int dst_sel = dst0 + z;
    float* C = (dst_sel == 0) ? g_Pf : (dst_sel == 1) ? g_Pb : g_Pc;

    __shared__ __align__(16) uint32_t As[2][128 * 20];
    __shared__ __align__(16) uint32_t Ws[2][128 * 20];

    const int tid = threadIdx.x;
    const int m0 = blockIdx.y * 128;
    const int g0 = blockIdx.x * 128;

    const __half* asrc[2];
    const __half* wsrc[2];
    int lrow[2], lseg[2];
#pragma unroll
    for (int i = 0; i < 2; i++) {
        int idx = tid + 256 * i;
        int row = idx >> 2;
        int seg = idx & 3;
        int m = m0 + row;
        int prow = (a_mode == 1) ? ((m & 63) * T_ + (m >> 6)) : m;
        asrc[i] = A + (size_t)prow * K + seg * 8;
        wsrc[i] = Wt + (size_t)(g0 + row) * K + seg * 8;
        lrow[i] = row; lseg[i] = seg;
    }
    uint32_t asm_a[2][2], wsm_a[2][2];
#pragma unroll
    for (int b = 0; b < 2; b++)
#pragma unroll
        for (int i = 0; i < 2; i++) {
            asm_a[b][i] = s2u(&As[b][lrow[i] * 20 + lseg[i] * 4]);
            wsm_a[b][i] = s2u(&Ws[b][lrow[i] * 20 + lseg[i] * 4]);
        }

    const int lane = tid & 31;
    const int wid = tid >> 5;
    const int gid = lane >> 2;
    const int tig = lane & 3;
    const int wm = (wid & 3) * 32;
    const int wn = (wid >> 2) * 64;

    const int rowA = lane & 15;
    const int koffA = (lane >> 4) * 4;
    const int cB = (lane & 7) + ((lane >> 4) << 3);
    const int kB = ((lane >> 3) & 1) * 4;

    uint32_t aaddr[2][2], baddr[2][4];
#pragma unroll
    for (int b = 0; b < 2; b++) {
#pragma unroll
        for (int mf = 0; mf < 2; mf++)
            aaddr[b][mf] = s2u(&As[b][(wm + mf * 16 + rowA) * 20 + koffA]);
#pragma unroll
        for (int np = 0; np < 4; np++)
            baddr[b][np] = s2u(&Ws[b][(wn + np * 16 + cB) * 20 + kB]);
    }

    float acc[2][8][4];
#pragma unroll
    for (int mf = 0; mf < 2; mf++)
#pragma unroll
        for (int nf = 0; nf < 8; nf++)
#pragma unroll
            for (int j = 0; j < 4; j++) acc[mf][nf][j] = 0.0f;

    const int NC = K / 32;
#pragma unroll
    for (int i = 0; i < 2; i++) {
        cp16(asm_a[0][i], asrc[i]);
        cp16(wsm_a[0][i], wsrc[i]);
    }
    cp_commit();

    for (int ch = 0; ch < NC; ch++) {
        const int buf = ch & 1;
        if (ch + 1 < NC) {
            const int nb = (ch + 1) & 1;
            const int k0 = (ch + 1) * 32;
#pragma unroll
            for (int i = 0; i < 2; i++) {
                cp16(asm_a[nb][i], asrc[i] + k0);
                cp16(wsm_a[nb][i], wsrc[i] + k0);
            }
            cp_commit();
            cp_wait<1>();
        } else {
            cp_wait<0>();
        }
        __syncthreads();

#pragma unroll
        for (int ks = 0; ks < 2; ks++) {
            const int kbb = ks * 32;
            uint32_t af[2][4];
#pragma unroll
            for (int mf = 0; mf < 2; mf++)
                ldsm_x4(af[mf][0], af[mf][1], af[mf][2], af[mf][3], aaddr[buf][mf] + kbb);
            uint32_t bf[8][2];
#pragma unroll
            for (int np = 0; np < 4; np++)
                ldsm_x4(bf[2 * np][0], bf[2 * np][1], bf[2 * np + 1][0], bf[2 * np + 1][1],
                        baddr[buf][np] + kbb);
#pragma unroll
            for (int mf = 0; mf < 2; mf++)
#pragma unroll
                for (int nf = 0; nf < 8; nf++)
                    mma_f16(acc[mf][nf], af[mf], bf[nf]);
        }
        __syncthreads();
    }

#pragma unroll
    for (int mf = 0; mf < 2; mf++) {
#pragma unroll
        for (int nf = 0; nf < 8; nf++) {
            int row = m0 + wm + mf * 16 + gid;
            int col = g0 + wn + nf * 8 + 2 * tig;
            float b0 = bias[col], b1 = bias[col + 1];
            float2 v0 = make_float2(acc[mf][nf][0] + b0, acc[mf][nf][1] + b1);
            float2 v1 = make_float2(acc[mf][nf][2] + b0, acc[mf][nf][3] + b1);
            *(float2*)&C[(size_t)row * G_ + col] = v0;
            *(float2*)&C[(size_t)(row + 8) * G_ + col] = v1;
        }
    }
}

// ---------------- persistent bilstm recurrence: 256 blocks x 256 thr (2/SM) ----------------
// bid: dir = bid>>7; bh = (bid>>6)&1 -> batches bh*32..+32; ublk = bid&63 -> 16 units (64 cols).
// Warp (8): mh = wid&1 (m16), jn = wid>>1 (0-3, 16 cols = 2 n8). Both h and W staged via
// cp.async double-buffered chunks (chunk = 128 k).
__global__ __launch_bounds__(256, 2) void bilstm_mma_kernel()
{
    extern __shared__ uint32_t smem_u[];
    uint32_t* hs[2] = { smem_u, smem_u + 32 * SPH };                  // [32][SPH] each
    uint32_t* ws[2] = { smem_u + 2 * 32 * SPH, smem_u + 2 * 32 * SPH + 4096 };
    float* gates = (float*)(smem_u + 2 * 32 * SPH + 2 * 4096);       // [32][68]

    const int bid = blockIdx.x;
    const int dir = bid >> 7;
    const int bh = (bid >> 6) & 1;
    const int ublk = bid & 63;
    const int b0 = bh * 32;
    const int u0 = ublk * 16;
    const float* Pbase = dir ? g_Pb : g_Pf;
    const uint32_t* wreg = g_Wsw_bi + ((size_t)(dir * 64 + ublk) << 15);

    const int tid = threadIdx.x;
    const int lane = tid & 31;
    const int wid = tid >> 5;
    const int gid = lane >> 2;
    const int tig = lane & 3;
    const int mh = wid & 1;
    const int jn = wid >> 1;

    // h staging: 512 cp16/chunk -> 2/thread: row tid>>3, segs (tid&7), (tid&7)+8
    const int srow = tid >> 3;
    const int sseg = tid & 7;
    uint32_t hs_a[2][2];
#pragma unroll
    for (int b = 0; b < 2; b++) {
        hs_a[b][0] = s2u(hs[b]) + (srow * SPH + sseg * 4) * 4;
        hs_a[b][1] = s2u(hs[b]) + (srow * SPH + (sseg + 8) * 4) * 4;
    }
    // W staging: 1024 cp16/chunk -> 4/thread, flat
    uint32_t ws_a[2];
    ws_a[0] = s2u(ws[0]) + tid * 16;
    ws_a[1] = s2u(ws[1]) + tid * 16;

    // ldmatrix h-fragment addresses (m16 tile at mh*16)
    const int rowA = lane & 15;
    const int koffA = (lane >> 4) * 4;
    uint32_t haddr[2];
#pragma unroll
    for (int b = 0; b < 2; b++)
        haddr[b] = s2u(&hs[b][(mh * 16 + rowA) * SPH + koffA]);

    // W smem read offsets (u32): per k16 l: l*512 + (2jn+nf)*64 + lane*2
    const uint32_t wofs0 = (2 * jn) * 64 + lane * 2;
    const uint32_t wofs1 = wofs0 + 64;

    // activation mapping: 32b x 16u = 512 pairs -> 2/thread
    int abl[2], au[2];
#pragma unroll
    for (int i = 0; i < 2; i++) {
        int p = tid + 256 * i;
        abl[i] = p >> 4;      // local batch 0..31
        au[i] = p & 15;
    }
    float c_reg[2] = {0.0f, 0.0f};

    // prefetch P for step 0
    float pre[2][4];
    {
        const float* P = Pbase + (size_t)(dir ? (T_ - 1) : 0) * B_ * G_;
#pragma unroll
        for (int i = 0; i < 2; i++) {
            const float* Pb = P + (size_t)(b0 + abl[i]) * G_ + u0 + au[i];
            pre[i][0] = Pb[0];
            pre[i][1] = Pb[N_];
            pre[i][2] = Pb[2 * N_];
            pre[i][3] = Pb[3 * N_];
        }
    }

    for (int s = 0; s < T_; s++) {
        const int t = dir ? (T_ - 1 - s) : s;
        const __half* h_prev = g_h16[2 * dir + (s & 1)];
        __half* h_next = g_h16[2 * dir + ((s + 1) & 1)];
        __half* hist = g_bi16 + (size_t)t * B_ * 2 * N_ + dir * N_;
        const __half* hp = h_prev + (size_t)(b0 + srow) * N_;

        // preload chunk 0
        cp16(hs_a[0][0], hp + sseg * 8);
        cp16(hs_a[0][1], hp + (sseg + 8) * 8);
#pragma unroll
        for (int i = 0; i < 4; i++)
            cp16(ws_a[0] + i * 4096, wreg + (size_t)(tid + 256 * i) * 4);
        cp_commit();

        float acc[2][4];
#pragma unroll
        for (int nf = 0; nf < 2; nf++)
#pragma unroll
            for (int j = 0; j < 4; j++) acc[nf][j] = 0.0f;

        for (int ch = 0; ch < 8; ch++) {
            const int buf = ch & 1;
            if (ch + 1 < 8) {
                const int ko = (ch + 1) * 128;
                cp16(hs_a[buf ^ 1][0], hp + ko + sseg * 8);
                cp16(hs_a[buf ^ 1][1], hp + ko + (sseg + 8) * 8);
                const uint32_t* wsrc = wreg + (size_t)(ch + 1) * 4096;
#pragma unroll
                for (int i = 0; i < 4; i++)
                    cp16(ws_a[buf ^ 1] + i * 4096, wsrc + (size_t)(tid + 256 * i) * 4);
                cp_commit();
                cp_wait<1>();
            } else {
                cp_wait<0>();
            }
            __syncthreads();

            const uint32_t* Wb = ws[buf];
#pragma unroll
            for (int l = 0; l < 8; l++) {
                uint32_t af[4];
                ldsm_x4(af[0], af[1], af[2], af[3], haddr[buf] + l * 32);
                uint2 w0 = *(const uint2*)(Wb + l * 512 + wofs0);
                uint2 w1 = *(const uint2*)(Wb + l * 512 + wofs1);
                uint32_t bf0[2] = { w0.x, w0.y };
                uint32_t bf1[2] = { w1.x, w1.y };
                mma_f16(acc[0], af, bf0);
                mma_f16(acc[1], af, bf1);
            }
            __syncthreads();
        }

        // write gates: rows mh*16+gid (+8); cols jn*16 + nf*8 + 2tig
#pragma unroll
        for (int nf = 0; nf < 2; nf++) {
            int row = mh * 16 + gid;
            int col = jn * 16 + nf * 8 + 2 * tig;
            gates[row * 68 + col]           = acc[nf][0];
            gates[row * 68 + col + 1]       = acc[nf][1];
            gates[(row + 8) * 68 + col]     = acc[nf][2];
            gates[(row + 8) * 68 + col + 1] = acc[nf][3];
        }
        __syncthreads();

        // activation + state update
#pragma unroll
        for (int i = 0; i < 2; i++) {
            int bl = abl[i];
            int u = au[i];
            int b = b0 + bl;
            int ug = u0 + u;
            float ig = gates[bl * 68 + u]      + pre[i][0];
            float fg = gates[bl * 68 + 16 + u] + pre[i][1];
            float gg = gates[bl * 68 + 32 + u] + pre[i][2];
            float og = gates[bl * 68 + 48 + u] + pre[i][3];
            ig = sig_f(ig);
            fg = sig_f(fg);
            gg = tanh_f(gg);
            og = sig_f(og);
            float cn = fg * c_reg[i] + ig * gg;
            c_reg[i] = cn;
            __half hn = __float2half_rn(og * tanh_f(cn));
            h_next[(size_t)b * N_ + ug] = hn;
            hist[(size_t)b * 2 * N_ + ug] = hn;
        }
        __syncthreads();   // gates reuse safety before next step's writes

        // prefetch next step's P
        if (s + 1 < T_) {
            const int tn = dir ? (T_ - 2 - s) : (s + 1);
            const float* P = Pbase + (size_t)tn * B_ * G_;
#pragma unroll
            for (int i = 0; i < 2; i++) {
                const float* Pb = P + (size_t)(b0 + abl[i]) * G_ + u0 + au[i];
                pre[i][0] = Pb[0];
                pre[i][1] = Pb[N_];
                pre[i][2] = Pb[2 * N_];
                pre[i][3] = Pb[3 * N_];
            }
        }
        grid_barrier(dir, 128);
    }
}

// ---------------- persistent cell recurrence: 256 blocks x 256 thr (2/SM) ----------------
// bid: bh = bid>>7 -> batches bh*32; ublk = bid&127 -> 8 units (32 cols).
// Warp (8): mh = wid&1 (m16), jn = wid>>1 (0-3, one n8 each).
__global__ __launch_bounds__(256, 2) void cell_mma_kernel(float* __restrict__ out)
{
    extern __shared__ uint32_t smem_u[];
    uint32_t* hs[2] = { smem_u, smem_u + 32 * SPH };
    uint32_t* ws[2] = { smem_u + 2 * 32 * SPH, smem_u + 2 * 32 * SPH + 2048 };
    float* gates = (float*)(smem_u + 2 * 32 * SPH + 2 * 2048);       // [32][36]

    const int bid = blockIdx.x;
    const int bh = bid >> 7;
    const int ublk = bid & 127;
    const int b0 = bh * 32;
    const int u0 = ublk * 8;
    const uint32_t* wreg = g_Wsw_c + ((size_t)ublk << 14);

    const int tid = threadIdx.x;
    const int lane = tid & 31;
    const int wid = tid >> 5;
    const int gid = lane >> 2;
    const int tig = lane & 3;
    const int mh = wid & 1;
    const int jn = wid >> 1;

    const int srow = tid >> 3;
    const int sseg = tid & 7;
    uint32_t hs_a[2][2];
#pragma unroll
    for (int b = 0; b < 2; b++) {
        hs_a[b][0] = s2u(hs[b]) + (srow * SPH + sseg * 4) * 4;
        hs_a[b][1] = s2u(hs[b]) + (srow * SPH + (sseg + 8) * 4) * 4;
    }
    uint32_t ws_a[2];
    ws_a[0] = s2u(ws[0]) + tid * 16;
    ws_a[1] = s2u(ws[1]) + tid * 16;

    const int rowA = lane & 15;
    const int koffA = (lane >> 4) * 4;
    uint32_t haddr[2];
#pragma unroll
    for (int b = 0; b < 2; b++)
        haddr[b] = s2u(&hs[b][(mh * 16 + rowA) * SPH + koffA]);

    const uint32_t wofs = jn * 64 + lane * 2;

    // activation: 32b x 8u = 256 pairs -> 1/thread
    const int abl = tid >> 3;
    const int au = tid & 7;
    float c_reg = 0.0f;

    float pre[4];
    {
        const float* Pb = g_Pc + (size_t)(b0 + abl) * G_ + u0 + au;
        pre[0] = Pb[0];
        pre[1] = Pb[N_];
        pre[2] = Pb[2 * N_];
        pre[3] = Pb[3 * N_];
    }

    for (int s = 0; s < T_; s++) {
        const __half* h_prev = g_h16[4 + (s & 1)];
        __half* h_next = g_h16[4 + ((s + 1) & 1)];
        const __half* hp = h_prev + (size_t)(b0 + srow) * N_;

        cp16(hs_a[0][0], hp + sseg * 8);
        cp16(hs_a[0][1], hp + (sseg + 8) * 8);
#pragma unroll
        for (int i = 0; i < 2; i++)
            cp16(ws_a[0] + i * 4096, wreg + (size_t)(tid + 256 * i) * 4);
        cp_commit();

        float acc[4] = {0.0f, 0.0f, 0.0f, 0.0f};

        for (int ch = 0; ch < 8; ch++) {
            const int buf = ch & 1;
            if (ch + 1 < 8) {
                const int ko = (ch + 1) * 128;
                cp16(hs_a[buf ^ 1][0], hp + ko + sseg * 8);
                cp16(hs_a[buf ^ 1][1], hp + ko + (sseg + 8) * 8);
                const uint32_t* wsrc = wreg + (size_t)(ch + 1) * 2048;
#pragma unroll
                for (int i = 0; i < 2; i++)
                    cp16(ws_a[buf ^ 1] + i * 4096, wsrc + (size_t)(tid + 256 * i) * 4);
                cp_commit();
                cp_wait<1>();
            } else {
                cp_wait<0>();
            }
            __syncthreads();

            const uint32_t* Wb = ws[buf];
#pragma unroll
            for (int l = 0; l < 8; l++) {
                uint32_t af[4];
                ldsm_x4(af[0], af[1], af[2], af[3], haddr[buf] + l * 32);
                uint2 w0 = *(const uint2*)(Wb + l * 256 + wofs);
                uint32_t bf[2] = { w0.x, w0.y };
                mma_f16(acc, af, bf);
            }
            __syncthreads();
        }

        {
            int row = mh * 16 + gid;
            int col = jn * 8 + 2 * tig;
            gates[row * 36 + col]           = acc[0];
            gates[row * 36 + col + 1]       = acc[1];
            gates[(row + 8) * 36 + col]     = acc[2];
            gates[(row + 8) * 36 + col + 1] = acc[3];
        }
        __syncthreads();

        {
            int b = b0 + abl;
            int ug = u0 + au;
            float ig = gates[abl * 36 + au]      + pre[0];
            float fg = gates[abl * 36 + 8 + au]  + pre[1];
            float gg = gates[abl * 36 + 16 + au] + pre[2];
            float og = gates[abl * 36 + 24 + au] + pre[3];
            ig = sig_f(ig);
            fg = sig_f(fg);
            gg = tanh_f(gg);
            og = sig_f(og);
            float cn = fg * c_reg + ig * gg;
            c_reg = cn;
            float hn = og * tanh_f(cn);
            out[((size_t)b * T_ + s) * N_ + ug] = hn;
            h_next[(size_t)b * N_ + ug] = __float2half_rn(hn);
            if (s == T_ - 1) {
                const size_t tail = (size_t)B_ * T_ * N_;
                size_t gi = (size_t)b * N_ + ug;
                out[tail + gi] = hn;
                out[tail + (size_t)B_ * N_ + gi] = cn;
            }
        }
        __syncthreads();

        if (s + 1 < T_) {
            const float* Pb = g_Pc + (size_t)(s + 1) * B_ * G_ + (size_t)(b0 + abl) * G_ + u0 + au;
            pre[0] = Pb[0];
            pre[1] = Pb[N_];
            pre[2] = Pb[2 * N_];
            pre[3] = Pb[3 * N_];
        }
        grid_barrier(0, 256);
    }
}

// ---------------- host launcher ----------------
extern "C" void kernel_launch(void* const* d_in, const int* in_sizes, int n_in,
                              void* d_out, int out_size) {
    (void)in_sizes; (void)n_in; (void)out_size;
    const float* x     = (const float*)d_in[0];
    const float* Wf_ih = (const float*)d_in[1];
    const float* Wf_hh = (const float*)d_in[2];
    const float* bf    = (const float*)d_in[3];
    const float* Wb_ih = (const float*)d_in[4];
    const float* Wb_hh = (const float*)d_in[5];
    const float* bb    = (const float*)d_in[6];
    const float* Wc_ih = (const float*)d_in[7];
    const float* Wc_hh = (const float*)d_in[8];
    const float* bc    = (const float*)d_in[9];
    float* out = (float*)d_out;

    __half *wih, *x16, *bi16;
    cudaGetSymbolAddress((void**)&wih, g_Wih16);
    cudaGetSymbolAddress((void**)&x16, g_x16);
    cudaGetSymbolAddress((void**)&bi16, g_bi16);
    const __half* wih_f = wih;
    const __half* wih_b = wih + (4u << 20);
    const __half* wih_c = wih + (8u << 20);

    const int bilstm_smem = (2 * 32 * SPH + 2 * 4096 + 32 * 68) * 4;  // 58880
    const int cell_smem   = (2 * 32 * SPH + 2 * 2048 + 32 * 36) * 4;  // 38400
    cudaFuncSetAttribute(bilstm_mma_kernel, cudaFuncAttributeMaxDynamicSharedMemorySize, bilstm_smem);
    cudaFuncSetAttribute(cell_mma_kernel, cudaFuncAttributeMaxDynamicSharedMemorySize, cell_smem);

    // 1) merged prep (xconv + wconv + zero)
    prep_all_kernel<<<49920, 256>>>(x, Wf_ih, Wb_ih, Wc_ih);
    // 2) merged W_hh swizzles
    wswz_all_kernel<<<24576, 256>>>(Wf_hh, Wb_hh, Wc_hh);
    // 3) fwd + bwd input projections in ONE launch (z = 0/1)
    dim3 ggrid(G_ / 128, (T_ * B_) / 128, 2);
    gemm_f16_kernel<<<ggrid, 256>>>(x16, wih_f, wih_b, bf, bb, N_, 1, 0);
    // 4) bilstm recurrence (256 blocks, 2/SM)
    bilstm_mma_kernel<<<256, 256, bilstm_smem>>>();
    // 5) cell input projection (K = 2N)
    dim3 cgrid(G_ / 128, (T_ * B_) / 128, 1);
    gemm_f16_kernel<<<cgrid, 256>>>(bi16, wih_c, wih_c, bc, bc, 2 * N_, 0, 2);
    // 6) cell recurrence (256 blocks, 2/SM) + output
    cell_mma_kernel<<<256, 256, cell_smem>>>(out);
}

// round 14
// speedup vs baseline: 1.3179x; 1.0887x over previous
#include <cuda_runtime.h>
#include <cuda_fp16.h>
#include <cstdint>
#include <math.h>

#define T_ 512
#define B_ 64
#define N_ 1024
#define G_ 4096   // 4*N
#define SPH 68    // smem pitch (u32) for a 128-fp16 h chunk row (64 u32 + 4 pad)

// ---------------- static device scratch ----------------
__device__ float g_Pf[(size_t)T_ * B_ * G_];
__device__ float g_Pb[(size_t)T_ * B_ * G_];
__device__ float g_Pc[(size_t)T_ * B_ * G_];
__device__ __half g_bi16[(size_t)T_ * B_ * 2 * N_];   // bilstm output, fp16
__device__ __half g_x16[(size_t)B_ * T_ * N_];        // inputs converted to fp16
__device__ __half g_Wih16[16 * 1024 * 1024];          // fp16 W_ih: f(4M) b(4M) c(8M)
__device__ __half g_h16[6][B_ * N_];                  // fp16 recurrent h
__device__ uint32_t g_Wsw_bi[2 * 64 * 32768];         // fp16 frag-swizzled W_hh fwd/bwd
__device__ uint32_t g_Wsw_c[128 * 16384];             // fp16 frag-swizzled W_hh cell

__device__ unsigned g_barc[2] = {0, 0};
__device__ unsigned g_barg[2] = {0, 0};

__device__ __forceinline__ void grid_barrier(int which, unsigned nb) {
    __syncthreads();
    if (threadIdx.x == 0) {
        __threadfence();
        volatile unsigned* gen = &g_barg[which];
        unsigned g = *gen;
        if (atomicAdd(&g_barc[which], 1) == nb - 1) {
            g_barc[which] = 0;
            __threadfence();
            atomicExch((unsigned*)gen, g + 1);
        } else {
            while (*gen == g) { }
            __threadfence();
        }
    }
    __syncthreads();
}

// ---------------- helpers ----------------
__device__ __forceinline__ void mma_f16(float* c, const uint32_t* a, const uint32_t* b) {
    asm volatile(
        "mma.sync.aligned.m16n8k16.row.col.f32.f16.f16.f32 "
        "{%0,%1,%2,%3}, {%4,%5,%6,%7}, {%8,%9}, {%0,%1,%2,%3};"
        : "+f"(c[0]), "+f"(c[1]), "+f"(c[2]), "+f"(c[3])
        : "r"(a[0]), "r"(a[1]), "r"(a[2]), "r"(a[3]), "r"(b[0]), "r"(b[1]));
}
__device__ __forceinline__ void ldsm_x4(uint32_t& r0, uint32_t& r1, uint32_t& r2, uint32_t& r3,
                                        uint32_t addr) {
    asm volatile("ldmatrix.sync.aligned.m8n8.x4.shared.b16 {%0,%1,%2,%3}, [%4];"
                 : "=r"(r0), "=r"(r1), "=r"(r2), "=r"(r3) : "r"(addr));
}
__device__ __forceinline__ void cp16(uint32_t dst, const void* src) {
    asm volatile("cp.async.cg.shared.global [%0], [%1], 16;" :: "r"(dst), "l"(src));
}
__device__ __forceinline__ void cp_commit() { asm volatile("cp.async.commit_group;"); }
template <int NN> __device__ __forceinline__ void cp_wait() {
    asm volatile("cp.async.wait_group %0;" :: "n"(NN));
}
__device__ __forceinline__ uint32_t pack2h(float a, float b) {
    __half2 h = __floats2half2_rn(a, b);
    return *(uint32_t*)&h;
}
__device__ __forceinline__ uint32_t s2u(const void* p) {
    return (uint32_t)__cvta_generic_to_shared(p);
}
__device__ __forceinline__ float sig_f(float x) {
    return __fdividef(1.0f, 1.0f + __expf(-x));
}
__device__ __forceinline__ float tanh_f(float x) {
    return 1.0f - 2.0f * __fdividef(1.0f, __expf(2.0f * x) + 1.0f);
}

// ---------------- merged one-time prep: xconv + wconv + zero ----------------
__global__ void prep_all_kernel(const float* __restrict__ x,
                                const float* __restrict__ Wf,
                                const float* __restrict__ Wb,
                                const float* __restrict__ Wc) {
    const int bid = blockIdx.x;
    const int tid = threadIdx.x;
    if (bid < 32768) {
        size_t i = (size_t)bid * 256 + tid;
        float4 v = ((const float4*)x)[i];
        uint2 o;
        o.x = pack2h(v.x, v.y);
        o.y = pack2h(v.z, v.w);
        ((uint2*)g_x16)[i] = o;
    } else if (bid < 49152) {
        size_t i = (size_t)(bid - 32768) * 256 + tid;
        const float* src;
        size_t off;
        if (i < (1u << 20))      { src = Wf; off = i; }
        else if (i < (2u << 20)) { src = Wb; off = i - (1u << 20); }
        else                     { src = Wc; off = i - (2u << 20); }
        float4 v = ((const float4*)src)[off];
        uint2 o;
        o.x = pack2h(v.x, v.y);
        o.y = pack2h(v.z, v.w);
        ((uint2*)g_Wih16)[i] = o;
    } else {
        size_t i = (size_t)(bid - 49152) * 256 + tid;
        ((uint32_t*)g_h16)[i] = 0;
    }
}

// ---------------- merged W_hh fragment swizzles ----------------
__global__ void wswz_all_kernel(const float* __restrict__ Wf,
                                const float* __restrict__ Wb,
                                const float* __restrict__ Wc) {
    const int bid = blockIdx.x;
    const int tid = threadIdx.x;
    if (bid < 16384) {
        // bilstm: idx(u32) = region*32768 + k16*512 + jn8*64 + lane*2 + r
        size_t idx = (size_t)bid * 256 + tid;
        unsigned region = idx >> 15;
        unsigned w = idx & 32767;
        int dir = region >> 6, ublk = region & 63;
        int k16 = w >> 9;
        int jn8 = (w >> 6) & 7;
        int lane = (w >> 1) & 31;
        int r = w & 1;
        int col = jn8 * 8 + (lane >> 2);
        int gate = col >> 4, u = col & 15;
        int row = gate * N_ + ublk * 16 + u;
        int k = k16 * 16 + r * 8 + (lane & 3) * 2;
        const float* W = dir ? Wb : Wf;
        g_Wsw_bi[idx] = pack2h(W[(size_t)row * N_ + k], W[(size_t)row * N_ + k + 1]);
    } else {
        // cell: idx(u32) = blk*16384 + k16*256 + nwq*64 + lane*2 + r
        size_t idx = (size_t)(bid - 16384) * 256 + tid;
        unsigned blk = idx >> 14;
        unsigned w = idx & 16383;
        int k16 = w >> 8;
        int nwq = (w >> 6) & 3;
        int lane = (w >> 1) & 31;
        int r = w & 1;
        int col = nwq * 8 + (lane >> 2);
        int gate = col >> 3, u = col & 7;
        int row = gate * N_ + blk * 8 + u;
        int k = k16 * 16 + r * 8 + (lane & 3) * 2;
        g_Wsw_c[idx] = pack2h(Wc[(size_t)row * N_ + k], Wc[(size_t)row * N_ + k + 1]);
    }
}

// ---------------- fp16 GEMM: 128x128x32, cp.async double buffered, ldmatrix ----------------
__global__ __launch_bounds__(256, 2) void gemm_f16_kernel(
    const __half* __restrict__ A,
    const __half* __restrict__ W0, const __half* __restrict__ W1,
    const float* __restrict__ bias0, const float* __restrict__ bias1,
    int K, int a_mode, int dst0)
{
    const int z = blockIdx.z;
    const __half* Wt = z ? W1 : W0;
    const float* bias = z ? bias1 : bias0;
    const int dst_sel = dst0 + z;
    float* C = (dst_sel == 0) ? g_Pf : (dst_sel == 1) ? g_Pb : g_Pc;

    __shared__ __align__(16) uint32_t As[2][128 * 20];
    __shared__ __align__(16) uint32_t Ws[2][128 * 20];

    const int tid = threadIdx.x;
    const int m0 = blockIdx.y * 128;
    const int g0 = blockIdx.x * 128;

    const __half* asrc[2];
    const __half* wsrc[2];
    int lrow[2], lseg[2];
#pragma unroll
    for (int i = 0; i < 2; i++) {
        int idx = tid + 256 * i;
        int row = idx >> 2;
        int seg = idx & 3;
        int m = m0 + row;
        int prow = (a_mode == 1) ? ((m & 63) * T_ + (m >> 6)) : m;
        asrc[i] = A + (size_t)prow * K + seg * 8;
        wsrc[i] = Wt + (size_t)(g0 + row) * K + seg * 8;
        lrow[i] = row; lseg[i] = seg;
    }
    uint32_t asm_a[2][2], wsm_a[2][2];
#pragma unroll
    for (int b = 0; b < 2; b++)
#pragma unroll
        for (int i = 0; i < 2; i++) {
            asm_a[b][i] = s2u(&As[b][lrow[i] * 20 + lseg[i] * 4]);
            wsm_a[b][i] = s2u(&Ws[b][lrow[i] * 20 + lseg[i] * 4]);
        }

    const int lane = tid & 31;
    const int wid = tid >> 5;
    const int gid = lane >> 2;
    const int tig = lane & 3;
    const int wm = (wid & 3) * 32;
    const int wn = (wid >> 2) * 64;

    const int rowA = lane & 15;
    const int koffA = (lane >> 4) * 4;
    const int cB = (lane & 7) + ((lane >> 4) << 3);
    const int kB = ((lane >> 3) & 1) * 4;

    uint32_t aaddr[2][2], baddr[2][4];
#pragma unroll
    for (int b = 0; b < 2; b++) {
#pragma unroll
        for (int mf = 0; mf < 2; mf++)
            aaddr[b][mf] = s2u(&As[b][(wm + mf * 16 + rowA) * 20 + koffA]);
#pragma unroll
        for (int np = 0; np < 4; np++)
            baddr[b][np] = s2u(&Ws[b][(wn + np * 16 + cB) * 20 + kB]);
    }

    float acc[2][8][4];
#pragma unroll
    for (int mf = 0; mf < 2; mf++)
#pragma unroll
        for (int nf = 0; nf < 8; nf++)
#pragma unroll
            for (int j = 0; j < 4; j++) acc[mf][nf][j] = 0.0f;

    const int NC = K / 32;
#pragma unroll
    for (int i = 0; i < 2; i++) {
        cp16(asm_a[0][i], asrc[i]);
        cp16(wsm_a[0][i], wsrc[i]);
    }
    cp_commit();

    for (int ch = 0; ch < NC; ch++) {
        const int buf = ch & 1;
        if (ch + 1 < NC) {
            const int nb = (ch + 1) & 1;
            const int k0 = (ch + 1) * 32;
#pragma unroll
            for (int i = 0; i < 2; i++) {
                cp16(asm_a[nb][i], asrc[i] + k0);
                cp16(wsm_a[nb][i], wsrc[i] + k0);
            }
            cp_commit();
            cp_wait<1>();
        } else {
            cp_wait<0>();
        }
        __syncthreads();

#pragma unroll
        for (int ks = 0; ks < 2; ks++) {
            const int kbb = ks * 32;
            uint32_t af[2][4];
#pragma unroll
            for (int mf = 0; mf < 2; mf++)
                ldsm_x4(af[mf][0], af[mf][1], af[mf][2], af[mf][3], aaddr[buf][mf] + kbb);
            uint32_t bf[8][2];
#pragma unroll
            for (int np = 0; np < 4; np++)
                ldsm_x4(bf[2 * np][0], bf[2 * np][1], bf[2 * np + 1][0], bf[2 * np + 1][1],
                        baddr[buf][np] + kbb);
#pragma unroll
            for (int mf = 0; mf < 2; mf++)
#pragma unroll
                for (int nf = 0; nf < 8; nf++)
                    mma_f16(acc[mf][nf], af[mf], bf[nf]);
        }
        __syncthreads();
    }

#pragma unroll
    for (int mf = 0; mf < 2; mf++) {
#pragma unroll
        for (int nf = 0; nf < 8; nf++) {
            int row = m0 + wm + mf * 16 + gid;
            int col = g0 + wn + nf * 8 + 2 * tig;
            float b0 = bias[col], b1 = bias[col + 1];
            float2 v0 = make_float2(acc[mf][nf][0] + b0, acc[mf][nf][1] + b1);
            float2 v1 = make_float2(acc[mf][nf][2] + b0, acc[mf][nf][3] + b1);
            *(float2*)&C[(size_t)row * G_ + col] = v0;
            *(float2*)&C[(size_t)(row + 8) * G_ + col] = v1;
        }
    }
}

// ---------------- persistent bilstm recurrence: 256 blocks x 256 thr, ring-3, k-split ----------------
// bid: dir = bid>>7; bh = (bid>>6)&1 -> batches bh*32; ublk = bid&63 -> 16 units (64 cols).
// Warp (8): kh = wid>>2 (k parity), mh = (wid>>1)&1 (m16), jn = wid&1 (32 cols = 4 n8 chains).
__global__ __launch_bounds__(256, 2) void bilstm_mma_kernel()
{
    extern __shared__ uint32_t smem_u[];
    uint32_t* hb[3] = { smem_u, smem_u + 32 * SPH, smem_u + 2 * 32 * SPH };
    uint32_t* wb[3] = { smem_u + 3 * 32 * SPH, smem_u + 3 * 32 * SPH + 4096,
                        smem_u + 3 * 32 * SPH + 8192 };
    float* gates0 = (float*)(smem_u + 3 * 32 * SPH + 12288);   // [32][68]
    float* gates1 = gates0 + 32 * 68;

    const int bid = blockIdx.x;
    const int dir = bid >> 7;
    const int bh = (bid >> 6) & 1;
    const int ublk = bid & 63;
    const int b0 = bh * 32;
    const int u0 = ublk * 16;
    const float* Pbase = dir ? g_Pb : g_Pf;
    const uint32_t* wreg = g_Wsw_bi + ((size_t)(dir * 64 + ublk) << 15);

    const int tid = threadIdx.x;
    const int lane = tid & 31;
    const int wid = tid >> 5;
    const int gid = lane >> 2;
    const int tig = lane & 3;
    const int kh = wid >> 2;
    const int mh = (wid >> 1) & 1;
    const int jn = wid & 1;

    // staging addresses
    const int srow = tid >> 3;
    const int sseg = tid & 7;
    uint32_t hs_a[3][2], ws_a[3];
#pragma unroll
    for (int b = 0; b < 3; b++) {
        hs_a[b][0] = s2u(hb[b]) + (srow * SPH + sseg * 4) * 4;
        hs_a[b][1] = s2u(hb[b]) + (srow * SPH + (sseg + 8) * 4) * 4;
        ws_a[b] = s2u(wb[b]) + tid * 16;
    }

    // ldmatrix h-fragment addresses
    const int rowA = lane & 15;
    const int koffA = (lane >> 4) * 4;
    uint32_t haddr[3];
#pragma unroll
    for (int b = 0; b < 3; b++)
        haddr[b] = s2u(&hb[b][(mh * 16 + rowA) * SPH + koffA]);

    // W smem read offsets: per k16 l: l*512 + (jn*4+c)*64 + lane*2
    uint32_t wofs[4];
#pragma unroll
    for (int c = 0; c < 4; c++) wofs[c] = (jn * 4 + c) * 64 + lane * 2;

    // activation mapping: 32b x 16u = 512 pairs -> 2/thread
    int abl[2], au[2];
#pragma unroll
    for (int i = 0; i < 2; i++) {
        int p = tid + 256 * i;
        abl[i] = p >> 4;
        au[i] = p & 15;
    }
    float c_reg[2] = {0.0f, 0.0f};

    float pre[2][4];
    {
        const float* P = Pbase + (size_t)(dir ? (T_ - 1) : 0) * B_ * G_;
#pragma unroll
        for (int i = 0; i < 2; i++) {
            const float* Pb = P + (size_t)(b0 + abl[i]) * G_ + u0 + au[i];
            pre[i][0] = Pb[0];
            pre[i][1] = Pb[N_];
            pre[i][2] = Pb[2 * N_];
            pre[i][3] = Pb[3 * N_];
        }
    }

    for (int s = 0; s < T_; s++) {
        const int t = dir ? (T_ - 1 - s) : s;
        const __half* h_prev = g_h16[2 * dir + (s & 1)];
        __half* h_next = g_h16[2 * dir + ((s + 1) & 1)];
        __half* hist = g_bi16 + (size_t)t * B_ * 2 * N_ + dir * N_;
        const __half* hp = h_prev + (size_t)(b0 + srow) * N_;

        // preload chunks 0, 1
#pragma unroll
        for (int pc = 0; pc < 2; pc++) {
            const int ko = pc * 128;
            cp16(hs_a[pc][0], hp + ko + sseg * 8);
            cp16(hs_a[pc][1], hp + ko + (sseg + 8) * 8);
            const uint32_t* wsrc = wreg + (size_t)pc * 4096;
#pragma unroll
            for (int i = 0; i < 4; i++)
                cp16(ws_a[pc] + i * 4096, wsrc + (size_t)(tid + 256 * i) * 4);
            cp_commit();
        }

        float acc[4][4];
#pragma unroll
        for (int c = 0; c < 4; c++)
#pragma unroll
            for (int j = 0; j < 4; j++) acc[c][j] = 0.0f;

        for (int ch = 0; ch < 8; ch++) {
            if (ch < 7) cp_wait<1>(); else cp_wait<0>();
            __syncthreads();
            // issue chunk ch+2 into buf (ch+2)%3 (safe: sync proved compute(ch-1) done)
            if (ch + 2 < 8) {
                const int nb = (ch + 2) % 3;
                const int ko = (ch + 2) * 128;
                cp16(hs_a[nb][0], hp + ko + sseg * 8);
                cp16(hs_a[nb][1], hp + ko + (sseg + 8) * 8);
                const uint32_t* wsrc = wreg + (size_t)(ch + 2) * 4096;
#pragma unroll
                for (int i = 0; i < 4; i++)
                    cp16(ws_a[nb] + i * 4096, wsrc + (size_t)(tid + 256 * i) * 4);
                cp_commit();
            }
            const int buf = ch % 3;
            const uint32_t* Wb = wb[buf];
#pragma unroll
            for (int li = 0; li < 4; li++) {
                const int l = 2 * li + kh;
                uint32_t af[4];
                ldsm_x4(af[0], af[1], af[2], af[3], haddr[buf] + l * 32);
#pragma unroll
                for (int c = 0; c < 4; c++) {
                    uint2 wv = *(const uint2*)(Wb + l * 512 + wofs[c]);
                    uint32_t bf[2] = { wv.x, wv.y };
                    mma_f16(acc[c], af, bf);
                }
            }
        }
        __syncthreads();   // all compute done before gates writes (also guards buf reuse next step)

        // write partial gates: rows mh*16+gid (+8); cols jn*32 + c*8 + 2tig
        float* G = kh ? gates1 : gates0;
#pragma unroll
        for (int c = 0; c < 4; c++) {
            int row = mh * 16 + gid;
            int col = jn * 32 + c * 8 + 2 * tig;
            G[row * 68 + col]           = acc[c][0];
            G[row * 68 + col + 1]       = acc[c][1];
            G[(row + 8) * 68 + col]     = acc[c][2];
            G[(row + 8) * 68 + col + 1] = acc[c][3];
        }
        __syncthreads();

        // activation + state update
#pragma unroll
        for (int i = 0; i < 2; i++) {
            int bl = abl[i];
            int u = au[i];
            int b = b0 + bl;
            int ug = u0 + u;
            float ig = gates0[bl * 68 + u]      + gates1[bl * 68 + u]      + pre[i][0];
            float fg = gates0[bl * 68 + 16 + u] + gates1[bl * 68 + 16 + u] + pre[i][1];
            float gg = gates0[bl * 68 + 32 + u] + gates1[bl * 68 + 32 + u] + pre[i][2];
            float og = gates0[bl * 68 + 48 + u] + gates1[bl * 68 + 48 + u] + pre[i][3];
            ig = sig_f(ig);
            fg = sig_f(fg);
            gg = tanh_f(gg);
            og = sig_f(og);
            float cn = fg * c_reg[i] + ig * gg;
            c_reg[i] = cn;
            __half hn = __float2half_rn(og * tanh_f(cn));
            h_next[(size_t)b * N_ + ug] = hn;
            hist[(size_t)b * 2 * N_ + ug] = hn;
        }

        // prefetch next step's P
        if (s + 1 < T_) {
            const int tn = dir ? (T_ - 2 - s) : (s + 1);
            const float* P = Pbase + (size_t)tn * B_ * G_;
#pragma unroll
            for (int i = 0; i < 2; i++) {
                const float* Pb = P + (size_t)(b0 + abl[i]) * G_ + u0 + au[i];
                pre[i][0] = Pb[0];
                pre[i][1] = Pb[N_];
                pre[i][2] = Pb[2 * N_];
                pre[i][3] = Pb[3 * N_];
            }
        }
        grid_barrier(dir, 128);
    }
}

// ---------------- persistent cell recurrence: 256 blocks x 256 thr, ring-3, k-split ----------------
// bid: bh = bid>>7 -> batches bh*32; ublk = bid&127 -> 8 units (32 cols).
// Warp (8): kh = wid>>2, mh = (wid>>1)&1, jn = wid&1 (16 cols = 2 n8 chains).
__global__ __launch_bounds__(256, 2) void cell_mma_kernel(float* __restrict__ out)
{
    extern __shared__ uint32_t smem_u[];
    uint32_t* hb[3] = { smem_u, smem_u + 32 * SPH, smem_u + 2 * 32 * SPH };
    uint32_t* wb[3] = { smem_u + 3 * 32 * SPH, smem_u + 3 * 32 * SPH + 2048,
                        smem_u + 3 * 32 * SPH + 4096 };
    float* gates0 = (float*)(smem_u + 3 * 32 * SPH + 6144);   // [32][36]
    float* gates1 = gates0 + 32 * 36;

    const int bid = blockIdx.x;
    const int bh = bid >> 7;
    const int ublk = bid & 127;
    const int b0 = bh * 32;
    const int u0 = ublk * 8;
    const uint32_t* wreg = g_Wsw_c + ((size_t)ublk << 14);

    const int tid = threadIdx.x;
    const int lane = tid & 31;
    const int wid = tid >> 5;
    const int gid = lane >> 2;
    const int tig = lane & 3;
    const int kh = wid >> 2;
    const int mh = (wid >> 1) & 1;
    const int jn = wid & 1;

    const int srow = tid >> 3;
    const int sseg = tid & 7;
    uint32_t hs_a[3][2], ws_a[3];
#pragma unroll
    for (int b = 0; b < 3; b++) {
        hs_a[b][0] = s2u(hb[b]) + (srow * SPH + sseg * 4) * 4;
        hs_a[b][1] = s2u(hb[b]) + (srow * SPH + (sseg + 8) * 4) * 4;
        ws_a[b] = s2u(wb[b]) + tid * 16;
    }

    const int rowA = lane & 15;
    const int koffA = (lane >> 4) * 4;
    uint32_t haddr[3];
#pragma unroll
    for (int b = 0; b < 3; b++)
        haddr[b] = s2u(&hb[b][(mh * 16 + rowA) * SPH + koffA]);

    uint32_t wofs[2];
#pragma unroll
    for (int c = 0; c < 2; c++) wofs[c] = (jn * 2 + c) * 64 + lane * 2;

    const int abl = tid >> 3;
    const int au = tid & 7;
    float c_reg = 0.0f;

    float pre[4];
    {
        const float* Pb = g_Pc + (size_t)(b0 + abl) * G_ + u0 + au;
        pre[0] = Pb[0];
        pre[1] = Pb[N_];
        pre[2] = Pb[2 * N_];
        pre[3] = Pb[3 * N_];
    }

    for (int s = 0; s < T_; s++) {
        const __half* h_prev = g_h16[4 + (s & 1)];
        __half* h_next = g_h16[4 + ((s + 1) & 1)];
        const __half* hp = h_prev + (size_t)(b0 + srow) * N_;

#pragma unroll
        for (int pc = 0; pc < 2; pc++) {
            const int ko = pc * 128;
            cp16(hs_a[pc][0], hp + ko + sseg * 8);
            cp16(hs_a[pc][1], hp + ko + (sseg + 8) * 8);
            const uint32_t* wsrc = wreg + (size_t)pc * 2048;
#pragma unroll
            for (int i = 0; i < 2; i++)
                cp16(ws_a[pc] + i * 4096, wsrc + (size_t)(tid + 256 * i) * 4);
            cp_commit();
        }

        float acc[2][4];
#pragma unroll
        for (int c = 0; c < 2; c++)
#pragma unroll
            for (int j = 0; j < 4; j++) acc[c][j] = 0.0f;

        for (int ch = 0; ch < 8; ch++) {
            if (ch < 7) cp_wait<1>(); else cp_wait<0>();
            __syncthreads();
            if (ch + 2 < 8) {
                const int nb = (ch + 2) % 3;
                const int ko = (ch + 2) * 128;
                cp16(hs_a[nb][0], hp + ko + sseg * 8);
                cp16(hs_a[nb][1], hp + ko + (sseg + 8) * 8);
                const uint32_t* wsrc = wreg + (size_t)(ch + 2) * 2048;
#pragma unroll
                for (int i = 0; i < 2; i++)
                    cp16(ws_a[nb] + i * 4096, wsrc + (size_t)(tid + 256 * i) * 4);
                cp_commit();
            }
            const int buf = ch % 3;
            const uint32_t* Wb = wb[buf];
#pragma unroll
            for (int li = 0; li < 4; li++) {
                const int l = 2 * li + kh;
                uint32_t af[4];
                ldsm_x4(af[0], af[1], af[2], af[3], haddr[buf] + l * 32);
#pragma unroll
                for (int c = 0; c < 2; c++) {
                    uint2 wv = *(const uint2*)(Wb + l * 256 + wofs[c]);
                    uint32_t bf[2] = { wv.x, wv.y };
                    mma_f16(acc[c], af, bf);
                }
            }
        }
        __syncthreads();

        float* G = kh ? gates1 : gates0;
#pragma unroll
        for (int c = 0; c < 2; c++) {
            int row = mh * 16 + gid;
            int col = jn * 16 + c * 8 + 2 * tig;
            G[row * 36 + col]           = acc[c][0];
            G[row * 36 + col + 1]       = acc[c][1];
            G[(row + 8) * 36 + col]     = acc[c][2];
            G[(row + 8) * 36 + col + 1] = acc[c][3];
        }
        __syncthreads();

        {
            int b = b0 + abl;
            int ug = u0 + au;
            float ig = gates0[abl * 36 + au]      + gates1[abl * 36 + au]      + pre[0];
            float fg = gates0[abl * 36 + 8 + au]  + gates1[abl * 36 + 8 + au]  + pre[1];
            float gg = gates0[abl * 36 + 16 + au] + gates1[abl * 36 + 16 + au] + pre[2];
            float og = gates0[abl * 36 + 24 + au] + gates1[abl * 36 + 24 + au] + pre[3];
            ig = sig_f(ig);
            fg = sig_f(fg);
            gg = tanh_f(gg);
            og = sig_f(og);
            float cn = fg * c_reg + ig * gg;
            c_reg = cn;
            float hn = og * tanh_f(cn);
            out[((size_t)b * T_ + s) * N_ + ug] = hn;
            h_next[(size_t)b * N_ + ug] = __float2half_rn(hn);
            if (s == T_ - 1) {
                const size_t tail = (size_t)B_ * T_ * N_;
                size_t gi = (size_t)b * N_ + ug;
                out[tail + gi] = hn;
                out[tail + (size_t)B_ * N_ + gi] = cn;
            }
        }

        if (s + 1 < T_) {
            const float* Pb = g_Pc + (size_t)(s + 1) * B_ * G_ + (size_t)(b0 + abl) * G_ + u0 + au;
            pre[0] = Pb[0];
            pre[1] = Pb[N_];
            pre[2] = Pb[2 * N_];
            pre[3] = Pb[3 * N_];
        }
        grid_barrier(0, 256);
    }
}

// ---------------- host launcher ----------------
extern "C" void kernel_launch(void* const* d_in, const int* in_sizes, int n_in,
                              void* d_out, int out_size) {
    (void)in_sizes; (void)n_in; (void)out_size;
    const float* x     = (const float*)d_in[0];
    const float* Wf_ih = (const float*)d_in[1];
    const float* Wf_hh = (const float*)d_in[2];
    const float* bf    = (const float*)d_in[3];
    const float* Wb_ih = (const float*)d_in[4];
    const float* Wb_hh = (const float*)d_in[5];
    const float* bb    = (const float*)d_in[6];
    const float* Wc_ih = (const float*)d_in[7];
    const float* Wc_hh = (const float*)d_in[8];
    const float* bc    = (const float*)d_in[9];
    float* out = (float*)d_out;

    __half *wih, *x16, *bi16;
    cudaGetSymbolAddress((void**)&wih, g_Wih16);
    cudaGetSymbolAddress((void**)&x16, g_x16);
    cudaGetSymbolAddress((void**)&bi16, g_bi16);
    const __half* wih_f = wih;
    const __half* wih_b = wih + (4u << 20);
    const __half* wih_c = wih + (8u << 20);

    const int bilstm_smem = (3 * 32 * SPH + 3 * 4096 + 2 * 32 * 68) * 4;  // 92672
    const int cell_smem   = (3 * 32 * SPH + 3 * 2048 + 2 * 32 * 36) * 4;  // 59904
    cudaFuncSetAttribute(bilstm_mma_kernel, cudaFuncAttributeMaxDynamicSharedMemorySize, bilstm_smem);
    cudaFuncSetAttribute(cell_mma_kernel, cudaFuncAttributeMaxDynamicSharedMemorySize, cell_smem);

    // 1) merged prep (xconv + wconv + zero)
    prep_all_kernel<<<49920, 256>>>(x, Wf_ih, Wb_ih, Wc_ih);
    // 2) merged W_hh swizzles
    wswz_all_kernel<<<24576, 256>>>(Wf_hh, Wb_hh, Wc_hh);
    // 3) fwd + bwd input projections in ONE launch
    dim3 ggrid(G_ / 128, (T_ * B_) / 128, 2);
    gemm_f16_kernel<<<ggrid, 256>>>(x16, wih_f, wih_b, bf, bb, N_, 1, 0);
    // 4) bilstm recurrence
    bilstm_mma_kernel<<<256, 256, bilstm_smem>>>();
    // 5) cell input projection (K = 2N)
    dim3 cgrid(G_ / 128, (T_ * B_) / 128, 1);
    gemm_f16_kernel<<<cgrid, 256>>>(bi16, wih_c, wih_c, bc, bc, 2 * N_, 0, 2);
    // 6) cell recurrence + output
    cell_mma_kernel<<<256, 256, cell_smem>>>(out);
}

// round 15
// speedup vs baseline: 1.3487x; 1.0233x over previous
#include <cuda_runtime.h>
#include <cuda_fp16.h>
#include <cstdint>
#include <math.h>

#define T_ 512
#define B_ 64
#define N_ 1024
#define G_ 4096   // 4*N
#define SPH 68    // smem pitch (u32) for a 128-fp16 h chunk row (64 u32 + 4 pad)
#define GPW 36    // gemm smem pitch (u32) for a 64-fp16 chunk row (32 u32 + 4 pad)

// ---------------- static device scratch ----------------
__device__ float g_Pf[(size_t)T_ * B_ * G_];
__device__ float g_Pb[(size_t)T_ * B_ * G_];
__device__ float g_Pc[(size_t)T_ * B_ * G_];
__device__ __half g_bi16[(size_t)T_ * B_ * 2 * N_];
__device__ __half g_x16[(size_t)B_ * T_ * N_];
__device__ __half g_Wih16[16 * 1024 * 1024];
__device__ __half g_h16[6][B_ * N_];
__device__ uint32_t g_Wsw_bi[2 * 64 * 32768];
__device__ uint32_t g_Wsw_c[128 * 16384];

__device__ unsigned g_barc[6] = {0, 0, 0, 0, 0, 0};
__device__ unsigned g_barg[6] = {0, 0, 0, 0, 0, 0};

__device__ __forceinline__ void grid_barrier(int which, unsigned nb) {
    __syncthreads();
    if (threadIdx.x == 0) {
        __threadfence();
        volatile unsigned* gen = &g_barg[which];
        unsigned g = *gen;
        if (atomicAdd(&g_barc[which], 1) == nb - 1) {
            g_barc[which] = 0;
            __threadfence();
            atomicExch((unsigned*)gen, g + 1);
        } else {
            while (*gen == g) { }
            __threadfence();
        }
    }
    __syncthreads();
}

// ---------------- helpers ----------------
__device__ __forceinline__ void mma_f16(float* c, const uint32_t* a, const uint32_t* b) {
    asm volatile(
        "mma.sync.aligned.m16n8k16.row.col.f32.f16.f16.f32 "
        "{%0,%1,%2,%3}, {%4,%5,%6,%7}, {%8,%9}, {%0,%1,%2,%3};"
        : "+f"(c[0]), "+f"(c[1]), "+f"(c[2]), "+f"(c[3])
        : "r"(a[0]), "r"(a[1]), "r"(a[2]), "r"(a[3]), "r"(b[0]), "r"(b[1]));
}
__device__ __forceinline__ void ldsm_x4(uint32_t& r0, uint32_t& r1, uint32_t& r2, uint32_t& r3,
                                        uint32_t addr) {
    asm volatile("ldmatrix.sync.aligned.m8n8.x4.shared.b16 {%0,%1,%2,%3}, [%4];"
                 : "=r"(r0), "=r"(r1), "=r"(r2), "=r"(r3) : "r"(addr));
}
__device__ __forceinline__ void cp16(uint32_t dst, const void* src) {
    asm volatile("cp.async.cg.shared.global [%0], [%1], 16;" :: "r"(dst), "l"(src));
}
__device__ __forceinline__ void cp_commit() { asm volatile("cp.async.commit_group;"); }
template <int NN> __device__ __forceinline__ void cp_wait() {
    asm volatile("cp.async.wait_group %0;" :: "n"(NN));
}
__device__ __forceinline__ uint32_t pack2h(float a, float b) {
    __half2 h = __floats2half2_rn(a, b);
    return *(uint32_t*)&h;
}
__device__ __forceinline__ uint32_t s2u(const void* p) {
    return (uint32_t)__cvta_generic_to_shared(p);
}
__device__ __forceinline__ float sig_f(float x) {
    return __fdividef(1.0f, 1.0f + __expf(-x));
}
__device__ __forceinline__ float tanh_f(float x) {
    return 1.0f - 2.0f * __fdividef(1.0f, __expf(2.0f * x) + 1.0f);
}

// ---------------- merged one-time prep ----------------
__global__ void prep_all_kernel(const float* __restrict__ x,
                                const float* __restrict__ Wf,
                                const float* __restrict__ Wb,
                                const float* __restrict__ Wc) {
    const int bid = blockIdx.x;
    const int tid = threadIdx.x;
    if (bid < 32768) {
        size_t i = (size_t)bid * 256 + tid;
        float4 v = ((const float4*)x)[i];
        uint2 o;
        o.x = pack2h(v.x, v.y);
        o.y = pack2h(v.z, v.w);
        ((uint2*)g_x16)[i] = o;
    } else if (bid < 49152) {
        size_t i = (size_t)(bid - 32768) * 256 + tid;
        const float* src;
        size_t off;
        if (i < (1u << 20))      { src = Wf; off = i; }
        else if (i < (2u << 20)) { src = Wb; off = i - (1u << 20); }
        else                     { src = Wc; off = i - (2u << 20); }
        float4 v = ((const float4*)src)[off];
        uint2 o;
        o.x = pack2h(v.x, v.y);
        o.y = pack2h(v.z, v.w);
        ((uint2*)g_Wih16)[i] = o;
    } else {
        size_t i = (size_t)(bid - 49152) * 256 + tid;
        ((uint32_t*)g_h16)[i] = 0;
    }
}

// ---------------- merged W_hh fragment swizzles ----------------
__global__ void wswz_all_kernel(const float* __restrict__ Wf,
                                const float* __restrict__ Wb,
                                const float* __restrict__ Wc) {
    const int bid = blockIdx.x;
    const int tid = threadIdx.x;
    if (bid < 16384) {
        size_t idx = (size_t)bid * 256 + tid;
        unsigned region = idx >> 15;
        unsigned w = idx & 32767;
        int dir = region >> 6, ublk = region & 63;
        int k16 = w >> 9;
        int jn8 = (w >> 6) & 7;
        int lane = (w >> 1) & 31;
        int r = w & 1;
        int col = jn8 * 8 + (lane >> 2);
        int gate = col >> 4, u = col & 15;
        int row = gate * N_ + ublk * 16 + u;
        int k = k16 * 16 + r * 8 + (lane & 3) * 2;
        const float* W = dir ? Wb : Wf;
        g_Wsw_bi[idx] = pack2h(W[(size_t)row * N_ + k], W[(size_t)row * N_ + k + 1]);
    } else {
        size_t idx = (size_t)(bid - 16384) * 256 + tid;
        unsigned blk = idx >> 14;
        unsigned w = idx & 16383;
        int k16 = w >> 8;
        int nwq = (w >> 6) & 3;
        int lane = (w >> 1) & 31;
        int r = w & 1;
        int col = nwq * 8 + (lane >> 2);
        int gate = col >> 3, u = col & 7;
        int row = gate * N_ + blk * 8 + u;
        int k = k16 * 16 + r * 8 + (lane & 3) * 2;
        g_Wsw_c[idx] = pack2h(Wc[(size_t)row * N_ + k], Wc[(size_t)row * N_ + k + 1]);
    }
}

// ---------------- fp16 GEMM v3: 128x128xK, chunk=64, ring-3, single sync/chunk ----------------
__global__ __launch_bounds__(256, 2) void gemm_f16_kernel(
    const __half* __restrict__ A,
    const __half* __restrict__ W0, const __half* __restrict__ W1,
    const float* __restrict__ bias0, const float* __restrict__ bias1,
    int K, int a_mode, int dst0)
{
    const int z = blockIdx.z;
    const __half* Wt = z ? W1 : W0;
    const float* bias = z ? bias1 : bias0;
    const int dst_sel = dst0 + z;
    float* C = (dst_sel == 0) ? g_Pf : (dst_sel == 1) ? g_Pb : g_Pc;

    extern __shared__ __align__(16) uint32_t gsm[];
    uint32_t* As[3] = { gsm, gsm + 128 * GPW, gsm + 2 * 128 * GPW };
    uint32_t* Ws[3] = { gsm + 3 * 128 * GPW, gsm + 4 * 128 * GPW, gsm + 5 * 128 * GPW };

    const int tid = threadIdx.x;
    const int m0 = blockIdx.y * 128;
    const int g0 = blockIdx.x * 128;

    // loaders: chunk = 128 rows x 64 fp16 = 1024 segs of 16B per matrix -> 4/thread
    // idx = tid + 256*i: row = idx>>3, seg = idx&7
    const int lrow = tid >> 3;
    const int lseg = tid & 7;
    const __half* asrc;
    {
        int m = m0 + lrow;
        int prow = (a_mode == 1) ? ((m & 63) * T_ + (m >> 6)) : m;
        asrc = A + (size_t)prow * K + lseg * 8;
    }
    const __half* wsrc = Wt + (size_t)(g0 + lrow) * K + lseg * 8;
    // each thread covers rows lrow + 32*i (i<4) with same seg
    const __half* asrc2[4];
    const __half* wsrc2[4];
    uint32_t asm_a[3][4], wsm_a[3][4];
#pragma unroll
    for (int i = 0; i < 4; i++) {
        int row = lrow + 32 * i;
        int m = m0 + row;
        int prow = (a_mode == 1) ? ((m & 63) * T_ + (m >> 6)) : m;
        asrc2[i] = A + (size_t)prow * K + lseg * 8;
        wsrc2[i] = Wt + (size_t)(g0 + row) * K + lseg * 8;
#pragma unroll
        for (int b = 0; b < 3; b++) {
            asm_a[b][i] = s2u(&As[b][row * GPW + lseg * 4]);
            wsm_a[b][i] = s2u(&Ws[b][row * GPW + lseg * 4]);
        }
    }
    (void)asrc; (void)wsrc;

    const int lane = tid & 31;
    const int wid = tid >> 5;
    const int gid = lane >> 2;
    const int tig = lane & 3;
    const int wm = (wid & 3) * 32;
    const int wn = (wid >> 2) * 64;

    const int rowA = lane & 15;
    const int koffA = (lane >> 4) * 4;
    const int cB = (lane & 7) + ((lane >> 4) << 3);
    const int kB = ((lane >> 3) & 1) * 4;

    uint32_t aaddr[3][2], baddr[3][4];
#pragma unroll
    for (int b = 0; b < 3; b++) {
#pragma unroll
        for (int mf = 0; mf < 2; mf++)
            aaddr[b][mf] = s2u(&As[b][(wm + mf * 16 + rowA) * GPW + koffA]);
#pragma unroll
        for (int np = 0; np < 4; np++)
            baddr[b][np] = s2u(&Ws[b][(wn + np * 16 + cB) * GPW + kB]);
    }

    float acc[2][8][4];
#pragma unroll
    for (int mf = 0; mf < 2; mf++)
#pragma unroll
        for (int nf = 0; nf < 8; nf++)
#pragma unroll
            for (int j = 0; j < 4; j++) acc[mf][nf][j] = 0.0f;

    const int NC = K / 64;
    // preload chunks 0, 1
#pragma unroll
    for (int pc = 0; pc < 2; pc++) {
        const int k0 = pc * 64;
#pragma unroll
        for (int i = 0; i < 4; i++) {
            cp16(asm_a[pc][i], asrc2[i] + k0);
            cp16(wsm_a[pc][i], wsrc2[i] + k0);
        }
        cp_commit();
    }

    for (int ch = 0; ch < NC; ch++) {
        if (ch + 1 < NC) cp_wait<1>(); else cp_wait<0>();
        __syncthreads();
        if (ch + 2 < NC) {
            const int nb = (ch + 2) % 3;
            const int k0 = (ch + 2) * 64;
#pragma unroll
            for (int i = 0; i < 4; i++) {
                cp16(asm_a[nb][i], asrc2[i] + k0);
                cp16(wsm_a[nb][i], wsrc2[i] + k0);
            }
            cp_commit();
        }
        const int buf = ch % 3;
#pragma unroll
        for (int ks = 0; ks < 4; ks++) {
            const int kbb = ks * 32;   // bytes: 16 fp16 = 8 u32 = 32 B
            uint32_t af[2][4];
#pragma unroll
            for (int mf = 0; mf < 2; mf++)
                ldsm_x4(af[mf][0], af[mf][1], af[mf][2], af[mf][3], aaddr[buf][mf] + kbb);
            uint32_t bf[8][2];
#pragma unroll
            for (int np = 0; np < 4; np++)
                ldsm_x4(bf[2 * np][0], bf[2 * np][1], bf[2 * np + 1][0], bf[2 * np + 1][1],
                        baddr[buf][np] + kbb);
#pragma unroll
            for (int mf = 0; mf < 2; mf++)
#pragma unroll
                for (int nf = 0; nf < 8; nf++)
                    mma_f16(acc[mf][nf], af[mf], bf[nf]);
        }
    }
    __syncthreads();

#pragma unroll
    for (int mf = 0; mf < 2; mf++) {
#pragma unroll
        for (int nf = 0; nf < 8; nf++) {
            int row = m0 + wm + mf * 16 + gid;
            int col = g0 + wn + nf * 8 + 2 * tig;
            float b0 = bias[col], b1 = bias[col + 1];
            float2 v0 = make_float2(acc[mf][nf][0] + b0, acc[mf][nf][1] + b1);
            float2 v1 = make_float2(acc[mf][nf][2] + b0, acc[mf][nf][3] + b1);
            *(float2*)&C[(size_t)row * G_ + col] = v0;
            *(float2*)&C[(size_t)(row + 8) * G_ + col] = v1;
        }
    }
}

// ---------------- persistent bilstm recurrence: 256 blocks x 256 thr, ring-3, k-split ----------------
__global__ __launch_bounds__(256, 2) void bilstm_mma_kernel()
{
    extern __shared__ uint32_t smem_u[];
    uint32_t* hb[3] = { smem_u, smem_u + 32 * SPH, smem_u + 2 * 32 * SPH };
    uint32_t* wb[3] = { smem_u + 3 * 32 * SPH, smem_u + 3 * 32 * SPH + 4096,
                        smem_u + 3 * 32 * SPH + 8192 };
    float* gates0 = (float*)(smem_u + 3 * 32 * SPH + 12288);
    float* gates1 = gates0 + 32 * 68;

    const int bid = blockIdx.x;
    const int dir = bid >> 7;
    const int bh = (bid >> 6) & 1;
    const int ublk = bid & 63;
    const int b0 = bh * 32;
    const int u0 = ublk * 16;
    const int bslot = dir * 2 + bh;     // 4 independent groups of 64 blocks
    const float* Pbase = dir ? g_Pb : g_Pf;
    const uint32_t* wreg = g_Wsw_bi + ((size_t)(dir * 64 + ublk) << 15);

    const int tid = threadIdx.x;
    const int lane = tid & 31;
    const int wid = tid >> 5;
    const int gid = lane >> 2;
    const int tig = lane & 3;
    const int kh = wid >> 2;
    const int mh = (wid >> 1) & 1;
    const int jn = wid & 1;

    const int srow = tid >> 3;
    const int sseg = tid & 7;
    uint32_t hs_a[3][2], ws_a[3];
#pragma unroll
    for (int b = 0; b < 3; b++) {
        hs_a[b][0] = s2u(hb[b]) + (srow * SPH + sseg * 4) * 4;
        hs_a[b][1] = s2u(hb[b]) + (srow * SPH + (sseg + 8) * 4) * 4;
        ws_a[b] = s2u(wb[b]) + tid * 16;
    }

    const int rowA = lane & 15;
    const int koffA = (lane >> 4) * 4;
    uint32_t haddr[3];
#pragma unroll
    for (int b = 0; b < 3; b++)
        haddr[b] = s2u(&hb[b][(mh * 16 + rowA) * SPH + koffA]);

    uint32_t wofs[4];
#pragma unroll
    for (int c = 0; c < 4; c++) wofs[c] = (jn * 4 + c) * 64 + lane * 2;

    int abl[2], au[2];
#pragma unroll
    for (int i = 0; i < 2; i++) {
        int p = tid + 256 * i;
        abl[i] = p >> 4;
        au[i] = p & 15;
    }
    float c_reg[2] = {0.0f, 0.0f};

    float pre[2][4];
    {
        const float* P = Pbase + (size_t)(dir ? (T_ - 1) : 0) * B_ * G_;
#pragma unroll
        for (int i = 0; i < 2; i++) {
            const float* Pb = P + (size_t)(b0 + abl[i]) * G_ + u0 + au[i];
            pre[i][0] = Pb[0];
            pre[i][1] = Pb[N_];
            pre[i][2] = Pb[2 * N_];
            pre[i][3] = Pb[3 * N_];
        }
    }

    for (int s = 0; s < T_; s++) {
        const int t = dir ? (T_ - 1 - s) : s;
        const __half* h_prev = g_h16[2 * dir + (s & 1)];
        __half* h_next = g_h16[2 * dir + ((s + 1) & 1)];
        __half* hist = g_bi16 + (size_t)t * B_ * 2 * N_ + dir * N_;
        const __half* hp = h_prev + (size_t)(b0 + srow) * N_;

#pragma unroll
        for (int pc = 0; pc < 2; pc++) {
            const int ko = pc * 128;
            cp16(hs_a[pc][0], hp + ko + sseg * 8);
            cp16(hs_a[pc][1], hp + ko + (sseg + 8) * 8);
            const uint32_t* wsrc = wreg + (size_t)pc * 4096;
#pragma unroll
            for (int i = 0; i < 4; i++)
                cp16(ws_a[pc] + i * 4096, wsrc + (size_t)(tid + 256 * i) * 4);
            cp_commit();
        }

        float acc[4][4];
#pragma unroll
        for (int c = 0; c < 4; c++)
#pragma unroll
            for (int j = 0; j < 4; j++) acc[c][j] = 0.0f;

        for (int ch = 0; ch < 8; ch++) {
            if (ch < 7) cp_wait<1>(); else cp_wait<0>();
            __syncthreads();
            if (ch + 2 < 8) {
                const int nb = (ch + 2) % 3;
                const int ko = (ch + 2) * 128;
                cp16(hs_a[nb][0], hp + ko + sseg * 8);
                cp16(hs_a[nb][1], hp + ko + (sseg + 8) * 8);
                const uint32_t* wsrc = wreg + (size_t)(ch + 2) * 4096;
#pragma unroll
                for (int i = 0; i < 4; i++)
                    cp16(ws_a[nb] + i * 4096, wsrc + (size_t)(tid + 256 * i) * 4);
                cp_commit();
            }
            const int buf = ch % 3;
            const uint32_t* Wb = wb[buf];
#pragma unroll
            for (int li = 0; li < 4; li++) {
                const int l = 2 * li + kh;
                uint32_t af[4];
                ldsm_x4(af[0], af[1], af[2], af[3], haddr[buf] + l * 32);
#pragma unroll
                for (int c = 0; c < 4; c++) {
                    uint2 wv = *(const uint2*)(Wb + l * 512 + wofs[c]);
                    uint32_t bf[2] = { wv.x, wv.y };
                    mma_f16(acc[c], af, bf);
                }
            }
        }
        __syncthreads();

        float* G = kh ? gates1 : gates0;
#pragma unroll
        for (int c = 0; c < 4; c++) {
            int row = mh * 16 + gid;
            int col = jn * 32 + c * 8 + 2 * tig;
            G[row * 68 + col]           = acc[c][0];
            G[row * 68 + col + 1]       = acc[c][1];
            G[(row + 8) * 68 + col]     = acc[c][2];
            G[(row + 8) * 68 + col + 1] = acc[c][3];
        }
        __syncthreads();

#pragma unroll
        for (int i = 0; i < 2; i++) {
            int bl = abl[i];
            int u = au[i];
            int b = b0 + bl;
            int ug = u0 + u;
            float ig = gates0[bl * 68 + u]      + gates1[bl * 68 + u]      + pre[i][0];
            float fg = gates0[bl * 68 + 16 + u] + gates1[bl * 68 + 16 + u] + pre[i][1];
            float gg = gates0[bl * 68 + 32 + u] + gates1[bl * 68 + 32 + u] + pre[i][2];
            float og = gates0[bl * 68 + 48 + u] + gates1[bl * 68 + 48 + u] + pre[i][3];
            ig = sig_f(ig);
            fg = sig_f(fg);
            gg = tanh_f(gg);
            og = sig_f(og);
            float cn = fg * c_reg[i] + ig * gg;
            c_reg[i] = cn;
            __half hn = __float2half_rn(og * tanh_f(cn));
            h_next[(size_t)b * N_ + ug] = hn;
            hist[(size_t)b * 2 * N_ + ug] = hn;
        }

        if (s + 1 < T_) {
            const int tn = dir ? (T_ - 2 - s) : (s + 1);
            const float* P = Pbase + (size_t)tn * B_ * G_;
#pragma unroll
            for (int i = 0; i < 2; i++) {
                const float* Pb = P + (size_t)(b0 + abl[i]) * G_ + u0 + au[i];
                pre[i][0] = Pb[0];
                pre[i][1] = Pb[N_];
                pre[i][2] = Pb[2 * N_];
                pre[i][3] = Pb[3 * N_];
            }
        }
        grid_barrier(bslot, 64);
    }
}

// ---------------- persistent cell recurrence: 256 blocks x 256 thr, ring-3, k-split ----------------
__global__ __launch_bounds__(256, 2) void cell_mma_kernel(float* __restrict__ out)
{
    extern __shared__ uint32_t smem_u[];
    uint32_t* hb[3] = { smem_u, smem_u + 32 * SPH, smem_u + 2 * 32 * SPH };
    uint32_t* wb[3] = { smem_u + 3 * 32 * SPH, smem_u + 3 * 32 * SPH + 2048,
                        smem_u + 3 * 32 * SPH + 4096 };
    float* gates0 = (float*)(smem_u + 3 * 32 * SPH + 6144);
    float* gates1 = gates0 + 32 * 36;

    const int bid = blockIdx.x;
    const int bh = bid >> 7;
    const int ublk = bid & 127;
    const int b0 = bh * 32;
    const int u0 = ublk * 8;
    const int bslot = 4 + bh;           // 2 independent groups of 128 blocks
    const uint32_t* wreg = g_Wsw_c + ((size_t)ublk << 14);

    const int tid = threadIdx.x;
    const int lane = tid & 31;
    const int wid = tid >> 5;
    const int gid = lane >> 2;
    const int tig = lane & 3;
    const int kh = wid >> 2;
    const int mh = (wid >> 1) & 1;
    const int jn = wid & 1;

    const int srow = tid >> 3;
    const int sseg = tid & 7;
    uint32_t hs_a[3][2], ws_a[3];
#pragma unroll
    for (int b = 0; b < 3; b++) {
        hs_a[b][0] = s2u(hb[b]) + (srow * SPH + sseg * 4) * 4;
        hs_a[b][1] = s2u(hb[b]) + (srow * SPH + (sseg + 8) * 4) * 4;
        ws_a[b] = s2u(wb[b]) + tid * 16;
    }

    const int rowA = lane & 15;
    const int koffA = (lane >> 4) * 4;
    uint32_t haddr[3];
#pragma unroll
    for (int b = 0; b < 3; b++)
        haddr[b] = s2u(&hb[b][(mh * 16 + rowA) * SPH + koffA]);

    uint32_t wofs[2];
#pragma unroll
    for (int c = 0; c < 2; c++) wofs[c] = (jn * 2 + c) * 64 + lane * 2;

    const int abl = tid >> 3;
    const int au = tid & 7;
    float c_reg = 0.0f;

    float pre[4];
    {
        const float* Pb = g_Pc + (size_t)(b0 + abl) * G_ + u0 + au;
        pre[0] = Pb[0];
        pre[1] = Pb[N_];
        pre[2] = Pb[2 * N_];
        pre[3] = Pb[3 * N_];
    }

    for (int s = 0; s < T_; s++) {
        const __half* h_prev = g_h16[4 + (s & 1)];
        __half* h_next = g_h16[4 + ((s + 1) & 1)];
        const __half* hp = h_prev + (size_t)(b0 + srow) * N_;

#pragma unroll
        for (int pc = 0; pc < 2; pc++) {
            const int ko = pc * 128;
            cp16(hs_a[pc][0], hp + ko + sseg * 8);
            cp16(hs_a[pc][1], hp + ko + (sseg + 8) * 8);
            const uint32_t* wsrc = wreg + (size_t)pc * 2048;
#pragma unroll
            for (int i = 0; i < 2; i++)
                cp16(ws_a[pc] + i * 4096, wsrc + (size_t)(tid + 256 * i) * 4);
            cp_commit();
        }

        float acc[2][4];
#pragma unroll
        for (int c = 0; c < 2; c++)
#pragma unroll
            for (int j = 0; j < 4; j++) acc[c][j] = 0.0f;

        for (int ch = 0; ch < 8; ch++) {
            if (ch < 7) cp_wait<1>(); else cp_wait<0>();
            __syncthreads();
            if (ch + 2 < 8) {
                const int nb = (ch + 2) % 3;
                const int ko = (ch + 2) * 128;
                cp16(hs_a[nb][0], hp + ko + sseg * 8);
                cp16(hs_a[nb][1], hp + ko + (sseg + 8) * 8);
                const uint32_t* wsrc = wreg + (size_t)(ch + 2) * 2048;
#pragma unroll
                for (int i = 0; i < 2; i++)
                    cp16(ws_a[nb] + i * 4096, wsrc + (size_t)(tid + 256 * i) * 4);
                cp_commit();
            }
            const int buf = ch % 3;
            const uint32_t* Wb = wb[buf];
#pragma unroll
            for (int li = 0; li < 4; li++) {
                const int l = 2 * li + kh;
                uint32_t af[4];
                ldsm_x4(af[0], af[1], af[2], af[3], haddr[buf] + l * 32);
#pragma unroll
                for (int c = 0; c < 2; c++) {
                    uint2 wv = *(const uint2*)(Wb + l * 256 + wofs[c]);
                    uint32_t bf[2] = { wv.x, wv.y };
                    mma_f16(acc[c], af, bf);
                }
            }
        }
        __syncthreads();

        float* G = kh ? gates1 : gates0;
#pragma unroll
        for (int c = 0; c < 2; c++) {
            int row = mh * 16 + gid;
            int col = jn * 16 + c * 8 + 2 * tig;
            G[row * 36 + col]           = acc[c][0];
            G[row * 36 + col + 1]       = acc[c][1];
            G[(row + 8) * 36 + col]     = acc[c][2];
            G[(row + 8) * 36 + col + 1] = acc[c][3];
        }
        __syncthreads();

        {
            int b = b0 + abl;
            int ug = u0 + au;
            float ig = gates0[abl * 36 + au]      + gates1[abl * 36 + au]      + pre[0];
            float fg = gates0[abl * 36 + 8 + au]  + gates1[abl * 36 + 8 + au]  + pre[1];
            float gg = gates0[abl * 36 + 16 + au] + gates1[abl * 36 + 16 + au] + pre[2];
            float og = gates0[abl * 36 + 24 + au] + gates1[abl * 36 + 24 + au] + pre[3];
            ig = sig_f(ig);
            fg = sig_f(fg);
            gg = tanh_f(gg);
            og = sig_f(og);
            float cn = fg * c_reg + ig * gg;
            c_reg = cn;
            float hn = og * tanh_f(cn);
            out[((size_t)b * T_ + s) * N_ + ug] = hn;
            h_next[(size_t)b * N_ + ug] = __float2half_rn(hn);
            if (s == T_ - 1) {
                const size_t tail = (size_t)B_ * T_ * N_;
                size_t gi = (size_t)b * N_ + ug;
                out[tail + gi] = hn;
                out[tail + (size_t)B_ * N_ + gi] = cn;
            }
        }

        if (s + 1 < T_) {
            const float* Pb = g_Pc + (size_t)(s + 1) * B_ * G_ + (size_t)(b0 + abl) * G_ + u0 + au;
            pre[0] = Pb[0];
            pre[1] = Pb[N_];
            pre[2] = Pb[2 * N_];
            pre[3] = Pb[3 * N_];
        }
        grid_barrier(bslot, 128);
    }
}

// ---------------- host launcher ----------------
extern "C" void kernel_launch(void* const* d_in, const int* in_sizes, int n_in,
                              void* d_out, int out_size) {
    (void)in_sizes; (void)n_in; (void)out_size;
    const float* x     = (const float*)d_in[0];
    const float* Wf_ih = (const float*)d_in[1];
    const float* Wf_hh = (const float*)d_in[2];
    const float* bf    = (const float*)d_in[3];
    const float* Wb_ih = (const float*)d_in[4];
    const float* Wb_hh = (const float*)d_in[5];
    const float* bb    = (const float*)d_in[6];
    const float* Wc_ih = (const float*)d_in[7];
    const float* Wc_hh = (const float*)d_in[8];
    const float* bc    = (const float*)d_in[9];
    float* out = (float*)d_out;

    __half *wih, *x16, *bi16;
    cudaGetSymbolAddress((void**)&wih, g_Wih16);
    cudaGetSymbolAddress((void**)&x16, g_x16);
    cudaGetSymbolAddress((void**)&bi16, g_bi16);
    const __half* wih_f = wih;
    const __half* wih_b = wih + (4u << 20);
    const __half* wih_c = wih + (8u << 20);

    const int gemm_smem   = 6 * 128 * GPW * 4;                            // 110592
    const int bilstm_smem = (3 * 32 * SPH + 3 * 4096 + 2 * 32 * 68) * 4;  // 92672
    const int cell_smem   = (3 * 32 * SPH + 3 * 2048 + 2 * 32 * 36) * 4;  // 59904
    cudaFuncSetAttribute(gemm_f16_kernel, cudaFuncAttributeMaxDynamicSharedMemorySize, gemm_smem);
    cudaFuncSetAttribute(bilstm_mma_kernel, cudaFuncAttributeMaxDynamicSharedMemorySize, bilstm_smem);
    cudaFuncSetAttribute(cell_mma_kernel, cudaFuncAttributeMaxDynamicSharedMemorySize, cell_smem);

    // 1) merged prep
    prep_all_kernel<<<49920, 256>>>(x, Wf_ih, Wb_ih, Wc_ih);
    // 2) merged W_hh swizzles
    wswz_all_kernel<<<24576, 256>>>(Wf_hh, Wb_hh, Wc_hh);
    // 3) fwd + bwd input projections (one launch)
    dim3 ggrid(G_ / 128, (T_ * B_) / 128, 2);
    gemm_f16_kernel<<<ggrid, 256, gemm_smem>>>(x16, wih_f, wih_b, bf, bb, N_, 1, 0);
    // 4) bilstm recurrence
    bilstm_mma_kernel<<<256, 256, bilstm_smem>>>();
    // 5) cell input projection (K = 2N)
    dim3 cgrid(G_ / 128, (T_ * B_) / 128, 1);
    gemm_f16_kernel<<<cgrid, 256, gemm_smem>>>(bi16, wih_c, wih_c, bc, bc, 2 * N_, 0, 2);
    // 6) cell recurrence + output
    cell_mma_kernel<<<256, 256, cell_smem>>>(out);
}

// round 16
// speedup vs baseline: 1.3491x; 1.0003x over previous
#include <cuda_runtime.h>
#include <cuda_fp16.h>
#include <cstdint>
#include <math.h>

#define T_ 512
#define B_ 64
#define N_ 1024
#define G_ 4096   // 4*N
#define SPH 68    // smem pitch (u32) for a 128-fp16 h chunk row (64 u32 + 4 pad)
#define GPW 36    // gemm smem pitch (u32) for a 64-fp16 chunk row (32 u32 + 4 pad)

// ---------------- static device scratch ----------------
__device__ float g_Pf[(size_t)T_ * B_ * G_];
__device__ float g_Pb[(size_t)T_ * B_ * G_];
__device__ float g_Pc[(size_t)T_ * B_ * G_];
__device__ __half g_bi16[(size_t)T_ * B_ * 2 * N_];
__device__ __half g_x16[(size_t)B_ * T_ * N_];
__device__ __half g_Wih16[16 * 1024 * 1024];
__device__ __half g_h16[6][B_ * N_];
__device__ uint32_t g_Wsw_bi[2 * 64 * 32768];
__device__ uint32_t g_Wsw_c[128 * 16384];

__device__ unsigned g_barc[6] = {0, 0, 0, 0, 0, 0};
__device__ unsigned g_barg[6] = {0, 0, 0, 0, 0, 0};

__device__ __forceinline__ void grid_barrier(int which, unsigned nb) {
    __syncthreads();
    if (threadIdx.x == 0) {
        __threadfence();
        volatile unsigned* gen = &g_barg[which];
        unsigned g = *gen;
        if (atomicAdd(&g_barc[which], 1) == nb - 1) {
            g_barc[which] = 0;
            __threadfence();
            atomicExch((unsigned*)gen, g + 1);
        } else {
            while (*gen == g) { }
            __threadfence();
        }
    }
    __syncthreads();
}

// ---------------- helpers ----------------
__device__ __forceinline__ void mma_f16(float* c, const uint32_t* a, const uint32_t* b) {
    asm volatile(
        "mma.sync.aligned.m16n8k16.row.col.f32.f16.f16.f32 "
        "{%0,%1,%2,%3}, {%4,%5,%6,%7}, {%8,%9}, {%0,%1,%2,%3};"
        : "+f"(c[0]), "+f"(c[1]), "+f"(c[2]), "+f"(c[3])
        : "r"(a[0]), "r"(a[1]), "r"(a[2]), "r"(a[3]), "r"(b[0]), "r"(b[1]));
}
__device__ __forceinline__ void ldsm_x4(uint32_t& r0, uint32_t& r1, uint32_t& r2, uint32_t& r3,
                                        uint32_t addr) {
    asm volatile("ldmatrix.sync.aligned.m8n8.x4.shared.b16 {%0,%1,%2,%3}, [%4];"
                 : "=r"(r0), "=r"(r1), "=r"(r2), "=r"(r3) : "r"(addr));
}
__device__ __forceinline__ void cp16(uint32_t dst, const void* src) {
    asm volatile("cp.async.cg.shared.global [%0], [%1], 16;" :: "r"(dst), "l"(src));
}
__device__ __forceinline__ void cp_commit() { asm volatile("cp.async.commit_group;"); }
template <int NN> __device__ __forceinline__ void cp_wait() {
    asm volatile("cp.async.wait_group %0;" :: "n"(NN));
}
__device__ __forceinline__ uint32_t pack2h(float a, float b) {
    __half2 h = __floats2half2_rn(a, b);
    return *(uint32_t*)&h;
}
__device__ __forceinline__ uint32_t s2u(const void* p) {
    return (uint32_t)__cvta_generic_to_shared(p);
}
__device__ __forceinline__ float sig_f(float x) {
    return __fdividef(1.0f, 1.0f + __expf(-x));
}
__device__ __forceinline__ float tanh_f(float x) {
    return 1.0f - 2.0f * __fdividef(1.0f, __expf(2.0f * x) + 1.0f);
}

// ---------------- merged one-time prep ----------------
__global__ void prep_all_kernel(const float* __restrict__ x,
                                const float* __restrict__ Wf,
                                const float* __restrict__ Wb,
                                const float* __restrict__ Wc) {
    const int bid = blockIdx.x;
    const int tid = threadIdx.x;
    if (bid < 32768) {
        size_t i = (size_t)bid * 256 + tid;
        float4 v = ((const float4*)x)[i];
        uint2 o;
        o.x = pack2h(v.x, v.y);
        o.y = pack2h(v.z, v.w);
        ((uint2*)g_x16)[i] = o;
    } else if (bid < 49152) {
        size_t i = (size_t)(bid - 32768) * 256 + tid;
        const float* src;
        size_t off;
        if (i < (1u << 20))      { src = Wf; off = i; }
        else if (i < (2u << 20)) { src = Wb; off = i - (1u << 20); }
        else                     { src = Wc; off = i - (2u << 20); }
        float4 v = ((const float4*)src)[off];
        uint2 o;
        o.x = pack2h(v.x, v.y);
        o.y = pack2h(v.z, v.w);
        ((uint2*)g_Wih16)[i] = o;
    } else {
        size_t i = (size_t)(bid - 49152) * 256 + tid;
        ((uint32_t*)g_h16)[i] = 0;
    }
}

// ---------------- merged W_hh fragment swizzles ----------------
__global__ void wswz_all_kernel(const float* __restrict__ Wf,
                                const float* __restrict__ Wb,
                                const float* __restrict__ Wc) {
    const int bid = blockIdx.x;
    const int tid = threadIdx.x;
    if (bid < 16384) {
        size_t idx = (size_t)bid * 256 + tid;
        unsigned region = idx >> 15;
        unsigned w = idx & 32767;
        int dir = region >> 6, ublk = region & 63;
        int k16 = w >> 9;
        int jn8 = (w >> 6) & 7;
        int lane = (w >> 1) & 31;
        int r = w & 1;
        int col = jn8 * 8 + (lane >> 2);
        int gate = col >> 4, u = col & 15;
        int row = gate * N_ + ublk * 16 + u;
        int k = k16 * 16 + r * 8 + (lane & 3) * 2;
        const float* W = dir ? Wb : Wf;
        g_Wsw_bi[idx] = pack2h(W[(size_t)row * N_ + k], W[(size_t)row * N_ + k + 1]);
    } else {
        size_t idx = (size_t)(bid - 16384) * 256 + tid;
        unsigned blk = idx >> 14;
        unsigned w = idx & 16383;
        int k16 = w >> 8;
        int nwq = (w >> 6) & 3;
        int lane = (w >> 1) & 31;
        int r = w & 1;
        int col = nwq * 8 + (lane >> 2);
        int gate = col >> 3, u = col & 7;
        int row = gate * N_ + blk * 8 + u;
        int k = k16 * 16 + r * 8 + (lane & 3) * 2;
        g_Wsw_c[idx] = pack2h(Wc[(size_t)row * N_ + k], Wc[(size_t)row * N_ + k + 1]);
    }
}

// ---------------- fp16 GEMM v3: 128x128xK, chunk=64, ring-3, single sync/chunk ----------------
__global__ __launch_bounds__(256, 2) void gemm_f16_kernel(
    const __half* __restrict__ A,
    const __half* __restrict__ W0, const __half* __restrict__ W1,
    const float* __restrict__ bias0, const float* __restrict__ bias1,
    int K, int a_mode, int dst0)
{
    const int z = blockIdx.z;
    const __half* Wt = z ? W1 : W0;
    const float* bias = z ? bias1 : bias0;
    const int dst_sel = dst0 + z;
    float* C = (dst_sel == 0) ? g_Pf : (dst_sel == 1) ? g_Pb : g_Pc;

    extern __shared__ __align__(16) uint32_t gsm[];
    uint32_t* As[3] = { gsm, gsm + 128 * GPW, gsm + 2 * 128 * GPW };
    uint32_t* Ws[3] = { gsm + 3 * 128 * GPW, gsm + 4 * 128 * GPW, gsm + 5 * 128 * GPW };

    const int tid = threadIdx.x;
    const int m0 = blockIdx.y * 128;
    const int g0 = blockIdx.x * 128;

    const int lrow = tid >> 3;
    const int lseg = tid & 7;
    const __half* asrc2[4];
    const __half* wsrc2[4];
    uint32_t asm_a[3][4], wsm_a[3][4];
#pragma unroll
    for (int i = 0; i < 4; i++) {
        int row = lrow + 32 * i;
        int m = m0 + row;
        int prow = (a_mode == 1) ? ((m & 63) * T_ + (m >> 6)) : m;
        asrc2[i] = A + (size_t)prow * K + lseg * 8;
        wsrc2[i] = Wt + (size_t)(g0 + row) * K + lseg * 8;
#pragma unroll
        for (int b = 0; b < 3; b++) {
            asm_a[b][i] = s2u(&As[b][row * GPW + lseg * 4]);
            wsm_a[b][i] = s2u(&Ws[b][row * GPW + lseg * 4]);
        }
    }

    const int lane = tid & 31;
    const int wid = tid >> 5;
    const int gid = lane >> 2;
    const int tig = lane & 3;
    const int wm = (wid & 3) * 32;
    const int wn = (wid >> 2) * 64;

    const int rowA = lane & 15;
    const int koffA = (lane >> 4) * 4;
    const int cB = (lane & 7) + ((lane >> 4) << 3);
    const int kB = ((lane >> 3) & 1) * 4;

    uint32_t aaddr[3][2], baddr[3][4];
#pragma unroll
    for (int b = 0; b < 3; b++) {
#pragma unroll
        for (int mf = 0; mf < 2; mf++)
            aaddr[b][mf] = s2u(&As[b][(wm + mf * 16 + rowA) * GPW + koffA]);
#pragma unroll
        for (int np = 0; np < 4; np++)
            baddr[b][np] = s2u(&Ws[b][(wn + np * 16 + cB) * GPW + kB]);
    }

    float acc[2][8][4];
#pragma unroll
    for (int mf = 0; mf < 2; mf++)
#pragma unroll
        for (int nf = 0; nf < 8; nf++)
#pragma unroll
            for (int j = 0; j < 4; j++) acc[mf][nf][j] = 0.0f;

    const int NC = K / 64;
#pragma unroll
    for (int pc = 0; pc < 2; pc++) {
        const int k0 = pc * 64;
#pragma unroll
        for (int i = 0; i < 4; i++) {
            cp16(asm_a[pc][i], asrc2[i] + k0);
            cp16(wsm_a[pc][i], wsrc2[i] + k0);
        }
        cp_commit();
    }

    for (int ch = 0; ch < NC; ch++) {
        if (ch + 1 < NC) cp_wait<1>(); else cp_wait<0>();
        __syncthreads();
        if (ch + 2 < NC) {
            const int nb = (ch + 2) % 3;
            const int k0 = (ch + 2) * 64;
#pragma unroll
            for (int i = 0; i < 4; i++) {
                cp16(asm_a[nb][i], asrc2[i] + k0);
                cp16(wsm_a[nb][i], wsrc2[i] + k0);
            }
            cp_commit();
        }
        const int buf = ch % 3;
#pragma unroll
        for (int ks = 0; ks < 4; ks++) {
            const int kbb = ks * 32;
            uint32_t af[2][4];
#pragma unroll
            for (int mf = 0; mf < 2; mf++)
                ldsm_x4(af[mf][0], af[mf][1], af[mf][2], af[mf][3], aaddr[buf][mf] + kbb);
            uint32_t bf[8][2];
#pragma unroll
            for (int np = 0; np < 4; np++)
                ldsm_x4(bf[2 * np][0], bf[2 * np][1], bf[2 * np + 1][0], bf[2 * np + 1][1],
                        baddr[buf][np] + kbb);
#pragma unroll
            for (int mf = 0; mf < 2; mf++)
#pragma unroll
                for (int nf = 0; nf < 8; nf++)
                    mma_f16(acc[mf][nf], af[mf], bf[nf]);
        }
    }
    __syncthreads();

#pragma unroll
    for (int mf = 0; mf < 2; mf++) {
#pragma unroll
        for (int nf = 0; nf < 8; nf++) {
            int row = m0 + wm + mf * 16 + gid;
            int col = g0 + wn + nf * 8 + 2 * tig;
            float b0 = bias[col], b1 = bias[col + 1];
            float2 v0 = make_float2(acc[mf][nf][0] + b0, acc[mf][nf][1] + b1);
            float2 v1 = make_float2(acc[mf][nf][2] + b0, acc[mf][nf][3] + b1);
            *(float2*)&C[(size_t)row * G_ + col] = v0;
            *(float2*)&C[(size_t)(row + 8) * G_ + col] = v1;
        }
    }
}

// ---------------- persistent bilstm recurrence: 256 blocks x 256 thr, ring-3, k-split 4 ----------------
// Warp (8): kh = wid>>1 (k16 mod 4), mh = wid&1 (m16). Each warp covers ALL 64 cols (8 n8 chains).
__global__ __launch_bounds__(256, 2) void bilstm_mma_kernel()
{
    extern __shared__ uint32_t smem_u[];
    uint32_t* hb[3] = { smem_u, smem_u + 32 * SPH, smem_u + 2 * 32 * SPH };
    uint32_t* wb[3] = { smem_u + 3 * 32 * SPH, smem_u + 3 * 32 * SPH + 4096,
                        smem_u + 3 * 32 * SPH + 8192 };
    float* gates = (float*)(smem_u + 3 * 32 * SPH + 12288);   // 4 arrays of [32][68]

    const int bid = blockIdx.x;
    const int dir = bid >> 7;
    const int bh = (bid >> 6) & 1;
    const int ublk = bid & 63;
    const int b0 = bh * 32;
    const int u0 = ublk * 16;
    const int bslot = dir * 2 + bh;
    const float* Pbase = dir ? g_Pb : g_Pf;
    const uint32_t* wreg = g_Wsw_bi + ((size_t)(dir * 64 + ublk) << 15);

    const int tid = threadIdx.x;
    const int lane = tid & 31;
    const int wid = tid >> 5;
    const int gid = lane >> 2;
    const int tig = lane & 3;
    const int kh = wid >> 1;
    const int mh = wid & 1;

    const int srow = tid >> 3;
    const int sseg = tid & 7;
    uint32_t hs_a[3][2], ws_a[3];
#pragma unroll
    for (int b = 0; b < 3; b++) {
        hs_a[b][0] = s2u(hb[b]) + (srow * SPH + sseg * 4) * 4;
        hs_a[b][1] = s2u(hb[b]) + (srow * SPH + (sseg + 8) * 4) * 4;
        ws_a[b] = s2u(wb[b]) + tid * 16;
    }

    const int rowA = lane & 15;
    const int koffA = (lane >> 4) * 4;
    uint32_t haddr[3];
#pragma unroll
    for (int b = 0; b < 3; b++)
        haddr[b] = s2u(&hb[b][(mh * 16 + rowA) * SPH + koffA]);

    const uint32_t wbase = lane * 2;   // + c*64 per chain

    int abl[2], au[2];
#pragma unroll
    for (int i = 0; i < 2; i++) {
        int p = tid + 256 * i;
        abl[i] = p >> 4;
        au[i] = p & 15;
    }
    float c_reg[2] = {0.0f, 0.0f};

    float pre[2][4];
    {
        const float* P = Pbase + (size_t)(dir ? (T_ - 1) : 0) * B_ * G_;
#pragma unroll
        for (int i = 0; i < 2; i++) {
            const float* Pb = P + (size_t)(b0 + abl[i]) * G_ + u0 + au[i];
            pre[i][0] = Pb[0];
            pre[i][1] = Pb[N_];
            pre[i][2] = Pb[2 * N_];
            pre[i][3] = Pb[3 * N_];
        }
    }

    for (int s = 0; s < T_; s++) {
        const int t = dir ? (T_ - 1 - s) : s;
        const __half* h_prev = g_h16[2 * dir + (s & 1)];
        __half* h_next = g_h16[2 * dir + ((s + 1) & 1)];
        __half* hist = g_bi16 + (size_t)t * B_ * 2 * N_ + dir * N_;
        const __half* hp = h_prev + (size_t)(b0 + srow) * N_;

#pragma unroll
        for (int pc = 0; pc < 2; pc++) {
            const int ko = pc * 128;
            cp16(hs_a[pc][0], hp + ko + sseg * 8);
            cp16(hs_a[pc][1], hp + ko + (sseg + 8) * 8);
            const uint32_t* wsrc = wreg + (size_t)pc * 4096;
#pragma unroll
            for (int i = 0; i < 4; i++)
                cp16(ws_a[pc] + i * 4096, wsrc + (size_t)(tid + 256 * i) * 4);
            cp_commit();
        }

        float acc[8][4];
#pragma unroll
        for (int c = 0; c < 8; c++)
#pragma unroll
            for (int j = 0; j < 4; j++) acc[c][j] = 0.0f;

        for (int ch = 0; ch < 8; ch++) {
            if (ch < 7) cp_wait<1>(); else cp_wait<0>();
            __syncthreads();
            if (ch + 2 < 8) {
                const int nb = (ch + 2) % 3;
                const int ko = (ch + 2) * 128;
                cp16(hs_a[nb][0], hp + ko + sseg * 8);
                cp16(hs_a[nb][1], hp + ko + (sseg + 8) * 8);
                const uint32_t* wsrc = wreg + (size_t)(ch + 2) * 4096;
#pragma unroll
                for (int i = 0; i < 4; i++)
                    cp16(ws_a[nb] + i * 4096, wsrc + (size_t)(tid + 256 * i) * 4);
                cp_commit();
            }
            const int buf = ch % 3;
            const uint32_t* Wb = wb[buf];
#pragma unroll
            for (int li = 0; li < 2; li++) {
                const int l = kh + 4 * li;
                uint32_t af[4];
                ldsm_x4(af[0], af[1], af[2], af[3], haddr[buf] + l * 32);
#pragma unroll
                for (int c = 0; c < 8; c++) {
                    uint2 wv = *(const uint2*)(Wb + l * 512 + c * 64 + wbase);
                    uint32_t bf[2] = { wv.x, wv.y };
                    mma_f16(acc[c], af, bf);
                }
            }
        }
        __syncthreads();

        float* G = gates + kh * (32 * 68);
#pragma unroll
        for (int c = 0; c < 8; c++) {
            int row = mh * 16 + gid;
            int col = c * 8 + 2 * tig;
            G[row * 68 + col]           = acc[c][0];
            G[row * 68 + col + 1]       = acc[c][1];
            G[(row + 8) * 68 + col]     = acc[c][2];
            G[(row + 8) * 68 + col + 1] = acc[c][3];
        }
        __syncthreads();

#pragma unroll
        for (int i = 0; i < 2; i++) {
            int bl = abl[i];
            int u = au[i];
            int b = b0 + bl;
            int ug = u0 + u;
            float ig = 0.0f, fg = 0.0f, gg = 0.0f, og = 0.0f;
#pragma unroll
            for (int q = 0; q < 4; q++) {
                const float* Gq = gates + q * (32 * 68) + bl * 68;
                ig += Gq[u];
                fg += Gq[16 + u];
                gg += Gq[32 + u];
                og += Gq[48 + u];
            }
            ig = sig_f(ig + pre[i][0]);
            fg = sig_f(fg + pre[i][1]);
            gg = tanh_f(gg + pre[i][2]);
            og = sig_f(og + pre[i][3]);
            float cn = fg * c_reg[i] + ig * gg;
            c_reg[i] = cn;
            __half hn = __float2half_rn(og * tanh_f(cn));
            h_next[(size_t)b * N_ + ug] = hn;
            hist[(size_t)b * 2 * N_ + ug] = hn;
        }

        if (s + 1 < T_) {
            const int tn = dir ? (T_ - 2 - s) : (s + 1);
            const float* P = Pbase + (size_t)tn * B_ * G_;
#pragma unroll
            for (int i = 0; i < 2; i++) {
                const float* Pb = P + (size_t)(b0 + abl[i]) * G_ + u0 + au[i];
                pre[i][0] = Pb[0];
                pre[i][1] = Pb[N_];
                pre[i][2] = Pb[2 * N_];
                pre[i][3] = Pb[3 * N_];
            }
        }
        grid_barrier(bslot, 64);
    }
}

// ---------------- persistent cell recurrence: 256 blocks x 256 thr, ring-3, k-split 4 ----------------
// Warp (8): kh = wid>>1, mh = wid&1. Each warp covers all 32 cols (4 n8 chains).
__global__ __launch_bounds__(256, 2) void cell_mma_kernel(float* __restrict__ out)
{
    extern __shared__ uint32_t smem_u[];
    uint32_t* hb[3] = { smem_u, smem_u + 32 * SPH, smem_u + 2 * 32 * SPH };
    uint32_t* wb[3] = { smem_u + 3 * 32 * SPH, smem_u + 3 * 32 * SPH + 2048,
                        smem_u + 3 * 32 * SPH + 4096 };
    float* gates = (float*)(smem_u + 3 * 32 * SPH + 6144);    // 4 arrays of [32][36]

    const int bid = blockIdx.x;
    const int bh = bid >> 7;
    const int ublk = bid & 127;
    const int b0 = bh * 32;
    const int u0 = ublk * 8;
    const int bslot = 4 + bh;
    const uint32_t* wreg = g_Wsw_c + ((size_t)ublk << 14);

    const int tid = threadIdx.x;
    const int lane = tid & 31;
    const int wid = tid >> 5;
    const int gid = lane >> 2;
    const int tig = lane & 3;
    const int kh = wid >> 1;
    const int mh = wid & 1;

    const int srow = tid >> 3;
    const int sseg = tid & 7;
    uint32_t hs_a[3][2], ws_a[3];
#pragma unroll
    for (int b = 0; b < 3; b++) {
        hs_a[b][0] = s2u(hb[b]) + (srow * SPH + sseg * 4) * 4;
        hs_a[b][1] = s2u(hb[b]) + (srow * SPH + (sseg + 8) * 4) * 4;
        ws_a[b] = s2u(wb[b]) + tid * 16;
    }

    const int rowA = lane & 15;
    const int koffA = (lane >> 4) * 4;
    uint32_t haddr[3];
#pragma unroll
    for (int b = 0; b < 3; b++)
        haddr[b] = s2u(&hb[b][(mh * 16 + rowA) * SPH + koffA]);

    const uint32_t wbase = lane * 2;

    const int abl = tid >> 3;
    const int au = tid & 7;
    float c_reg = 0.0f;

    float pre[4];
    {
        const float* Pb = g_Pc + (size_t)(b0 + abl) * G_ + u0 + au;
        pre[0] = Pb[0];
        pre[1] = Pb[N_];
        pre[2] = Pb[2 * N_];
        pre[3] = Pb[3 * N_];
    }

    for (int s = 0; s < T_; s++) {
        const __half* h_prev = g_h16[4 + (s & 1)];
        __half* h_next = g_h16[4 + ((s + 1) & 1)];
        const __half* hp = h_prev + (size_t)(b0 + srow) * N_;

#pragma unroll
        for (int pc = 0; pc < 2; pc++) {
            const int ko = pc * 128;
            cp16(hs_a[pc][0], hp + ko + sseg * 8);
            cp16(hs_a[pc][1], hp + ko + (sseg + 8) * 8);
            const uint32_t* wsrc = wreg + (size_t)pc * 2048;
#pragma unroll
            for (int i = 0; i < 2; i++)
                cp16(ws_a[pc] + i * 4096, wsrc + (size_t)(tid + 256 * i) * 4);
            cp_commit();
        }

        float acc[4][4];
#pragma unroll
        for (int c = 0; c < 4; c++)
#pragma unroll
            for (int j = 0; j < 4; j++) acc[c][j] = 0.0f;

        for (int ch = 0; ch < 8; ch++) {
            if (ch < 7) cp_wait<1>(); else cp_wait<0>();
            __syncthreads();
            if (ch + 2 < 8) {
                const int nb = (ch + 2) % 3;
                const int ko = (ch + 2) * 128;
                cp16(hs_a[nb][0], hp + ko + sseg * 8);
                cp16(hs_a[nb][1], hp + ko + (sseg + 8) * 8);
                const uint32_t* wsrc = wreg + (size_t)(ch + 2) * 2048;
#pragma unroll
                for (int i = 0; i < 2; i++)
                    cp16(ws_a[nb] + i * 4096, wsrc + (size_t)(tid + 256 * i) * 4);
                cp_commit();
            }
            const int buf = ch % 3;
            const uint32_t* Wb = wb[buf];
#pragma unroll
            for (int li = 0; li < 2; li++) {
                const int l = kh + 4 * li;
                uint32_t af[4];
                ldsm_x4(af[0], af[1], af[2], af[3], haddr[buf] + l * 32);
#pragma unroll
                for (int c = 0; c < 4; c++) {
                    uint2 wv = *(const uint2*)(Wb + l * 256 + c * 64 + wbase);
                    uint32_t bf[2] = { wv.x, wv.y };
                    mma_f16(acc[c], af, bf);
                }
            }
        }
        __syncthreads();

        float* G = gates + kh * (32 * 36);
#pragma unroll
        for (int c = 0; c < 4; c++) {
            int row = mh * 16 + gid;
            int col = c * 8 + 2 * tig;
            G[row * 36 + col]           = acc[c][0];
            G[row * 36 + col + 1]       = acc[c][1];
            G[(row + 8) * 36 + col]     = acc[c][2];
            G[(row + 8) * 36 + col + 1] = acc[c][3];
        }
        __syncthreads();

        {
            int b = b0 + abl;
            int ug = u0 + au;
            float ig = 0.0f, fg = 0.0f, gg = 0.0f, og = 0.0f;
#pragma unroll
            for (int q = 0; q < 4; q++) {
                const float* Gq = gates + q * (32 * 36) + abl * 36;
                ig += Gq[au];
                fg += Gq[8 + au];
                gg += Gq[16 + au];
                og += Gq[24 + au];
            }
            ig = sig_f(ig + pre[0]);
            fg = sig_f(fg + pre[1]);
            gg = tanh_f(gg + pre[2]);
            og = sig_f(og + pre[3]);
            float cn = fg * c_reg + ig * gg;
            c_reg = cn;
            float hn = og * tanh_f(cn);
            out[((size_t)b * T_ + s) * N_ + ug] = hn;
            h_next[(size_t)b * N_ + ug] = __float2half_rn(hn);
            if (s == T_ - 1) {
                const size_t tail = (size_t)B_ * T_ * N_;
                size_t gi = (size_t)b * N_ + ug;
                out[tail + gi] = hn;
                out[tail + (size_t)B_ * N_ + gi] = cn;
            }
        }

        if (s + 1 < T_) {
            const float* Pb = g_Pc + (size_t)(s + 1) * B_ * G_ + (size_t)(b0 + abl) * G_ + u0 + au;
            pre[0] = Pb[0];
            pre[1] = Pb[N_];
            pre[2] = Pb[2 * N_];
            pre[3] = Pb[3 * N_];
        }
        grid_barrier(bslot, 128);
    }
}

// ---------------- host launcher ----------------
extern "C" void kernel_launch(void* const* d_in, const int* in_sizes, int n_in,
                              void* d_out, int out_size) {
    (void)in_sizes; (void)n_in; (void)out_size;
    const float* x     = (const float*)d_in[0];
    const float* Wf_ih = (const float*)d_in[1];
    const float* Wf_hh = (const float*)d_in[2];
    const float* bf    = (const float*)d_in[3];
    const float* Wb_ih = (const float*)d_in[4];
    const float* Wb_hh = (const float*)d_in[5];
    const float* bb    = (const float*)d_in[6];
    const float* Wc_ih = (const float*)d_in[7];
    const float* Wc_hh = (const float*)d_in[8];
    const float* bc    = (const float*)d_in[9];
    float* out = (float*)d_out;

    __half *wih, *x16, *bi16;
    cudaGetSymbolAddress((void**)&wih, g_Wih16);
    cudaGetSymbolAddress((void**)&x16, g_x16);
    cudaGetSymbolAddress((void**)&bi16, g_bi16);
    const __half* wih_f = wih;
    const __half* wih_b = wih + (4u << 20);
    const __half* wih_c = wih + (8u << 20);

    const int gemm_smem   = 6 * 128 * GPW * 4;                            // 110592
    const int bilstm_smem = (3 * 32 * SPH + 3 * 4096 + 4 * 32 * 68) * 4;  // 110080
    const int cell_smem   = (3 * 32 * SPH + 3 * 2048 + 4 * 32 * 36) * 4;  // 69120
    cudaFuncSetAttribute(gemm_f16_kernel, cudaFuncAttributeMaxDynamicSharedMemorySize, gemm_smem);
    cudaFuncSetAttribute(bilstm_mma_kernel, cudaFuncAttributeMaxDynamicSharedMemorySize, bilstm_smem);
    cudaFuncSetAttribute(cell_mma_kernel, cudaFuncAttributeMaxDynamicSharedMemorySize, cell_smem);

    // 1) merged prep
    prep_all_kernel<<<49920, 256>>>(x, Wf_ih, Wb_ih, Wc_ih);
    // 2) merged W_hh swizzles
    wswz_all_kernel<<<24576, 256>>>(Wf_hh, Wb_hh, Wc_hh);
    // 3) fwd + bwd input projections (one launch)
    dim3 ggrid(G_ / 128, (T_ * B_) / 128, 2);
    gemm_f16_kernel<<<ggrid, 256, gemm_smem>>>(x16, wih_f, wih_b, bf, bb, N_, 1, 0);
    // 4) bilstm recurrence
    bilstm_mma_kernel<<<256, 256, bilstm_smem>>>();
    // 5) cell input projection (K = 2N)
    dim3 cgrid(G_ / 128, (T_ * B_) / 128, 1);
    gemm_f16_kernel<<<cgrid, 256, gemm_smem>>>(bi16, wih_c, wih_c, bc, bc, 2 * N_, 0, 2);
    // 6) cell recurrence + output
    cell_mma_kernel<<<256, 256, cell_smem>>>(out);
}

// round 17
// speedup vs baseline: 1.3953x; 1.0343x over previous
#include <cuda_runtime.h>
#include <cuda_fp16.h>
#include <cstdint>
#include <math.h>

#define T_ 512
#define B_ 64
#define N_ 1024
#define G_ 4096   // 4*N
#define SPH 68    // smem pitch (u32) for a 128-fp16 h chunk row (64 u32 + 4 pad)
#define GPW 36    // gemm smem pitch (u32) for a 64-fp16 chunk row (32 u32 + 4 pad)

// ---------------- static device scratch ----------------
__device__ float g_Pf[(size_t)T_ * B_ * G_];
__device__ float g_Pb[(size_t)T_ * B_ * G_];
__device__ float g_Pc[(size_t)T_ * B_ * G_];
__device__ __half g_bi16[(size_t)T_ * B_ * 2 * N_];
__device__ __half g_x16[(size_t)B_ * T_ * N_];
__device__ __half g_Wih16[16 * 1024 * 1024];
__device__ __half g_h16[6][B_ * N_];
__device__ uint32_t g_Wsw_bi[2 * 64 * 32768];
__device__ uint32_t g_Wsw_c[128 * 16384];

__device__ unsigned g_barc[6] = {0, 0, 0, 0, 0, 0};
__device__ unsigned g_barg[6] = {0, 0, 0, 0, 0, 0};

__device__ __forceinline__ void grid_barrier(int which, unsigned nb) {
    __syncthreads();
    if (threadIdx.x == 0) {
        __threadfence();
        volatile unsigned* gen = &g_barg[which];
        unsigned g = *gen;
        if (atomicAdd(&g_barc[which], 1) == nb - 1) {
            g_barc[which] = 0;
            __threadfence();
            atomicExch((unsigned*)gen, g + 1);
        } else {
            while (*gen == g) { }
            __threadfence();
        }
    }
    __syncthreads();
}

// ---------------- helpers ----------------
__device__ __forceinline__ void mma_f16(float* c, const uint32_t* a, const uint32_t* b) {
    asm volatile(
        "mma.sync.aligned.m16n8k16.row.col.f32.f16.f16.f32 "
        "{%0,%1,%2,%3}, {%4,%5,%6,%7}, {%8,%9}, {%0,%1,%2,%3};"
        : "+f"(c[0]), "+f"(c[1]), "+f"(c[2]), "+f"(c[3])
        : "r"(a[0]), "r"(a[1]), "r"(a[2]), "r"(a[3]), "r"(b[0]), "r"(b[1]));
}
__device__ __forceinline__ void ldsm_x4(uint32_t& r0, uint32_t& r1, uint32_t& r2, uint32_t& r3,
                                        uint32_t addr) {
    asm volatile("ldmatrix.sync.aligned.m8n8.x4.shared.b16 {%0,%1,%2,%3}, [%4];"
                 : "=r"(r0), "=r"(r1), "=r"(r2), "=r"(r3) : "r"(addr));
}
__device__ __forceinline__ void cp16(uint32_t dst, const void* src) {
    asm volatile("cp.async.cg.shared.global [%0], [%1], 16;" :: "r"(dst), "l"(src));
}
__device__ __forceinline__ void cp_commit() { asm volatile("cp.async.commit_group;"); }
template <int NN> __device__ __forceinline__ void cp_wait() {
    asm volatile("cp.async.wait_group %0;" :: "n"(NN));
}
__device__ __forceinline__ uint32_t pack2h(float a, float b) {
    __half2 h = __floats2half2_rn(a, b);
    return *(uint32_t*)&h;
}
__device__ __forceinline__ uint32_t s2u(const void* p) {
    return (uint32_t)__cvta_generic_to_shared(p);
}
__device__ __forceinline__ float sig_f(float x) {
    return __fdividef(1.0f, 1.0f + __expf(-x));
}
__device__ __forceinline__ float tanh_f(float x) {
    return 1.0f - 2.0f * __fdividef(1.0f, __expf(2.0f * x) + 1.0f);
}

// ---------------- merged one-time prep ----------------
__global__ void prep_all_kernel(const float* __restrict__ x,
                                const float* __restrict__ Wf,
                                const float* __restrict__ Wb,
                                const float* __restrict__ Wc) {
    const int bid = blockIdx.x;
    const int tid = threadIdx.x;
    if (bid < 32768) {
        size_t i = (size_t)bid * 256 + tid;
        float4 v = ((const float4*)x)[i];
        uint2 o;
        o.x = pack2h(v.x, v.y);
        o.y = pack2h(v.z, v.w);
        ((uint2*)g_x16)[i] = o;
    } else if (bid < 49152) {
        size_t i = (size_t)(bid - 32768) * 256 + tid;
        const float* src;
        size_t off;
        if (i < (1u << 20))      { src = Wf; off = i; }
        else if (i < (2u << 20)) { src = Wb; off = i - (1u << 20); }
        else                     { src = Wc; off = i - (2u << 20); }
        float4 v = ((const float4*)src)[off];
        uint2 o;
        o.x = pack2h(v.x, v.y);
        o.y = pack2h(v.z, v.w);
        ((uint2*)g_Wih16)[i] = o;
    } else {
        size_t i = (size_t)(bid - 49152) * 256 + tid;
        ((uint32_t*)g_h16)[i] = 0;
    }
}

// ---------------- merged W_hh fragment swizzles ----------------
__global__ void wswz_all_kernel(const float* __restrict__ Wf,
                                const float* __restrict__ Wb,
                                const float* __restrict__ Wc) {
    const int bid = blockIdx.x;
    const int tid = threadIdx.x;
    if (bid < 16384) {
        size_t idx = (size_t)bid * 256 + tid;
        unsigned region = idx >> 15;
        unsigned w = idx & 32767;
        int dir = region >> 6, ublk = region & 63;
        int k16 = w >> 9;
        int jn8 = (w >> 6) & 7;
        int lane = (w >> 1) & 31;
        int r = w & 1;
        int col = jn8 * 8 + (lane >> 2);
        int gate = col >> 4, u = col & 15;
        int row = gate * N_ + ublk * 16 + u;
        int k = k16 * 16 + r * 8 + (lane & 3) * 2;
        const float* W = dir ? Wb : Wf;
        g_Wsw_bi[idx] = pack2h(W[(size_t)row * N_ + k], W[(size_t)row * N_ + k + 1]);
    } else {
        size_t idx = (size_t)(bid - 16384) * 256 + tid;
        unsigned blk = idx >> 14;
        unsigned w = idx & 16383;
        int k16 = w >> 8;
        int nwq = (w >> 6) & 3;
        int lane = (w >> 1) & 31;
        int r = w & 1;
        int col = nwq * 8 + (lane >> 2);
        int gate = col >> 3, u = col & 7;
        int row = gate * N_ + blk * 8 + u;
        int k = k16 * 16 + r * 8 + (lane & 3) * 2;
        g_Wsw_c[idx] = pack2h(Wc[(size_t)row * N_ + k], Wc[(size_t)row * N_ + k + 1]);
    }
}

// ---------------- fp16 GEMM v3: 128x128xK, chunk=64, ring-3, single sync/chunk ----------------
__global__ __launch_bounds__(256, 2) void gemm_f16_kernel(
    const __half* __restrict__ A,
    const __half* __restrict__ W0, const __half* __restrict__ W1,
    const float* __restrict__ bias0, const float* __restrict__ bias1,
    int K, int a_mode, int dst0)
{
    const int z = blockIdx.z;
    const __half* Wt = z ? W1 : W0;
    const float* bias = z ? bias1 : bias0;
    const int dst_sel = dst0 + z;
    float* C = (dst_sel == 0) ? g_Pf : (dst_sel == 1) ? g_Pb : g_Pc;

    extern __shared__ __align__(16) uint32_t gsm[];
    uint32_t* As[3] = { gsm, gsm + 128 * GPW, gsm + 2 * 128 * GPW };
    uint32_t* Ws[3] = { gsm + 3 * 128 * GPW, gsm + 4 * 128 * GPW, gsm + 5 * 128 * GPW };

    const int tid = threadIdx.x;
    const int m0 = blockIdx.y * 128;
    const int g0 = blockIdx.x * 128;

    const int lrow = tid >> 3;
    const int lseg = tid & 7;
    const __half* asrc2[4];
    const __half* wsrc2[4];
    uint32_t asm_a[3][4], wsm_a[3][4];
#pragma unroll
    for (int i = 0; i < 4; i++) {
        int row = lrow + 32 * i;
        int m = m0 + row;
        int prow = (a_mode == 1) ? ((m & 63) * T_ + (m >> 6)) : m;
        asrc2[i] = A + (size_t)prow * K + lseg * 8;
        wsrc2[i] = Wt + (size_t)(g0 + row) * K + lseg * 8;
#pragma unroll
        for (int b = 0; b < 3; b++) {
            asm_a[b][i] = s2u(&As[b][row * GPW + lseg * 4]);
            wsm_a[b][i] = s2u(&Ws[b][row * GPW + lseg * 4]);
        }
    }

    const int lane = tid & 31;
    const int wid = tid >> 5;
    const int gid = lane >> 2;
    const int tig = lane & 3;
    const int wm = (wid & 3) * 32;
    const int wn = (wid >> 2) * 64;

    const int rowA = lane & 15;
    const int koffA = (lane >> 4) * 4;
    const int cB = (lane & 7) + ((lane >> 4) << 3);
    const int kB = ((lane >> 3) & 1) * 4;

    uint32_t aaddr[3][2], baddr[3][4];
#pragma unroll
    for (int b = 0; b < 3; b++) {
#pragma unroll
        for (int mf = 0; mf < 2; mf++)
            aaddr[b][mf] = s2u(&As[b][(wm + mf * 16 + rowA) * GPW + koffA]);
#pragma unroll
        for (int np = 0; np < 4; np++)
            baddr[b][np] = s2u(&Ws[b][(wn + np * 16 + cB) * GPW + kB]);
    }

    float acc[2][8][4];
#pragma unroll
    for (int mf = 0; mf < 2; mf++)
#pragma unroll
        for (int nf = 0; nf < 8; nf++)
#pragma unroll
            for (int j = 0; j < 4; j++) acc[mf][nf][j] = 0.0f;

    const int NC = K / 64;
#pragma unroll
    for (int pc = 0; pc < 2; pc++) {
        const int k0 = pc * 64;
#pragma unroll
        for (int i = 0; i < 4; i++) {
            cp16(asm_a[pc][i], asrc2[i] + k0);
            cp16(wsm_a[pc][i], wsrc2[i] + k0);
        }
        cp_commit();
    }

    for (int ch = 0; ch < NC; ch++) {
        if (ch + 1 < NC) cp_wait<1>(); else cp_wait<0>();
        __syncthreads();
        if (ch + 2 < NC) {
            const int nb = (ch + 2) % 3;
            const int k0 = (ch + 2) * 64;
#pragma unroll
            for (int i = 0; i < 4; i++) {
                cp16(asm_a[nb][i], asrc2[i] + k0);
                cp16(wsm_a[nb][i], wsrc2[i] + k0);
            }
            cp_commit();
        }
        const int buf = ch % 3;
#pragma unroll
        for (int ks = 0; ks < 4; ks++) {
            const int kbb = ks * 32;
            uint32_t af[2][4];
#pragma unroll
            for (int mf = 0; mf < 2; mf++)
                ldsm_x4(af[mf][0], af[mf][1], af[mf][2], af[mf][3], aaddr[buf][mf] + kbb);
            uint32_t bf[8][2];
#pragma unroll
            for (int np = 0; np < 4; np++)
                ldsm_x4(bf[2 * np][0], bf[2 * np][1], bf[2 * np + 1][0], bf[2 * np + 1][1],
                        baddr[buf][np] + kbb);
#pragma unroll
            for (int mf = 0; mf < 2; mf++)
#pragma unroll
                for (int nf = 0; nf < 8; nf++)
                    mma_f16(acc[mf][nf], af[mf], bf[nf]);
        }
    }
    __syncthreads();

#pragma unroll
    for (int mf = 0; mf < 2; mf++) {
#pragma unroll
        for (int nf = 0; nf < 8; nf++) {
            int row = m0 + wm + mf * 16 + gid;
            int col = g0 + wn + nf * 8 + 2 * tig;
            float b0 = bias[col], b1 = bias[col + 1];
            float2 v0 = make_float2(acc[mf][nf][0] + b0, acc[mf][nf][1] + b1);
            float2 v1 = make_float2(acc[mf][nf][2] + b0, acc[mf][nf][3] + b1);
            *(float2*)&C[(size_t)row * G_ + col] = v0;
            *(float2*)&C[(size_t)(row + 8) * G_ + col] = v1;
        }
    }
}

// ---------------- persistent bilstm recurrence: 256 blocks x 256 thr, ring-3, k-split 4 ----------------
__global__ __launch_bounds__(256, 2) void bilstm_mma_kernel()
{
    extern __shared__ uint32_t smem_u[];
    uint32_t* hb[3] = { smem_u, smem_u + 32 * SPH, smem_u + 2 * 32 * SPH };
    uint32_t* wb[3] = { smem_u + 3 * 32 * SPH, smem_u + 3 * 32 * SPH + 4096,
                        smem_u + 3 * 32 * SPH + 8192 };
    float* gates = (float*)(smem_u + 3 * 32 * SPH + 12288);   // 4 arrays of [32][68]

    const int bid = blockIdx.x;
    const int dir = bid >> 7;
    const int bh = (bid >> 6) & 1;
    const int ublk = bid & 63;
    const int b0 = bh * 32;
    const int u0 = ublk * 16;
    const int bslot = dir * 2 + bh;
    const float* Pbase = dir ? g_Pb : g_Pf;
    const uint32_t* wreg = g_Wsw_bi + ((size_t)(dir * 64 + ublk) << 15);

    const int tid = threadIdx.x;
    const int lane = tid & 31;
    const int wid = tid >> 5;
    const int gid = lane >> 2;
    const int tig = lane & 3;
    const int kh = wid >> 1;
    const int mh = wid & 1;

    const int srow = tid >> 3;
    const int sseg = tid & 7;
    uint32_t hs_a[3][2], ws_a[3];
#pragma unroll
    for (int b = 0; b < 3; b++) {
        hs_a[b][0] = s2u(hb[b]) + (srow * SPH + sseg * 4) * 4;
        hs_a[b][1] = s2u(hb[b]) + (srow * SPH + (sseg + 8) * 4) * 4;
        ws_a[b] = s2u(wb[b]) + tid * 16;
    }

    const int rowA = lane & 15;
    const int koffA = (lane >> 4) * 4;
    uint32_t haddr[3];
#pragma unroll
    for (int b = 0; b < 3; b++)
        haddr[b] = s2u(&hb[b][(mh * 16 + rowA) * SPH + koffA]);

    const uint32_t wbase = lane * 2;   // + c*64 per chain

    int abl[2], au[2];
#pragma unroll
    for (int i = 0; i < 2; i++) {
        int p = tid + 256 * i;
        abl[i] = p >> 4;
        au[i] = p & 15;
    }
    float c_reg[2] = {0.0f, 0.0f};

    float pre[2][4];
    {
        const float* P = Pbase + (size_t)(dir ? (T_ - 1) : 0) * B_ * G_;
#pragma unroll
        for (int i = 0; i < 2; i++) {
            const float* Pb = P + (size_t)(b0 + abl[i]) * G_ + u0 + au[i];
            pre[i][0] = Pb[0];
            pre[i][1] = Pb[N_];
            pre[i][2] = Pb[2 * N_];
            pre[i][3] = Pb[3 * N_];
        }
    }

    for (int s = 0; s < T_; s++) {
        const int t = dir ? (T_ - 1 - s) : s;
        const __half* h_prev = g_h16[2 * dir + (s & 1)];
        __half* h_next = g_h16[2 * dir + ((s + 1) & 1)];
        __half* hist = g_bi16 + (size_t)t * B_ * 2 * N_ + dir * N_;
        const __half* hp = h_prev + (size_t)(b0 + srow) * N_;

#pragma unroll
        for (int pc = 0; pc < 2; pc++) {
            const int ko = pc * 128;
            cp16(hs_a[pc][0], hp + ko + sseg * 8);
            cp16(hs_a[pc][1], hp + ko + (sseg + 8) * 8);
            const uint32_t* wsrc = wreg + (size_t)pc * 4096;
#pragma unroll
            for (int i = 0; i < 4; i++)
                cp16(ws_a[pc] + i * 4096, wsrc + (size_t)(tid + 256 * i) * 4);
            cp_commit();
        }

        float acc[8][4];
#pragma unroll
        for (int c = 0; c < 8; c++)
#pragma unroll
            for (int j = 0; j < 4; j++) acc[c][j] = 0.0f;

        for (int ch = 0; ch < 8; ch++) {
            if (ch < 7) cp_wait<1>(); else cp_wait<0>();
            __syncthreads();
            if (ch + 2 < 8) {
                const int nb = (ch + 2) % 3;
                const int ko = (ch + 2) * 128;
                cp16(hs_a[nb][0], hp + ko + sseg * 8);
                cp16(hs_a[nb][1], hp + ko + (sseg + 8) * 8);
                const uint32_t* wsrc = wreg + (size_t)(ch + 2) * 4096;
#pragma unroll
                for (int i = 0; i < 4; i++)
                    cp16(ws_a[nb] + i * 4096, wsrc + (size_t)(tid + 256 * i) * 4);
                cp_commit();
            }
            const int buf = ch % 3;
            const uint32_t* Wb = wb[buf];
#pragma unroll
            for (int li = 0; li < 2; li++) {
                const int l = kh + 4 * li;
                uint32_t af[4];
                ldsm_x4(af[0], af[1], af[2], af[3], haddr[buf] + l * 32);
#pragma unroll
                for (int c = 0; c < 8; c++) {
                    uint2 wv = *(const uint2*)(Wb + l * 512 + c * 64 + wbase);
                    uint32_t bf[2] = { wv.x, wv.y };
                    mma_f16(acc[c], af, bf);
                }
            }
        }
        // NOTE: no sync here — gates arrays are disjoint from h/W buffers;
        // the pre-activation sync below orders write->read, the grid barrier
        // orders buffer reuse for the next step.

        float* G = gates + kh * (32 * 68);
#pragma unroll
        for (int c = 0; c < 8; c++) {
            int row = mh * 16 + gid;
            int col = c * 8 + 2 * tig;
            G[row * 68 + col]           = acc[c][0];
            G[row * 68 + col + 1]       = acc[c][1];
            G[(row + 8) * 68 + col]     = acc[c][2];
            G[(row + 8) * 68 + col + 1] = acc[c][3];
        }
        __syncthreads();

#pragma unroll
        for (int i = 0; i < 2; i++) {
            int bl = abl[i];
            int u = au[i];
            int b = b0 + bl;
            int ug = u0 + u;
            float ig = 0.0f, fg = 0.0f, gg = 0.0f, og = 0.0f;
#pragma unroll
            for (int q = 0; q < 4; q++) {
                const float* Gq = gates + q * (32 * 68) + bl * 68;
                ig += Gq[u];
                fg += Gq[16 + u];
                gg += Gq[32 + u];
                og += Gq[48 + u];
            }
            ig = sig_f(ig + pre[i][0]);
            fg = sig_f(fg + pre[i][1]);
            gg = tanh_f(gg + pre[i][2]);
            og = sig_f(og + pre[i][3]);
            float cn = fg * c_reg[i] + ig * gg;
            c_reg[i] = cn;
            __half hn = __float2half_rn(og * tanh_f(cn));
            h_next[(size_t)b * N_ + ug] = hn;
            hist[(size_t)b * 2 * N_ + ug] = hn;
        }

        if (s + 1 < T_) {
            const int tn = dir ? (T_ - 2 - s) : (s + 1);
            const float* P = Pbase + (size_t)tn * B_ * G_;
#pragma unroll
            for (int i = 0; i < 2; i++) {
                const float* Pb = P + (size_t)(b0 + abl[i]) * G_ + u0 + au[i];
                pre[i][0] = Pb[0];
                pre[i][1] = Pb[N_];
                pre[i][2] = Pb[2 * N_];
                pre[i][3] = Pb[3 * N_];
            }
        }
        grid_barrier(bslot, 64);
    }
}

// ---------------- persistent cell recurrence: 256 blocks x 256 thr, W smem-resident ----------------
// Warp (8): kh = wid>>1 (k16 mod 4), mh = wid&1. Each warp covers all 32 cols (4 n8 chains).
__global__ __launch_bounds__(256, 2) void cell_mma_kernel(float* __restrict__ out)
{
    extern __shared__ uint32_t smem_u[];
    uint32_t* wsm = smem_u;                                   // 16384 u32 = full W region
    uint32_t* hb[3] = { smem_u + 16384, smem_u + 16384 + 32 * SPH,
                        smem_u + 16384 + 2 * 32 * SPH };
    float* gates = (float*)(smem_u + 16384 + 3 * 32 * SPH);   // 4 arrays of [32][36]

    const int bid = blockIdx.x;
    const int bh = bid >> 7;
    const int ublk = bid & 127;
    const int b0 = bh * 32;
    const int u0 = ublk * 8;
    const int bslot = 4 + bh;
    const uint32_t* wreg = g_Wsw_c + ((size_t)ublk << 14);

    const int tid = threadIdx.x;
    const int lane = tid & 31;
    const int wid = tid >> 5;
    const int gid = lane >> 2;
    const int tig = lane & 3;
    const int kh = wid >> 1;
    const int mh = wid & 1;

    // one-time: load full W region (64 KB) into smem
    {
        const uint32_t ws_base = s2u(wsm);
#pragma unroll
        for (int i = 0; i < 16; i++)
            cp16(ws_base + (tid + 256 * i) * 16, wreg + (size_t)(tid + 256 * i) * 4);
        cp_commit();
        cp_wait<0>();
        __syncthreads();
    }

    const int srow = tid >> 3;
    const int sseg = tid & 7;
    uint32_t hs_a[3][2];
#pragma unroll
    for (int b = 0; b < 3; b++) {
        hs_a[b][0] = s2u(hb[b]) + (srow * SPH + sseg * 4) * 4;
        hs_a[b][1] = s2u(hb[b]) + (srow * SPH + (sseg + 8) * 4) * 4;
    }

    const int rowA = lane & 15;
    const int koffA = (lane >> 4) * 4;
    uint32_t haddr[3];
#pragma unroll
    for (int b = 0; b < 3; b++)
        haddr[b] = s2u(&hb[b][(mh * 16 + rowA) * SPH + koffA]);

    const uint32_t wbase = lane * 2;

    const int abl = tid >> 3;
    const int au = tid & 7;
    float c_reg = 0.0f;

    float pre[4];
    {
        const float* Pb = g_Pc + (size_t)(b0 + abl) * G_ + u0 + au;
        pre[0] = Pb[0];
        pre[1] = Pb[N_];
        pre[2] = Pb[2 * N_];
        pre[3] = Pb[3 * N_];
    }

    for (int s = 0; s < T_; s++) {
        const __half* h_prev = g_h16[4 + (s & 1)];
        __half* h_next = g_h16[4 + ((s + 1) & 1)];
        const __half* hp = h_prev + (size_t)(b0 + srow) * N_;

#pragma unroll
        for (int pc = 0; pc < 2; pc++) {
            const int ko = pc * 128;
            cp16(hs_a[pc][0], hp + ko + sseg * 8);
            cp16(hs_a[pc][1], hp + ko + (sseg + 8) * 8);
            cp_commit();
        }

        float acc[4][4];
#pragma unroll
        for (int c = 0; c < 4; c++)
#pragma unroll
            for (int j = 0; j < 4; j++) acc[c][j] = 0.0f;

        for (int ch = 0; ch < 8; ch++) {
            if (ch < 7) cp_wait<1>(); else cp_wait<0>();
            __syncthreads();
            if (ch + 2 < 8) {
                const int nb = (ch + 2) % 3;
                const int ko = (ch + 2) * 128;
                cp16(hs_a[nb][0], hp + ko + sseg * 8);
                cp16(hs_a[nb][1], hp + ko + (sseg + 8) * 8);
                cp_commit();
            }
            const int buf = ch % 3;
#pragma unroll
            for (int li = 0; li < 2; li++) {
                const int l = kh + 4 * li;
                const int g16 = ch * 8 + l;
                uint32_t af[4];
                ldsm_x4(af[0], af[1], af[2], af[3], haddr[buf] + l * 32);
#pragma unroll
                for (int c = 0; c < 4; c++) {
                    uint2 wv = *(const uint2*)(wsm + g16 * 256 + c * 64 + wbase);
                    uint32_t bf[2] = { wv.x, wv.y };
                    mma_f16(acc[c], af, bf);
                }
            }
        }
        // no post-mma sync (see bilstm note)

        float* G = gates + kh * (32 * 36);
#pragma unroll
        for (int c = 0; c < 4; c++) {
            int row = mh * 16 + gid;
            int col = c * 8 + 2 * tig;
            G[row * 36 + col]           = acc[c][0];
            G[row * 36 + col + 1]       = acc[c][1];
            G[(row + 8) * 36 + col]     = acc[c][2];
            G[(row + 8) * 36 + col + 1] = acc[c][3];
        }
        __syncthreads();

        {
            int b = b0 + abl;
            int ug = u0 + au;
            float ig = 0.0f, fg = 0.0f, gg = 0.0f, og = 0.0f;
#pragma unroll
            for (int q = 0; q < 4; q++) {
                const float* Gq = gates + q * (32 * 36) + abl * 36;
                ig += Gq[au];
                fg += Gq[8 + au];
                gg += Gq[16 + au];
                og += Gq[24 + au];
            }
            ig = sig_f(ig + pre[0]);
            fg = sig_f(fg + pre[1]);
            gg = tanh_f(gg + pre[2]);
            og = sig_f(og + pre[3]);
            float cn = fg * c_reg + ig * gg;
            c_reg = cn;
            float hn = og * tanh_f(cn);
            out[((size_t)b * T_ + s) * N_ + ug] = hn;
            h_next[(size_t)b * N_ + ug] = __float2half_rn(hn);
            if (s == T_ - 1) {
                const size_t tail = (size_t)B_ * T_ * N_;
                size_t gi = (size_t)b * N_ + ug;
                out[tail + gi] = hn;
                out[tail + (size_t)B_ * N_ + gi] = cn;
            }
        }

        if (s + 1 < T_) {
            const float* Pb = g_Pc + (size_t)(s + 1) * B_ * G_ + (size_t)(b0 + abl) * G_ + u0 + au;
            pre[0] = Pb[0];
            pre[1] = Pb[N_];
            pre[2] = Pb[2 * N_];
            pre[3] = Pb[3 * N_];
        }
        grid_barrier(bslot, 128);
    }
}

// ---------------- host launcher ----------------
extern "C" void kernel_launch(void* const* d_in, const int* in_sizes, int n_in,
                              void* d_out, int out_size) {
    (void)in_sizes; (void)n_in; (void)out_size;
    const float* x     = (const float*)d_in[0];
    const float* Wf_ih = (const float*)d_in[1];
    const float* Wf_hh = (const float*)d_in[2];
    const float* bf    = (const float*)d_in[3];
    const float* Wb_ih = (const float*)d_in[4];
    const float* Wb_hh = (const float*)d_in[5];
    const float* bb    = (const float*)d_in[6];
    const float* Wc_ih = (const float*)d_in[7];
    const float* Wc_hh = (const float*)d_in[8];
    const float* bc    = (const float*)d_in[9];
    float* out = (float*)d_out;

    __half *wih, *x16, *bi16;
    cudaGetSymbolAddress((void**)&wih, g_Wih16);
    cudaGetSymbolAddress((void**)&x16, g_x16);
    cudaGetSymbolAddress((void**)&bi16, g_bi16);
    const __half* wih_f = wih;
    const __half* wih_b = wih + (4u << 20);
    const __half* wih_c = wih + (8u << 20);

    const int gemm_smem   = 6 * 128 * GPW * 4;                            // 110592
    const int bilstm_smem = (3 * 32 * SPH + 3 * 4096 + 4 * 32 * 68) * 4;  // 110080
    const int cell_smem   = (16384 + 3 * 32 * SPH + 4 * 32 * 36) * 4;     // 110080
    cudaFuncSetAttribute(gemm_f16_kernel, cudaFuncAttributeMaxDynamicSharedMemorySize, gemm_smem);
    cudaFuncSetAttribute(bilstm_mma_kernel, cudaFuncAttributeMaxDynamicSharedMemorySize, bilstm_smem);
    cudaFuncSetAttribute(cell_mma_kernel, cudaFuncAttributeMaxDynamicSharedMemorySize, cell_smem);

    // 1) merged prep
    prep_all_kernel<<<49920, 256>>>(x, Wf_ih, Wb_ih, Wc_ih);
    // 2) merged W_hh swizzles
    wswz_all_kernel<<<24576, 256>>>(Wf_hh, Wb_hh, Wc_hh);
    // 3) fwd + bwd input projections (one launch)
    dim3 ggrid(G_ / 128, (T_ * B_) / 128, 2);
    gemm_f16_kernel<<<ggrid, 256, gemm_smem>>>(x16, wih_f, wih_b, bf, bb, N_, 1, 0);
    // 4) bilstm recurrence
    bilstm_mma_kernel<<<256, 256, bilstm_smem>>>();
    // 5) cell input projection (K = 2N)
    dim3 cgrid(G_ / 128, (T_ * B_) / 128, 1);
    gemm_f16_kernel<<<cgrid, 256, gemm_smem>>>(bi16, wih_c, wih_c, bc, bc, 2 * N_, 0, 2);
    // 6) cell recurrence + output
    cell_mma_kernel<<<256, 256, cell_smem>>>(out);
}